// round 1
// baseline (speedup 1.0000x reference)
#include <cuda_runtime.h>
#include <math.h>

#define PI_F 3.14159265358979323846f

// ---------------- scratch (allocation-free: __device__ globals) ----------------
__device__ float g_H  [2048 * 512];   // hidden (reused for k then q)
__device__ float g_CSk[2048 * 128];   // [cos|sin] of key phase
__device__ float g_CSq[2048 * 128];   // [cos|sin] of query phase
__device__ float g_V  [2048 * 512];
__device__ float g_A  [2 * 1024 * 1024]; // causal score matrix per batch
__device__ float g_R  [2048 * 512];   // retrieved / norm
__device__ float g_LN [2048 * 512];

// ---------------- epilogue kinds ----------------
#define EPI_BIAS   0
#define EPI_GELU   1
#define EPI_COSSIN 2
#define EPI_CAUSAL 3
#define EPI_SCALEN 4
#define EPI_RESID  5

// ---------------- tiled SGEMM, 256 threads, BK=16 ----------------
// C[M,N] = A[M,K] @ B  (B is K x N, or N x K if TRANSB) + epilogue
template<int BM, int BN, int TM, int TN, bool TRANSB, int EPI>
__global__ __launch_bounds__(256)
void gemm_kernel(const float* __restrict__ Ag, const float* __restrict__ Bg,
                 const float* __restrict__ bias, const float* __restrict__ Rg,
                 float* __restrict__ Cg, int M, int N, int K,
                 long sA, long sB, long sC)
{
    constexpr int BK = 16;
    __shared__ float As[BK][BM];   // K-major for vectorized compute reads
    __shared__ float Bs[BK][BN];

    const int tid = threadIdx.x;
    const int tx = tid % (BN / TN);
    const int ty = tid / (BN / TN);
    const int row0 = blockIdx.y * BM;
    const int col0 = blockIdx.x * BN;

    Ag += (long)blockIdx.z * sA;
    Bg += (long)blockIdx.z * sB;
    Cg += (long)blockIdx.z * sC;

    // Fully-masked causal tile: write zeros, skip all compute.
    if (EPI == EPI_CAUSAL && col0 > row0 + BM - 1) {
        #pragma unroll
        for (int i = 0; i < TM; i++) {
            int row = row0 + ty * TM + i;
            #pragma unroll
            for (int j = 0; j < TN; j++)
                Cg[(long)row * N + col0 + tx * TN + j] = 0.0f;
        }
        return;
    }

    float acc[TM][TN];
    #pragma unroll
    for (int i = 0; i < TM; i++)
        #pragma unroll
        for (int j = 0; j < TN; j++) acc[i][j] = 0.0f;

    // Causal truncation of the K loop for R = tril(A) @ V:
    // A[row, k] == 0 for k > row, so rows [row0, row0+BM) only need k < row0+BM.
    int Kend = K;
    if (EPI == EPI_SCALEN) Kend = min(K, row0 + BM);

    for (int k0 = 0; k0 < Kend; k0 += BK) {
        // ---- load A tile (BM x 16), store transposed into As[K][M]
        #pragma unroll
        for (int l = 0; l < (BM * BK) / 1024; l++) {
            int idx = tid + l * 256;
            int r = idx >> 2;            // 4 float4 per row (BK=16)
            int c = (idx & 3) * 4;
            float4 v = *(const float4*)(Ag + (long)(row0 + r) * K + k0 + c);
            As[c + 0][r] = v.x; As[c + 1][r] = v.y;
            As[c + 2][r] = v.z; As[c + 3][r] = v.w;
        }
        // ---- load B tile (16 x BN)
        if (!TRANSB) {
            #pragma unroll
            for (int l = 0; l < (BK * BN) / 1024; l++) {
                int idx = tid + l * 256;
                int r = idx / (BN / 4);
                int c = (idx % (BN / 4)) * 4;
                *(float4*)&Bs[r][c] =
                    *(const float4*)(Bg + (long)(k0 + r) * N + col0 + c);
            }
        } else { // B is N x K row-major
            #pragma unroll
            for (int l = 0; l < (BN * BK) / 1024; l++) {
                int idx = tid + l * 256;
                int n = idx >> 2;
                int c = (idx & 3) * 4;
                float4 v = *(const float4*)(Bg + (long)(col0 + n) * K + k0 + c);
                Bs[c + 0][n] = v.x; Bs[c + 1][n] = v.y;
                Bs[c + 2][n] = v.z; Bs[c + 3][n] = v.w;
            }
        }
        __syncthreads();

        #pragma unroll
        for (int k = 0; k < BK; k++) {
            float a[TM], b[TN];
            #pragma unroll
            for (int i = 0; i < TM / 4; i++) {
                float4 t4 = *(const float4*)&As[k][ty * TM + i * 4];
                a[i*4+0] = t4.x; a[i*4+1] = t4.y; a[i*4+2] = t4.z; a[i*4+3] = t4.w;
            }
            #pragma unroll
            for (int j = 0; j < TN / 4; j++) {
                float4 t4 = *(const float4*)&Bs[k][tx * TN + j * 4];
                b[j*4+0] = t4.x; b[j*4+1] = t4.y; b[j*4+2] = t4.z; b[j*4+3] = t4.w;
            }
            #pragma unroll
            for (int i = 0; i < TM; i++)
                #pragma unroll
                for (int j = 0; j < TN; j++)
                    acc[i][j] = fmaf(a[i], b[j], acc[i][j]);
        }
        __syncthreads();
    }

    // ---- epilogue
    #pragma unroll
    for (int i = 0; i < TM; i++) {
        int row = row0 + ty * TM + i;
        #pragma unroll
        for (int j = 0; j < TN; j++) {
            int col = col0 + tx * TN + j;
            float v = acc[i][j];
            if (EPI == EPI_BIAS) {
                Cg[(long)row * N + col] = v + bias[col];
            } else if (EPI == EPI_GELU) {
                float t = v + bias[col];
                Cg[(long)row * N + col] = 0.5f * t * (1.0f + erff(t * 0.70710678118654752f));
            } else if (EPI == EPI_COSSIN) {
                float p = tanhf(v + bias[col]) * PI_F;
                float s, c;
                sincosf(p, &s, &c);
                Cg[(long)row * (2 * N) + col]     = c;  // cos block
                Cg[(long)row * (2 * N) + N + col] = s;  // sin block
            } else if (EPI == EPI_CAUSAL) {
                Cg[(long)row * N + col] = (col <= row) ? v : 0.0f;
            } else if (EPI == EPI_SCALEN) {
                Cg[(long)row * N + col] = v * rsqrtf((float)(row + 1) * 64.0f);
            } else { // EPI_RESID: out = resid + acc + bias
                Cg[(long)row * N + col] = Rg[(long)row * N + col] + v + bias[col];
            }
        }
    }
}

// ---------------- LayerNorm over D=512, one row per block ----------------
__global__ __launch_bounds__(128)
void ln_kernel(const float* __restrict__ X, const float* __restrict__ g,
               const float* __restrict__ b, float* __restrict__ out)
{
    const int D = 512;
    int row = blockIdx.x;
    int t = threadIdx.x; // 128 threads * float4 = 512
    float4 v = ((const float4*)(X + (long)row * D))[t];
    float s  = v.x + v.y + v.z + v.w;
    float sq = v.x * v.x + v.y * v.y + v.z * v.z + v.w * v.w;
    #pragma unroll
    for (int o = 16; o; o >>= 1) {
        s  += __shfl_xor_sync(0xFFFFFFFFu, s, o);
        sq += __shfl_xor_sync(0xFFFFFFFFu, sq, o);
    }
    __shared__ float ss[4], ssq[4];
    int w = t >> 5, l = t & 31;
    if (l == 0) { ss[w] = s; ssq[w] = sq; }
    __syncthreads();
    s  = ss[0] + ss[1] + ss[2] + ss[3];
    sq = ssq[0] + ssq[1] + ssq[2] + ssq[3];
    float mean = s * (1.0f / 512.0f);
    float var  = sq * (1.0f / 512.0f) - mean * mean;
    float rs   = rsqrtf(var + 1e-5f);
    float4 gv = ((const float4*)g)[t];
    float4 bv = ((const float4*)b)[t];
    float4 o;
    o.x = (v.x - mean) * rs * gv.x + bv.x;
    o.y = (v.y - mean) * rs * gv.y + bv.y;
    o.z = (v.z - mean) * rs * gv.z + bv.z;
    o.w = (v.w - mean) * rs * gv.w + bv.w;
    ((float4*)(out + (long)row * D))[t] = o;
}

// ---------------- launch ----------------
extern "C" void kernel_launch(void* const* d_in, const int* in_sizes, int n_in,
                              void* d_out, int out_size)
{
    const float* x    = (const float*)d_in[0];
    const float* Wk1  = (const float*)d_in[1];
    const float* bk1  = (const float*)d_in[2];
    const float* Wk2  = (const float*)d_in[3];
    const float* bk2  = (const float*)d_in[4];
    const float* Wq1  = (const float*)d_in[5];
    const float* bq1  = (const float*)d_in[6];
    const float* Wq2  = (const float*)d_in[7];
    const float* bq2  = (const float*)d_in[8];
    const float* Wv   = (const float*)d_in[9];
    const float* bv   = (const float*)d_in[10];
    const float* ln_g = (const float*)d_in[11];
    const float* ln_b = (const float*)d_in[12];
    const float* Wo   = (const float*)d_in[13];
    const float* bo   = (const float*)d_in[14];
    float* out = (float*)d_out;

    void* p;
    cudaGetSymbolAddress(&p, g_H);   float* H   = (float*)p;
    cudaGetSymbolAddress(&p, g_CSk); float* CSk = (float*)p;
    cudaGetSymbolAddress(&p, g_CSq); float* CSq = (float*)p;
    cudaGetSymbolAddress(&p, g_V);   float* V   = (float*)p;
    cudaGetSymbolAddress(&p, g_A);   float* A   = (float*)p;
    cudaGetSymbolAddress(&p, g_R);   float* R   = (float*)p;
    cudaGetSymbolAddress(&p, g_LN);  float* LN  = (float*)p;

    dim3 blk(256);

    // Hk = gelu(x @ Wk1 + bk1)            (2048 x 512 x 512)
    gemm_kernel<128,128,8,8,false,EPI_GELU><<<dim3(4,16,1), blk>>>(
        x, Wk1, bk1, nullptr, H, 2048, 512, 512, 0, 0, 0);
    // CSk = [cos|sin](tanh(Hk @ Wk2 + bk2) * pi)   (2048 x 64 x 512 -> 2048 x 128)
    gemm_kernel<128,64,8,4,false,EPI_COSSIN><<<dim3(1,16,1), blk>>>(
        H, Wk2, bk2, nullptr, CSk, 2048, 64, 512, 0, 0, 0);
    // Hq = gelu(x @ Wq1 + bq1)
    gemm_kernel<128,128,8,8,false,EPI_GELU><<<dim3(4,16,1), blk>>>(
        x, Wq1, bq1, nullptr, H, 2048, 512, 512, 0, 0, 0);
    // CSq
    gemm_kernel<128,64,8,4,false,EPI_COSSIN><<<dim3(1,16,1), blk>>>(
        H, Wq2, bq2, nullptr, CSq, 2048, 64, 512, 0, 0, 0);
    // V = x @ Wv + bv
    gemm_kernel<128,128,8,8,false,EPI_BIAS><<<dim3(4,16,1), blk>>>(
        x, Wv, bv, nullptr, V, 2048, 512, 512, 0, 0, 0);
    // A = tril(CSq @ CSk^T) per batch     (1024 x 1024 x 128, NT)
    gemm_kernel<128,128,8,8,true,EPI_CAUSAL><<<dim3(8,8,2), blk>>>(
        CSq, CSk, nullptr, nullptr, A, 1024, 1024, 128,
        1024L*128, 1024L*128, 1024L*1024);
    // R = (A @ V) * rsqrt((t+1)*64) per batch, causal-truncated K loop
    gemm_kernel<128,128,8,8,false,EPI_SCALEN><<<dim3(4,8,2), blk>>>(
        A, V, nullptr, nullptr, R, 1024, 512, 1024,
        1024L*1024, 1024L*512, 1024L*512);
    // LayerNorm rows of R
    ln_kernel<<<2048, 128>>>(R, ln_g, ln_b, LN);
    // out = x + LN @ Wo + bo
    gemm_kernel<128,128,8,8,false,EPI_RESID><<<dim3(4,16,1), blk>>>(
        LN, Wo, bo, x, out, 2048, 512, 512, 0, 0, 0);
}

// round 2
// speedup vs baseline: 1.4595x; 1.4595x over previous
#include <cuda_runtime.h>
#include <math.h>

#define PI_F 3.14159265358979323846f

// ---------------- scratch (allocation-free: __device__ globals) ----------------
__device__ float g_Hk [2048 * 512];
__device__ float g_Hq [2048 * 512];
__device__ float g_CSk[2048 * 128];   // [cos|sin] of key phase, ld=128
__device__ float g_CSq[2048 * 128];
__device__ float g_V  [2048 * 512];
__device__ float g_A  [2 * 1024 * 1024]; // causal score matrix per batch
__device__ float g_R  [2048 * 512];
__device__ float g_LN [2048 * 512];

// ---------------- epilogue kinds ----------------
#define EPI_BIAS   0
#define EPI_GELU   1
#define EPI_CAUSAL 3
#define EPI_SCALEN 4
#define EPI_RESID  5
#define EPI_XW     6   // fused x@{Wk1,Wq1,Wv}: blockIdx.z selects weight/output

// =====================================================================
// Generic double-buffered tiled SGEMM, 256 threads, BK=16.
// C[M,N] = A[M,K] @ B (B is KxN, or NxK if TRANSB), + epilogue.
// =====================================================================
template<int BM, int BN, int TM, int TN, bool TRANSB, int EPI>
__global__ __launch_bounds__(256)
void gemm_kernel(const float* __restrict__ Ag,
                 const float* __restrict__ Bg, const float* __restrict__ Bg2,
                 const float* __restrict__ Bg3,
                 const float* __restrict__ bias, const float* __restrict__ bias2,
                 const float* __restrict__ bias3,
                 const float* __restrict__ Rg,
                 float* __restrict__ Cg, float* __restrict__ Cg2,
                 float* __restrict__ Cg3,
                 int M, int N, int K,
                 long sA, long sB, long sC)
{
    constexpr int BK = 16;
    constexpr int A_LD = (BM * BK / 4) / 256;   // float4 loads per thread (A)
    constexpr int B_LD = ((TRANSB ? BN : BN) * BK / 4) / 256;

    __shared__ float As[2][BK][BM];
    __shared__ float Bs[2][BK][BN];

    const int tid = threadIdx.x;
    const int tx = tid % (BN / TN);
    const int ty = tid / (BN / TN);

    int row0, col0;
    if (EPI == EPI_CAUSAL) {
        // triangular tile map: blockIdx.x -> (i, j), j <= i
        int t = blockIdx.x;
        int i = (int)((sqrtf(8.0f * t + 1.0f) - 1.0f) * 0.5f);
        while ((i + 1) * (i + 2) / 2 <= t) i++;
        while (i * (i + 1) / 2 > t) i--;
        row0 = i * BM;
        col0 = (t - i * (i + 1) / 2) * BN;
    } else {
        row0 = blockIdx.y * BM;
        col0 = blockIdx.x * BN;
    }

    bool xw_gelu = true;
    if (EPI == EPI_XW) {
        int w = blockIdx.z;
        if (w == 1) { Bg = Bg2; bias = bias2; Cg = Cg2; }
        else if (w == 2) { Bg = Bg3; bias = bias3; Cg = Cg3; xw_gelu = false; }
    } else {
        Ag += (long)blockIdx.z * sA;
        Bg += (long)blockIdx.z * sB;
        Cg += (long)blockIdx.z * sC;
    }

    float acc[TM][TN];
    #pragma unroll
    for (int i = 0; i < TM; i++)
        #pragma unroll
        for (int j = 0; j < TN; j++) acc[i][j] = 0.0f;

    // Causal truncation of K loop for R = tril(A) @ V.
    int Kend = K;
    if (EPI == EPI_SCALEN) Kend = min(K, row0 + BM);
    const int nIter = Kend / BK;

    float4 rA[A_LD], rB[B_LD];

    auto loadA = [&](int k0) {
        #pragma unroll
        for (int l = 0; l < A_LD; l++) {
            int i = tid + l * 256;
            int r = i / (BK / 4);
            int c = (i % (BK / 4)) * 4;
            rA[l] = *(const float4*)(Ag + (long)(row0 + r) * K + k0 + c);
        }
    };
    auto storeA = [&](int b) {
        #pragma unroll
        for (int l = 0; l < A_LD; l++) {
            int i = tid + l * 256;
            int r = i / (BK / 4);
            int c = (i % (BK / 4)) * 4;
            As[b][c + 0][r] = rA[l].x; As[b][c + 1][r] = rA[l].y;
            As[b][c + 2][r] = rA[l].z; As[b][c + 3][r] = rA[l].w;
        }
    };
    auto loadB = [&](int k0) {
        if (!TRANSB) {
            #pragma unroll
            for (int l = 0; l < B_LD; l++) {
                int i = tid + l * 256;
                int r = i / (BN / 4);
                int c = (i % (BN / 4)) * 4;
                rB[l] = *(const float4*)(Bg + (long)(k0 + r) * N + col0 + c);
            }
        } else { // B is N x K row-major (ldb == K)
            #pragma unroll
            for (int l = 0; l < B_LD; l++) {
                int i = tid + l * 256;
                int n = i / (BK / 4);
                int c = (i % (BK / 4)) * 4;
                rB[l] = *(const float4*)(Bg + (long)(col0 + n) * K + k0 + c);
            }
        }
    };
    auto storeB = [&](int b) {
        if (!TRANSB) {
            #pragma unroll
            for (int l = 0; l < B_LD; l++) {
                int i = tid + l * 256;
                int r = i / (BN / 4);
                int c = (i % (BN / 4)) * 4;
                *(float4*)&Bs[b][r][c] = rB[l];
            }
        } else {
            #pragma unroll
            for (int l = 0; l < B_LD; l++) {
                int i = tid + l * 256;
                int n = i / (BK / 4);
                int c = (i % (BK / 4)) * 4;
                Bs[b][c + 0][n] = rB[l].x; Bs[b][c + 1][n] = rB[l].y;
                Bs[b][c + 2][n] = rB[l].z; Bs[b][c + 3][n] = rB[l].w;
            }
        }
    };

    // prologue: tile 0
    loadA(0); loadB(0);
    storeA(0); storeB(0);
    __syncthreads();

    int buf = 0;
    for (int it = 0; it < nIter; ++it) {
        if (it + 1 < nIter) { loadA((it + 1) * BK); loadB((it + 1) * BK); }

        #pragma unroll
        for (int k = 0; k < BK; k++) {
            float a[TM], b[TN];
            #pragma unroll
            for (int i = 0; i < TM / 4; i++) {
                float4 t4 = *(const float4*)&As[buf][k][ty * TM + i * 4];
                a[i*4+0] = t4.x; a[i*4+1] = t4.y; a[i*4+2] = t4.z; a[i*4+3] = t4.w;
            }
            #pragma unroll
            for (int j = 0; j < TN / 4; j++) {
                float4 t4 = *(const float4*)&Bs[buf][k][tx * TN + j * 4];
                b[j*4+0] = t4.x; b[j*4+1] = t4.y; b[j*4+2] = t4.z; b[j*4+3] = t4.w;
            }
            #pragma unroll
            for (int i = 0; i < TM; i++)
                #pragma unroll
                for (int j = 0; j < TN; j++)
                    acc[i][j] = fmaf(a[i], b[j], acc[i][j]);
        }

        if (it + 1 < nIter) { storeA(buf ^ 1); storeB(buf ^ 1); }
        __syncthreads();
        buf ^= 1;
    }

    // ---- epilogue
    #pragma unroll
    for (int i = 0; i < TM; i++) {
        int row = row0 + ty * TM + i;
        #pragma unroll
        for (int j = 0; j < TN; j++) {
            int col = col0 + tx * TN + j;
            float v = acc[i][j];
            if (EPI == EPI_BIAS) {
                Cg[(long)row * N + col] = v + bias[col];
            } else if (EPI == EPI_GELU) {
                float t = v + bias[col];
                Cg[(long)row * N + col] = 0.5f * t * (1.0f + erff(t * 0.70710678118654752f));
            } else if (EPI == EPI_XW) {
                float t = v + bias[col];
                Cg[(long)row * N + col] =
                    xw_gelu ? 0.5f * t * (1.0f + erff(t * 0.70710678118654752f)) : t;
            } else if (EPI == EPI_CAUSAL) {
                Cg[(long)row * N + col] = (col <= row) ? v : 0.0f;
            } else if (EPI == EPI_SCALEN) {
                Cg[(long)row * N + col] = v * rsqrtf((float)(row + 1) * 64.0f);
            } else { // EPI_RESID
                Cg[(long)row * N + col] = Rg[(long)row * N + col] + v + bias[col];
            }
        }
    }
}

// =====================================================================
// Phase kernel: CS = [cos|sin](tanh(H @ W2 + b2) * pi), H: 2048x512, W2: 512x64
// 32-row tiles, z selects key/query. grid (64,1,2), 256 threads.
// =====================================================================
__global__ __launch_bounds__(256)
void phase_kernel(const float* __restrict__ Hk, const float* __restrict__ Hq,
                  const float* __restrict__ Wk2, const float* __restrict__ Wq2,
                  const float* __restrict__ bk2, const float* __restrict__ bq2,
                  float* __restrict__ CSk, float* __restrict__ CSq)
{
    const int z = blockIdx.z;
    const float* H  = z ? Hq  : Hk;
    const float* W  = z ? Wq2 : Wk2;
    const float* bb = z ? bq2 : bk2;
    float* CS = z ? CSq : CSk;

    const int row0 = blockIdx.x * 32;
    __shared__ float As[32][33];   // [k][m], padded
    __shared__ float Bs[32][64];   // [k][n]

    const int tid = threadIdx.x;
    const int tx = tid % 16;       // 16 cols of TN=4
    const int ty = tid / 16;       // 16 rows of TM=2
    float acc[2][4] = {{0,0,0,0},{0,0,0,0}};

    for (int k0 = 0; k0 < 512; k0 += 32) {
        { // A: 32 rows x 32 k = 256 float4, one per thread
            int r = tid / 8, c = (tid % 8) * 4;
            float4 v = *(const float4*)(H + (long)(row0 + r) * 512 + k0 + c);
            As[c + 0][r] = v.x; As[c + 1][r] = v.y;
            As[c + 2][r] = v.z; As[c + 3][r] = v.w;
        }
        #pragma unroll
        for (int l = 0; l < 2; l++) { // B: 32 k x 64 n = 512 float4
            int i = tid + l * 256;
            int r = i / 16, c = (i % 16) * 4;
            *(float4*)&Bs[r][c] = *(const float4*)(W + (long)(k0 + r) * 64 + c);
        }
        __syncthreads();
        #pragma unroll
        for (int k = 0; k < 32; k++) {
            float a0 = As[k][ty * 2], a1 = As[k][ty * 2 + 1];
            float4 b = *(const float4*)&Bs[k][tx * 4];
            acc[0][0] = fmaf(a0, b.x, acc[0][0]); acc[0][1] = fmaf(a0, b.y, acc[0][1]);
            acc[0][2] = fmaf(a0, b.z, acc[0][2]); acc[0][3] = fmaf(a0, b.w, acc[0][3]);
            acc[1][0] = fmaf(a1, b.x, acc[1][0]); acc[1][1] = fmaf(a1, b.y, acc[1][1]);
            acc[1][2] = fmaf(a1, b.z, acc[1][2]); acc[1][3] = fmaf(a1, b.w, acc[1][3]);
        }
        __syncthreads();
    }

    #pragma unroll
    for (int i = 0; i < 2; i++) {
        int row = row0 + ty * 2 + i;
        #pragma unroll
        for (int j = 0; j < 4; j++) {
            int col = tx * 4 + j;
            float p = tanhf(acc[i][j] + bb[col]) * PI_F;
            float s, c;
            sincosf(p, &s, &c);
            CS[(long)row * 128 + col]      = c;
            CS[(long)row * 128 + 64 + col] = s;
        }
    }
}

// ---------------- LayerNorm over D=512, one row per block ----------------
__global__ __launch_bounds__(128)
void ln_kernel(const float* __restrict__ X, const float* __restrict__ g,
               const float* __restrict__ b, float* __restrict__ out)
{
    const int D = 512;
    int row = blockIdx.x;
    int t = threadIdx.x;
    float4 v = ((const float4*)(X + (long)row * D))[t];
    float s  = v.x + v.y + v.z + v.w;
    float sq = v.x * v.x + v.y * v.y + v.z * v.z + v.w * v.w;
    #pragma unroll
    for (int o = 16; o; o >>= 1) {
        s  += __shfl_xor_sync(0xFFFFFFFFu, s, o);
        sq += __shfl_xor_sync(0xFFFFFFFFu, sq, o);
    }
    __shared__ float ss[4], ssq[4];
    int w = t >> 5, l = t & 31;
    if (l == 0) { ss[w] = s; ssq[w] = sq; }
    __syncthreads();
    s  = ss[0] + ss[1] + ss[2] + ss[3];
    sq = ssq[0] + ssq[1] + ssq[2] + ssq[3];
    float mean = s * (1.0f / 512.0f);
    float var  = sq * (1.0f / 512.0f) - mean * mean;
    float rs   = rsqrtf(var + 1e-5f);
    float4 gv = ((const float4*)g)[t];
    float4 bv = ((const float4*)b)[t];
    float4 o;
    o.x = (v.x - mean) * rs * gv.x + bv.x;
    o.y = (v.y - mean) * rs * gv.y + bv.y;
    o.z = (v.z - mean) * rs * gv.z + bv.z;
    o.w = (v.w - mean) * rs * gv.w + bv.w;
    ((float4*)(out + (long)row * D))[t] = o;
}

// ---------------- launch ----------------
extern "C" void kernel_launch(void* const* d_in, const int* in_sizes, int n_in,
                              void* d_out, int out_size)
{
    const float* x    = (const float*)d_in[0];
    const float* Wk1  = (const float*)d_in[1];
    const float* bk1  = (const float*)d_in[2];
    const float* Wk2  = (const float*)d_in[3];
    const float* bk2  = (const float*)d_in[4];
    const float* Wq1  = (const float*)d_in[5];
    const float* bq1  = (const float*)d_in[6];
    const float* Wq2  = (const float*)d_in[7];
    const float* bq2  = (const float*)d_in[8];
    const float* Wv   = (const float*)d_in[9];
    const float* bv   = (const float*)d_in[10];
    const float* ln_g = (const float*)d_in[11];
    const float* ln_b = (const float*)d_in[12];
    const float* Wo   = (const float*)d_in[13];
    const float* bo   = (const float*)d_in[14];
    float* out = (float*)d_out;

    void* p;
    cudaGetSymbolAddress(&p, g_Hk);  float* Hk  = (float*)p;
    cudaGetSymbolAddress(&p, g_Hq);  float* Hq  = (float*)p;
    cudaGetSymbolAddress(&p, g_CSk); float* CSk = (float*)p;
    cudaGetSymbolAddress(&p, g_CSq); float* CSq = (float*)p;
    cudaGetSymbolAddress(&p, g_V);   float* V   = (float*)p;
    cudaGetSymbolAddress(&p, g_A);   float* A   = (float*)p;
    cudaGetSymbolAddress(&p, g_R);   float* R   = (float*)p;
    cudaGetSymbolAddress(&p, g_LN);  float* LN  = (float*)p;

    dim3 blk(256);

    // Fused: Hk = gelu(x@Wk1+bk1), Hq = gelu(x@Wq1+bq1), V = x@Wv+bv
    // grid (4,16,3) = 192 blocks.
    gemm_kernel<128,128,8,8,false,EPI_XW><<<dim3(4,16,3), blk>>>(
        x, Wk1, Wq1, Wv, bk1, bq1, bv, nullptr,
        Hk, Hq, V, 2048, 512, 512, 0, 0, 0);

    // Phases: CSk / CSq, grid (64,1,2) = 128 blocks
    phase_kernel<<<dim3(64,1,2), blk>>>(Hk, Hq, Wk2, Wq2, bk2, bq2, CSk, CSq);

    // A = tril(CSq @ CSk^T) per batch, lower/diag tiles only: 36 per batch
    gemm_kernel<128,128,8,8,true,EPI_CAUSAL><<<dim3(36,1,2), blk>>>(
        CSq, CSk, nullptr, nullptr, nullptr, nullptr, nullptr, nullptr,
        A, nullptr, nullptr, 1024, 1024, 128,
        1024L*128, 1024L*128, 1024L*1024);

    // R = (A @ V) * rsqrt((t+1)*64), causal-truncated K, grid (4,16,2) = 128
    gemm_kernel<64,128,4,8,false,EPI_SCALEN><<<dim3(4,16,2), blk>>>(
        A, V, nullptr, nullptr, nullptr, nullptr, nullptr, nullptr,
        R, nullptr, nullptr, 1024, 512, 1024,
        1024L*1024, 1024L*512, 1024L*512);

    // LayerNorm rows of R
    ln_kernel<<<2048, 128>>>(R, ln_g, ln_b, LN);

    // out = x + LN @ Wo + bo, grid (4,32) = 128 blocks
    gemm_kernel<64,128,4,8,false,EPI_RESID><<<dim3(4,32,1), blk>>>(
        LN, Wo, nullptr, nullptr, bo, nullptr, nullptr, x,
        out, nullptr, nullptr, 2048, 512, 512, 0, 0, 0);
}

// round 3
// speedup vs baseline: 1.8819x; 1.2894x over previous
#include <cuda_runtime.h>
#include <math.h>

#define PI_F 3.14159265358979323846f

// ---------------- scratch (allocation-free: __device__ globals) ----------------
__device__ float g_Hk [2048 * 512];
__device__ float g_Hq [2048 * 512];
__device__ float g_CSk[2048 * 128];     // [cos|sin] key phase, ld=128
__device__ float g_CSq[2048 * 128];
__device__ float g_V  [2048 * 512];
__device__ float g_S  [16 * 128 * 512]; // per-chunk states CSk_c^T @ V_c
__device__ float g_P  [16 * 128 * 512]; // exclusive prefix of states
__device__ float g_Ac [16 * 128 * 128]; // per-chunk masked diagonal scores
__device__ float g_R  [2048 * 512];
__device__ float g_LN [2048 * 512];

// ---------------- epilogue kinds ----------------
#define EPI_NONE   0
#define EPI_CAUSAL 1
#define EPI_RESID  2
#define EPI_XW     3

// f32x2 helpers
__device__ __forceinline__ unsigned long long pack2(float a) {
    unsigned long long r;
    asm("mov.b64 %0, {%1, %1};" : "=l"(r) : "r"(__float_as_uint(a)));
    return r;
}
__device__ __forceinline__ void fma2(unsigned long long& acc,
                                     unsigned long long a, unsigned long long b) {
    asm("fma.rn.f32x2 %0, %1, %2, %0;" : "+l"(acc) : "l"(a), "l"(b));
}

// =====================================================================
// Generic double-buffered GEMM with packed-f32x2 inner loop.
// C[M,N] = op(A) @ op(B) + epilogue. BK=16.
//  TRANSA: A stored [K][M] (ld=ldA over k-rows)  -> direct vector As load
//  TRANSB: B stored [N][K] (ld=ldB over n-rows)
// =====================================================================
template<int BM, int BN, int TM, int TN, int THREADS,
         bool TRANSA, bool TRANSB, int EPI>
__global__ __launch_bounds__(THREADS)
void gemm_f32x2(const float* __restrict__ Ag,
                const float* __restrict__ Bg, const float* __restrict__ Bg2,
                const float* __restrict__ Bg3,
                const float* __restrict__ bias, const float* __restrict__ bias2,
                const float* __restrict__ bias3,
                const float* __restrict__ Rg,
                float* __restrict__ Cg, float* __restrict__ Cg2,
                float* __restrict__ Cg3,
                int M, int N, int K, int ldA, int ldB, int ldC,
                long zA, long zB, long zC)
{
    constexpr int BK = 16;
    constexpr int A_LD = (BM * BK / 4) / THREADS;
    constexpr int B_LD = (BN * BK / 4) / THREADS;
    constexpr int TN2 = TN / 2;

    __shared__ float As[2][BK][BM];
    __shared__ float Bs[2][BK][BN];

    const int tid = threadIdx.x;
    const int tx = tid % (BN / TN);
    const int ty = tid / (BN / TN);
    const int row0 = blockIdx.y * BM;
    const int col0 = blockIdx.x * BN;

    bool xw_gelu = true;
    if (EPI == EPI_XW) {
        int w = blockIdx.z;
        if (w == 1) { Bg = Bg2; bias = bias2; Cg = Cg2; }
        else if (w == 2) { Bg = Bg3; bias = bias3; Cg = Cg3; xw_gelu = false; }
    } else {
        Ag += (long)blockIdx.z * zA;
        Bg += (long)blockIdx.z * zB;
        Cg += (long)blockIdx.z * zC;
    }

    unsigned long long acc2[TM][TN2];
    #pragma unroll
    for (int i = 0; i < TM; i++)
        #pragma unroll
        for (int j = 0; j < TN2; j++) acc2[i][j] = 0ull;

    float4 rA[A_LD], rB[B_LD];

    auto loadA = [&](int k0) {
        if (!TRANSA) {
            #pragma unroll
            for (int l = 0; l < A_LD; l++) {
                int i = tid + l * THREADS;
                int r = i / (BK / 4);
                int c = (i % (BK / 4)) * 4;
                rA[l] = *(const float4*)(Ag + (long)(row0 + r) * ldA + k0 + c);
            }
        } else { // A stored [k][m]
            #pragma unroll
            for (int l = 0; l < A_LD; l++) {
                int i = tid + l * THREADS;
                int kk = i / (BM / 4);
                int mc = (i % (BM / 4)) * 4;
                rA[l] = *(const float4*)(Ag + (long)(k0 + kk) * ldA + row0 + mc);
            }
        }
    };
    auto storeA = [&](int b) {
        if (!TRANSA) {
            #pragma unroll
            for (int l = 0; l < A_LD; l++) {
                int i = tid + l * THREADS;
                int r = i / (BK / 4);
                int c = (i % (BK / 4)) * 4;
                As[b][c + 0][r] = rA[l].x; As[b][c + 1][r] = rA[l].y;
                As[b][c + 2][r] = rA[l].z; As[b][c + 3][r] = rA[l].w;
            }
        } else {
            #pragma unroll
            for (int l = 0; l < A_LD; l++) {
                int i = tid + l * THREADS;
                int kk = i / (BM / 4);
                int mc = (i % (BM / 4)) * 4;
                *(float4*)&As[b][kk][mc] = rA[l];
            }
        }
    };
    auto loadB = [&](int k0) {
        if (!TRANSB) {
            #pragma unroll
            for (int l = 0; l < B_LD; l++) {
                int i = tid + l * THREADS;
                int r = i / (BN / 4);
                int c = (i % (BN / 4)) * 4;
                rB[l] = *(const float4*)(Bg + (long)(k0 + r) * ldB + col0 + c);
            }
        } else { // B stored [n][k]
            #pragma unroll
            for (int l = 0; l < B_LD; l++) {
                int i = tid + l * THREADS;
                int n = i / (BK / 4);
                int c = (i % (BK / 4)) * 4;
                rB[l] = *(const float4*)(Bg + (long)(col0 + n) * ldB + k0 + c);
            }
        }
    };
    auto storeB = [&](int b) {
        if (!TRANSB) {
            #pragma unroll
            for (int l = 0; l < B_LD; l++) {
                int i = tid + l * THREADS;
                int r = i / (BN / 4);
                int c = (i % (BN / 4)) * 4;
                *(float4*)&Bs[b][r][c] = rB[l];
            }
        } else {
            #pragma unroll
            for (int l = 0; l < B_LD; l++) {
                int i = tid + l * THREADS;
                int n = i / (BK / 4);
                int c = (i % (BK / 4)) * 4;
                Bs[b][c + 0][n] = rB[l].x; Bs[b][c + 1][n] = rB[l].y;
                Bs[b][c + 2][n] = rB[l].z; Bs[b][c + 3][n] = rB[l].w;
            }
        }
    };

    const int nIter = K / BK;
    loadA(0); loadB(0);
    storeA(0); storeB(0);
    __syncthreads();

    int buf = 0;
    for (int it = 0; it < nIter; ++it) {
        if (it + 1 < nIter) { loadA((it + 1) * BK); loadB((it + 1) * BK); }

        #pragma unroll
        for (int k = 0; k < BK; k++) {
            float a[TM];
            #pragma unroll
            for (int i = 0; i < TM / 4; i++) {
                float4 t4 = *(const float4*)&As[buf][k][ty * TM + i * 4];
                a[i*4+0] = t4.x; a[i*4+1] = t4.y; a[i*4+2] = t4.z; a[i*4+3] = t4.w;
            }
            unsigned long long bv[TN2];
            #pragma unroll
            for (int j = 0; j < TN / 4; j++) {
                ulonglong2 u = *(const ulonglong2*)&Bs[buf][k][tx * TN + j * 4];
                bv[j*2] = u.x; bv[j*2+1] = u.y;
            }
            #pragma unroll
            for (int i = 0; i < TM; i++) {
                unsigned long long av = pack2(a[i]);
                #pragma unroll
                for (int j = 0; j < TN2; j++) fma2(acc2[i][j], av, bv[j]);
            }
        }

        if (it + 1 < nIter) { storeA(buf ^ 1); storeB(buf ^ 1); }
        __syncthreads();
        buf ^= 1;
    }

    // ---- epilogue
    #pragma unroll
    for (int i = 0; i < TM; i++) {
        int row = row0 + ty * TM + i;
        #pragma unroll
        for (int jp = 0; jp < TN2; jp++) {
            float2 f = *reinterpret_cast<float2*>(&acc2[i][jp]);
            int col = col0 + tx * TN + jp * 2;
            #pragma unroll
            for (int e = 0; e < 2; e++) {
                float v = e ? f.y : f.x;
                int cc = col + e;
                if (EPI == EPI_NONE) {
                    Cg[(long)row * ldC + cc] = v;
                } else if (EPI == EPI_XW) {
                    float t = v + bias[cc];
                    Cg[(long)row * ldC + cc] =
                        xw_gelu ? 0.5f * t * (1.0f + erff(t * 0.70710678118654752f)) : t;
                } else if (EPI == EPI_CAUSAL) {
                    Cg[(long)row * ldC + cc] = (cc <= row) ? v : 0.0f;
                } else { // EPI_RESID
                    Cg[(long)row * ldC + cc] = Rg[(long)row * ldC + cc] + v + bias[cc];
                }
            }
        }
    }
}

// =====================================================================
// Rfinal: R[row, n] = sum_k<128 CSq[row,k] * P[c][k,n]
//                   + sum_k<128 Ac[c][row%128,k] * V[c*128+k, n], scaled.
// BM=64, BN=128, TM=TN=8, 128 threads. K=256 (or 128 for first chunk).
// =====================================================================
__global__ __launch_bounds__(128)
void rfinal_kernel(const float* __restrict__ CSq, const float* __restrict__ Ac,
                   const float* __restrict__ P, const float* __restrict__ V,
                   float* __restrict__ R)
{
    constexpr int BK = 16;
    __shared__ float As[2][BK][64];
    __shared__ float Bs[2][BK][128];

    const int tid = threadIdx.x;
    const int tx = tid % 16;
    const int ty = tid / 16;
    const int row0 = blockIdx.y * 64;
    const int col0 = blockIdx.x * 128;
    const int c = row0 >> 7;           // global chunk 0..15
    const int kstart = ((c & 7) == 0) ? 128 : 0;

    unsigned long long acc2[8][4];
    #pragma unroll
    for (int i = 0; i < 8; i++)
        #pragma unroll
        for (int j = 0; j < 4; j++) acc2[i][j] = 0ull;

    float4 rA[2], rB[4];
    auto loadA = [&](int k0) {
        #pragma unroll
        for (int l = 0; l < 2; l++) {
            int i = tid + l * 128;
            int r = i / 4;
            int cc = (i % 4) * 4;
            const float* src = (k0 < 128)
                ? CSq + (long)(row0 + r) * 128 + k0 + cc
                : Ac + (long)c * 16384 + (long)((row0 & 127) + r) * 128 + (k0 - 128) + cc;
            rA[l] = *(const float4*)src;
        }
    };
    auto storeA = [&](int b) {
        #pragma unroll
        for (int l = 0; l < 2; l++) {
            int i = tid + l * 128;
            int r = i / 4;
            int cc = (i % 4) * 4;
            As[b][cc + 0][r] = rA[l].x; As[b][cc + 1][r] = rA[l].y;
            As[b][cc + 2][r] = rA[l].z; As[b][cc + 3][r] = rA[l].w;
        }
    };
    auto loadB = [&](int k0) {
        #pragma unroll
        for (int l = 0; l < 4; l++) {
            int i = tid + l * 128;
            int r = i / 32;
            int cc = (i % 32) * 4;
            const float* src = (k0 < 128)
                ? P + (long)c * 65536 + (long)(k0 + r) * 512 + col0 + cc
                : V + ((long)c * 128 + (k0 - 128) + r) * 512 + col0 + cc;
            rB[l] = *(const float4*)src;
        }
    };
    auto storeB = [&](int b) {
        #pragma unroll
        for (int l = 0; l < 4; l++) {
            int i = tid + l * 128;
            int r = i / 32;
            int cc = (i % 32) * 4;
            *(float4*)&Bs[b][r][cc] = rB[l];
        }
    };

    const int nIter = (256 - kstart) / BK;
    loadA(kstart); loadB(kstart);
    storeA(0); storeB(0);
    __syncthreads();

    int buf = 0;
    for (int it = 0; it < nIter; ++it) {
        if (it + 1 < nIter) { loadA(kstart + (it + 1) * BK); loadB(kstart + (it + 1) * BK); }
        #pragma unroll
        for (int k = 0; k < BK; k++) {
            float a[8];
            #pragma unroll
            for (int i = 0; i < 2; i++) {
                float4 t4 = *(const float4*)&As[buf][k][ty * 8 + i * 4];
                a[i*4+0] = t4.x; a[i*4+1] = t4.y; a[i*4+2] = t4.z; a[i*4+3] = t4.w;
            }
            unsigned long long bv[4];
            #pragma unroll
            for (int j = 0; j < 2; j++) {
                ulonglong2 u = *(const ulonglong2*)&Bs[buf][k][tx * 8 + j * 4];
                bv[j*2] = u.x; bv[j*2+1] = u.y;
            }
            #pragma unroll
            for (int i = 0; i < 8; i++) {
                unsigned long long av = pack2(a[i]);
                #pragma unroll
                for (int j = 0; j < 4; j++) fma2(acc2[i][j], av, bv[j]);
            }
        }
        if (it + 1 < nIter) { storeA(buf ^ 1); storeB(buf ^ 1); }
        __syncthreads();
        buf ^= 1;
    }

    #pragma unroll
    for (int i = 0; i < 8; i++) {
        int row = row0 + ty * 8 + i;
        float scale = rsqrtf((float)((row & 1023) + 1) * 64.0f);
        #pragma unroll
        for (int jp = 0; jp < 4; jp++) {
            float2 f = *reinterpret_cast<float2*>(&acc2[i][jp]);
            int col = col0 + tx * 8 + jp * 2;
            R[(long)row * 512 + col]     = f.x * scale;
            R[(long)row * 512 + col + 1] = f.y * scale;
        }
    }
}

// =====================================================================
// Phase kernel: CS = [cos|sin](tanh(H @ W2 + b2) * pi)
// =====================================================================
__global__ __launch_bounds__(256)
void phase_kernel(const float* __restrict__ Hk, const float* __restrict__ Hq,
                  const float* __restrict__ Wk2, const float* __restrict__ Wq2,
                  const float* __restrict__ bk2, const float* __restrict__ bq2,
                  float* __restrict__ CSk, float* __restrict__ CSq)
{
    const int z = blockIdx.z;
    const float* H  = z ? Hq  : Hk;
    const float* W  = z ? Wq2 : Wk2;
    const float* bb = z ? bq2 : bk2;
    float* CS = z ? CSq : CSk;

    const int row0 = blockIdx.x * 32;
    __shared__ float As[32][33];
    __shared__ float Bs[32][64];

    const int tid = threadIdx.x;
    const int tx = tid % 16;
    const int ty = tid / 16;
    float acc[2][4] = {{0,0,0,0},{0,0,0,0}};

    for (int k0 = 0; k0 < 512; k0 += 32) {
        {
            int r = tid / 8, c = (tid % 8) * 4;
            float4 v = *(const float4*)(H + (long)(row0 + r) * 512 + k0 + c);
            As[c + 0][r] = v.x; As[c + 1][r] = v.y;
            As[c + 2][r] = v.z; As[c + 3][r] = v.w;
        }
        #pragma unroll
        for (int l = 0; l < 2; l++) {
            int i = tid + l * 256;
            int r = i / 16, c = (i % 16) * 4;
            *(float4*)&Bs[r][c] = *(const float4*)(W + (long)(k0 + r) * 64 + c);
        }
        __syncthreads();
        #pragma unroll
        for (int k = 0; k < 32; k++) {
            float a0 = As[k][ty * 2], a1 = As[k][ty * 2 + 1];
            float4 b = *(const float4*)&Bs[k][tx * 4];
            acc[0][0] = fmaf(a0, b.x, acc[0][0]); acc[0][1] = fmaf(a0, b.y, acc[0][1]);
            acc[0][2] = fmaf(a0, b.z, acc[0][2]); acc[0][3] = fmaf(a0, b.w, acc[0][3]);
            acc[1][0] = fmaf(a1, b.x, acc[1][0]); acc[1][1] = fmaf(a1, b.y, acc[1][1]);
            acc[1][2] = fmaf(a1, b.z, acc[1][2]); acc[1][3] = fmaf(a1, b.w, acc[1][3]);
        }
        __syncthreads();
    }

    #pragma unroll
    for (int i = 0; i < 2; i++) {
        int row = row0 + ty * 2 + i;
        #pragma unroll
        for (int j = 0; j < 4; j++) {
            int col = tx * 4 + j;
            float p = tanhf(acc[i][j] + bb[col]) * PI_F;
            float s, c;
            sincosf(p, &s, &c);
            CS[(long)row * 128 + col]      = c;
            CS[(long)row * 128 + 64 + col] = s;
        }
    }
}

// ---------------- exclusive prefix over 8 chunks per batch ----------------
__global__ __launch_bounds__(256)
void prefix_kernel(const float4* __restrict__ S, float4* __restrict__ P)
{
    int g = blockIdx.x * 256 + threadIdx.x;     // [0, 32768)
    int b = g >> 14;                            // batch
    int i = g & 16383;                          // float4 index within chunk
    long base = (long)b * 8 * 16384 + i;
    float4 run = make_float4(0.f, 0.f, 0.f, 0.f);
    #pragma unroll
    for (int c = 0; c < 8; c++) {
        long idx = base + (long)c * 16384;
        P[idx] = run;
        float4 s = S[idx];
        run.x += s.x; run.y += s.y; run.z += s.z; run.w += s.w;
    }
}

// ---------------- LayerNorm over D=512 ----------------
__global__ __launch_bounds__(128)
void ln_kernel(const float* __restrict__ X, const float* __restrict__ g,
               const float* __restrict__ b, float* __restrict__ out)
{
    const int D = 512;
    int row = blockIdx.x;
    int t = threadIdx.x;
    float4 v = ((const float4*)(X + (long)row * D))[t];
    float s  = v.x + v.y + v.z + v.w;
    float sq = v.x * v.x + v.y * v.y + v.z * v.z + v.w * v.w;
    #pragma unroll
    for (int o = 16; o; o >>= 1) {
        s  += __shfl_xor_sync(0xFFFFFFFFu, s, o);
        sq += __shfl_xor_sync(0xFFFFFFFFu, sq, o);
    }
    __shared__ float ss[4], ssq[4];
    int w = t >> 5, l = t & 31;
    if (l == 0) { ss[w] = s; ssq[w] = sq; }
    __syncthreads();
    s  = ss[0] + ss[1] + ss[2] + ss[3];
    sq = ssq[0] + ssq[1] + ssq[2] + ssq[3];
    float mean = s * (1.0f / 512.0f);
    float var  = sq * (1.0f / 512.0f) - mean * mean;
    float rs   = rsqrtf(var + 1e-5f);
    float4 gv = ((const float4*)g)[t];
    float4 bv = ((const float4*)b)[t];
    float4 o;
    o.x = (v.x - mean) * rs * gv.x + bv.x;
    o.y = (v.y - mean) * rs * gv.y + bv.y;
    o.z = (v.z - mean) * rs * gv.z + bv.z;
    o.w = (v.w - mean) * rs * gv.w + bv.w;
    ((float4*)(out + (long)row * D))[t] = o;
}

// ---------------- launch ----------------
extern "C" void kernel_launch(void* const* d_in, const int* in_sizes, int n_in,
                              void* d_out, int out_size)
{
    const float* x    = (const float*)d_in[0];
    const float* Wk1  = (const float*)d_in[1];
    const float* bk1  = (const float*)d_in[2];
    const float* Wk2  = (const float*)d_in[3];
    const float* bk2  = (const float*)d_in[4];
    const float* Wq1  = (const float*)d_in[5];
    const float* bq1  = (const float*)d_in[6];
    const float* Wq2  = (const float*)d_in[7];
    const float* bq2  = (const float*)d_in[8];
    const float* Wv   = (const float*)d_in[9];
    const float* bv   = (const float*)d_in[10];
    const float* ln_g = (const float*)d_in[11];
    const float* ln_b = (const float*)d_in[12];
    const float* Wo   = (const float*)d_in[13];
    const float* bo   = (const float*)d_in[14];
    float* out = (float*)d_out;

    void* p;
    cudaGetSymbolAddress(&p, g_Hk);  float* Hk  = (float*)p;
    cudaGetSymbolAddress(&p, g_Hq);  float* Hq  = (float*)p;
    cudaGetSymbolAddress(&p, g_CSk); float* CSk = (float*)p;
    cudaGetSymbolAddress(&p, g_CSq); float* CSq = (float*)p;
    cudaGetSymbolAddress(&p, g_V);   float* V   = (float*)p;
    cudaGetSymbolAddress(&p, g_S);   float* S   = (float*)p;
    cudaGetSymbolAddress(&p, g_P);   float* P   = (float*)p;
    cudaGetSymbolAddress(&p, g_Ac);  float* Ac  = (float*)p;
    cudaGetSymbolAddress(&p, g_R);   float* R   = (float*)p;
    cudaGetSymbolAddress(&p, g_LN);  float* LN  = (float*)p;

    // 1) Fused projections: Hk, Hq (GELU) and V (bias). grid 192.
    gemm_f32x2<128,128,8,8,256,false,false,EPI_XW><<<dim3(4,16,3), 256>>>(
        x, Wk1, Wq1, Wv, bk1, bq1, bv, nullptr,
        Hk, Hq, V, 2048, 512, 512, 512, 512, 512, 0, 0, 0);

    // 2) Phases
    phase_kernel<<<dim3(64,1,2), 256>>>(Hk, Hq, Wk2, Wq2, bk2, bq2, CSk, CSq);

    // 3) Diagonal scores Ac[c] = tril(CSq_c @ CSk_c^T), 16 chunks
    gemm_f32x2<128,128,8,8,256,false,true,EPI_CAUSAL><<<dim3(1,1,16), 256>>>(
        CSq, CSk, nullptr, nullptr, nullptr, nullptr, nullptr, nullptr,
        Ac, nullptr, nullptr, 128, 128, 128, 128, 128, 128,
        16384, 16384, 16384);

    // 4) States S[c] = CSk_c^T @ V_c  (TRANSA)
    gemm_f32x2<128,128,8,8,256,true,false,EPI_NONE><<<dim3(4,1,16), 256>>>(
        CSk, V, nullptr, nullptr, nullptr, nullptr, nullptr, nullptr,
        S, nullptr, nullptr, 128, 512, 128, 128, 512, 512,
        16384, 65536, 65536);

    // 5) Exclusive prefix of states per batch
    prefix_kernel<<<128, 256>>>((const float4*)S, (float4*)P);

    // 6) R = (CSq_c @ P_c + Ac_c @ V_c) * rsqrt((t+1)*64)
    rfinal_kernel<<<dim3(4,32), 128>>>(CSq, Ac, P, V, R);

    // 7) LayerNorm
    ln_kernel<<<2048, 128>>>(R, ln_g, ln_b, LN);

    // 8) out = x + LN @ Wo + bo. grid 128.
    gemm_f32x2<64,128,8,8,128,false,false,EPI_RESID><<<dim3(4,32,1), 128>>>(
        LN, Wo, nullptr, nullptr, bo, nullptr, nullptr, x,
        out, nullptr, nullptr, 2048, 512, 512, 512, 512, 512, 0, 0, 0);
}

// round 5
// speedup vs baseline: 2.6450x; 1.4055x over previous
#include <cuda_runtime.h>
#include <cuda_bf16.h>
#include <math.h>
#include <stdint.h>

#define PI_F 3.14159265358979323846f

// ---------------- scratch (allocation-free: __device__ globals) ----------------
__device__ float g_Hk [2048 * 512];
__device__ float g_Hq [2048 * 512];
__device__ float g_CSk[2048 * 128];
__device__ float g_CSq[2048 * 128];
__device__ float g_V  [2048 * 512];
__device__ float g_S  [16 * 128 * 512];
__device__ float g_P  [16 * 128 * 512];
__device__ float g_Ac [16 * 128 * 128];
__device__ float g_R  [2048 * 512];
__device__ __nv_bfloat16 g_xh [2048 * 512];
__device__ __nv_bfloat16 g_xl [2048 * 512];
__device__ __nv_bfloat16 g_LNh[2048 * 512];
__device__ __nv_bfloat16 g_LNl[2048 * 512];
__device__ __nv_bfloat16 g_Wth[4 * 512 * 512];  // transposed weights hi: Wk1,Wq1,Wv,Wo
__device__ __nv_bfloat16 g_Wtl[4 * 512 * 512];

#define EPI_NONE   0
#define EPI_CAUSAL 1

// ================= PTX helpers =================
__device__ __forceinline__ uint32_t smem_u32(const void* p) {
    uint32_t a;
    asm("{ .reg .u64 t; cvta.to.shared.u64 t, %1; cvt.u32.u64 %0, t; }" : "=r"(a) : "l"(p));
    return a;
}
__device__ __forceinline__ void cp16(uint32_t dst, const void* src) {
    asm volatile("cp.async.cg.shared.global [%0], [%1], 16;" :: "r"(dst), "l"(src));
}
__device__ __forceinline__ void ldx4(uint32_t* r, uint32_t addr) {
    asm volatile("ldmatrix.sync.aligned.m8n8.x4.shared.b16 {%0,%1,%2,%3}, [%4];"
        : "=r"(r[0]), "=r"(r[1]), "=r"(r[2]), "=r"(r[3]) : "r"(addr));
}
__device__ __forceinline__ void mma16816(float* c, const uint32_t* a,
                                         uint32_t b0, uint32_t b1) {
    asm volatile("mma.sync.aligned.m16n8k16.row.col.f32.bf16.bf16.f32 "
        "{%0,%1,%2,%3}, {%4,%5,%6,%7}, {%8,%9}, {%0,%1,%2,%3};"
        : "+f"(c[0]), "+f"(c[1]), "+f"(c[2]), "+f"(c[3])
        : "r"(a[0]), "r"(a[1]), "r"(a[2]), "r"(a[3]), "r"(b0), "r"(b1));
}

// ================= mma.sync split-bf16 GEMM =================
// C[M,512] = A[M,512] @ W^T (+ bias [+gelu] [+resid]) with A=Ah+Al, W=Wh+Wl,
// accumulating Ah*Wh + Al*Wh + Ah*Wl in fp32. 128x128x32 tiles.
// smem: 4 arrays (Ah,Al,Bh,Bl) x 2 buffers, each 128 rows x 80B pitch.
static constexpr int MM_PITCH = 80;                 // 32 bf16 + 8 pad
static constexpr int MM_ARR   = 128 * MM_PITCH;     // 10240
static constexpr int MM_BUF   = 4 * MM_ARR;         // 40960
static constexpr int MM_SMEM  = 2 * MM_BUF;         // 81920

template<bool XW>
__global__ __launch_bounds__(256)
void mma_gemm(const __nv_bfloat16* __restrict__ Ah, const __nv_bfloat16* __restrict__ Al,
              const __nv_bfloat16* __restrict__ Wth, const __nv_bfloat16* __restrict__ Wtl,
              const float* __restrict__ b0, const float* __restrict__ b1,
              const float* __restrict__ b2, const float* __restrict__ resid,
              float* __restrict__ C0, float* __restrict__ C1, float* __restrict__ C2)
{
    extern __shared__ __align__(128) char smem[];
    const uint32_t sb = smem_u32(smem);
    const int tid = threadIdx.x, wid = tid >> 5, lane = tid & 31;
    const int row0 = blockIdx.y * 128, col0 = blockIdx.x * 128;
    const int z = XW ? blockIdx.z : 0;
    const __nv_bfloat16* Bh = Wth + (long)z * 262144;
    const __nv_bfloat16* Bl = Wtl + (long)z * 262144;
    const float* bias = (!XW || z == 0) ? b0 : (z == 1 ? b1 : b2);
    float* C = (!XW || z == 0) ? C0 : (z == 1 ? C1 : C2);
    const bool gelu = XW && (z < 2);

    const int wm = (wid & 3) * 32;   // warp m offset
    const int wn = (wid >> 2) * 64;  // warp n offset

    float acc[2][8][4];
    #pragma unroll
    for (int i = 0; i < 2; i++)
        #pragma unroll
        for (int j = 0; j < 8; j++)
            #pragma unroll
            for (int e = 0; e < 4; e++) acc[i][j][e] = 0.0f;

    // ldmatrix lane mapping for a 16x16 b16 tile: 4 8x8 matrices
    const int g  = lane >> 3, wr = lane & 7;
    const int fRow = wr + (g & 1) * 8;     // row within 16
    const int fK   = (g >> 1) * 8;         // k within 16

    auto load_chunk = [&](int ch, int b) {
        const int k0 = ch * 32;
        const uint32_t base = sb + b * MM_BUF;
        #pragma unroll
        for (int l = 0; l < 8; l++) {
            const int arr = l >> 1;
            const int idx = tid + (l & 1) * 256;      // 0..511
            const int r = idx >> 2, s = idx & 3;
            const uint32_t dst = base + arr * MM_ARR + r * MM_PITCH + s * 16;
            const __nv_bfloat16* src;
            if (arr == 0)      src = Ah + (long)(row0 + r) * 512 + k0 + s * 8;
            else if (arr == 1) src = Al + (long)(row0 + r) * 512 + k0 + s * 8;
            else if (arr == 2) src = Bh + (long)(col0 + r) * 512 + k0 + s * 8;
            else               src = Bl + (long)(col0 + r) * 512 + k0 + s * 8;
            cp16(dst, src);
        }
        asm volatile("cp.async.commit_group;" ::: "memory");
    };

    load_chunk(0, 0);

    for (int ch = 0; ch < 16; ch++) {
        const int b = ch & 1;
        if (ch < 15) {
            load_chunk(ch + 1, b ^ 1);
            asm volatile("cp.async.wait_group 1;" ::: "memory");
        } else {
            asm volatile("cp.async.wait_group 0;" ::: "memory");
        }
        __syncthreads();

        const uint32_t base = sb + b * MM_BUF;
        #pragma unroll
        for (int ks = 0; ks < 2; ks++) {
            uint32_t ahf[2][4], alf[2][4], bb[4][4];
            #pragma unroll
            for (int mt = 0; mt < 2; mt++) {
                const uint32_t ra = base + (wm + mt * 16 + fRow) * MM_PITCH
                                  + (ks * 16 + fK) * 2;
                ldx4(ahf[mt], ra);
                ldx4(alf[mt], ra + MM_ARR);
            }
            #pragma unroll
            for (int nt = 0; nt < 4; nt++) {
                const uint32_t rb = base + 2 * MM_ARR
                                  + (wn + nt * 16 + fRow) * MM_PITCH
                                  + (ks * 16 + fK) * 2;
                ldx4(bb[nt], rb);
            }
            // pass 1+2: (Ah + Al) * Bh
            #pragma unroll
            for (int mt = 0; mt < 2; mt++)
                #pragma unroll
                for (int nt = 0; nt < 4; nt++) {
                    mma16816(acc[mt][nt*2],   ahf[mt], bb[nt][0], bb[nt][2]);
                    mma16816(acc[mt][nt*2+1], ahf[mt], bb[nt][1], bb[nt][3]);
                    mma16816(acc[mt][nt*2],   alf[mt], bb[nt][0], bb[nt][2]);
                    mma16816(acc[mt][nt*2+1], alf[mt], bb[nt][1], bb[nt][3]);
                }
            // pass 3: Ah * Bl
            #pragma unroll
            for (int nt = 0; nt < 4; nt++) {
                const uint32_t rb = base + 3 * MM_ARR
                                  + (wn + nt * 16 + fRow) * MM_PITCH
                                  + (ks * 16 + fK) * 2;
                ldx4(bb[nt], rb);
            }
            #pragma unroll
            for (int mt = 0; mt < 2; mt++)
                #pragma unroll
                for (int nt = 0; nt < 4; nt++) {
                    mma16816(acc[mt][nt*2],   ahf[mt], bb[nt][0], bb[nt][2]);
                    mma16816(acc[mt][nt*2+1], ahf[mt], bb[nt][1], bb[nt][3]);
                }
        }
        __syncthreads();
    }

    // ---- epilogue: thread holds rows (lane/4, lane/4+8) x cols (lane%4)*2 per n8
    const int rbase = row0 + wm + (lane >> 2);
    const int cbase = col0 + wn + (lane & 3) * 2;
    #pragma unroll
    for (int mt = 0; mt < 2; mt++) {
        #pragma unroll
        for (int h = 0; h < 2; h++) {
            const int row = rbase + mt * 16 + h * 8;
            #pragma unroll
            for (int n8 = 0; n8 < 8; n8++) {
                const int col = cbase + n8 * 8;
                float v0 = acc[mt][n8][h * 2 + 0];
                float v1 = acc[mt][n8][h * 2 + 1];
                const float2 bq = *(const float2*)&bias[col];
                v0 += bq.x; v1 += bq.y;
                if (gelu) {
                    v0 = 0.5f * v0 * (1.0f + erff(v0 * 0.70710678118654752f));
                    v1 = 0.5f * v1 * (1.0f + erff(v1 * 0.70710678118654752f));
                } else if (!XW) {
                    const float2 r2 = *(const float2*)&resid[(long)row * 512 + col];
                    v0 += r2.x; v1 += r2.y;
                }
                float2 o; o.x = v0; o.y = v1;
                *(float2*)&C[(long)row * 512 + col] = o;
            }
        }
    }
}

// ================= conversion kernels =================
__global__ __launch_bounds__(256)
void xsplit_kernel(const float4* __restrict__ src, __nv_bfloat16* __restrict__ hi,
                   __nv_bfloat16* __restrict__ lo)
{
    int i = blockIdx.x * 256 + threadIdx.x;
    float4 v = src[i];
    float vv[4] = {v.x, v.y, v.z, v.w};
    #pragma unroll
    for (int j = 0; j < 4; j++) {
        __nv_bfloat16 h = __float2bfloat16(vv[j]);
        hi[i * 4 + j] = h;
        lo[i * 4 + j] = __float2bfloat16(vv[j] - __bfloat162float(h));
    }
}

__global__ __launch_bounds__(1024)
void wsplit_kernel(const float* __restrict__ W0, const float* __restrict__ W1,
                   const float* __restrict__ W2, const float* __restrict__ W3,
                   __nv_bfloat16* __restrict__ hi, __nv_bfloat16* __restrict__ lo)
{
    const int z = blockIdx.z;
    const float* W = z == 0 ? W0 : z == 1 ? W1 : z == 2 ? W2 : W3;
    __shared__ float t[32][33];
    int tx = threadIdx.x & 31, ty = threadIdx.x >> 5;
    int k0 = blockIdx.y * 32, n0 = blockIdx.x * 32;
    t[ty][tx] = W[(long)(k0 + ty) * 512 + n0 + tx];
    __syncthreads();
    float v = t[tx][ty];
    long o = (long)z * 262144 + (long)(n0 + ty) * 512 + k0 + tx;
    __nv_bfloat16 h = __float2bfloat16(v);
    hi[o] = h;
    lo[o] = __float2bfloat16(v - __bfloat162float(h));
}

// ================= scalar f32x2 GEMM (attention pieces) =================
__device__ __forceinline__ unsigned long long pack2(float a) {
    unsigned long long r;
    asm("mov.b64 %0, {%1, %1};" : "=l"(r) : "r"(__float_as_uint(a)));
    return r;
}
__device__ __forceinline__ void fma2(unsigned long long& acc,
                                     unsigned long long a, unsigned long long b) {
    asm("fma.rn.f32x2 %0, %1, %2, %0;" : "+l"(acc) : "l"(a), "l"(b));
}

template<int BM, int BN, int TM, int TN, int THREADS, bool TRANSA, bool TRANSB, int EPI>
__global__ __launch_bounds__(THREADS)
void gemm_f32x2(const float* __restrict__ Ag, const float* __restrict__ Bg,
                float* __restrict__ Cg,
                int M, int N, int K, int ldA, int ldB, int ldC,
                long zA, long zB, long zC)
{
    constexpr int BK = 16;
    constexpr int A_LD = (BM * BK / 4) / THREADS;
    constexpr int B_LD = (BN * BK / 4) / THREADS;
    constexpr int TN2 = TN / 2;

    __shared__ float As[2][BK][BM];
    __shared__ float Bs[2][BK][BN];

    const int tid = threadIdx.x;
    const int tx = tid % (BN / TN);
    const int ty = tid / (BN / TN);
    const int row0 = blockIdx.y * BM;
    const int col0 = blockIdx.x * BN;

    Ag += (long)blockIdx.z * zA;
    Bg += (long)blockIdx.z * zB;
    Cg += (long)blockIdx.z * zC;

    unsigned long long acc2[TM][TN2];
    #pragma unroll
    for (int i = 0; i < TM; i++)
        #pragma unroll
        for (int j = 0; j < TN2; j++) acc2[i][j] = 0ull;

    float4 rA[A_LD], rB[B_LD];

    auto loadA = [&](int k0) {
        #pragma unroll
        for (int l = 0; l < A_LD; l++) {
            int i = tid + l * THREADS;
            if (!TRANSA) {
                int r = i / (BK / 4), c = (i % (BK / 4)) * 4;
                rA[l] = *(const float4*)(Ag + (long)(row0 + r) * ldA + k0 + c);
            } else {
                int kk = i / (BM / 4), mc = (i % (BM / 4)) * 4;
                rA[l] = *(const float4*)(Ag + (long)(k0 + kk) * ldA + row0 + mc);
            }
        }
    };
    auto storeA = [&](int b) {
        #pragma unroll
        for (int l = 0; l < A_LD; l++) {
            int i = tid + l * THREADS;
            if (!TRANSA) {
                int r = i / (BK / 4), c = (i % (BK / 4)) * 4;
                As[b][c + 0][r] = rA[l].x; As[b][c + 1][r] = rA[l].y;
                As[b][c + 2][r] = rA[l].z; As[b][c + 3][r] = rA[l].w;
            } else {
                int kk = i / (BM / 4), mc = (i % (BM / 4)) * 4;
                *(float4*)&As[b][kk][mc] = rA[l];
            }
        }
    };
    auto loadB = [&](int k0) {
        #pragma unroll
        for (int l = 0; l < B_LD; l++) {
            int i = tid + l * THREADS;
            if (!TRANSB) {
                int r = i / (BN / 4), c = (i % (BN / 4)) * 4;
                rB[l] = *(const float4*)(Bg + (long)(k0 + r) * ldB + col0 + c);
            } else {
                int n = i / (BK / 4), c = (i % (BK / 4)) * 4;
                rB[l] = *(const float4*)(Bg + (long)(col0 + n) * ldB + k0 + c);
            }
        }
    };
    auto storeB = [&](int b) {
        #pragma unroll
        for (int l = 0; l < B_LD; l++) {
            int i = tid + l * THREADS;
            if (!TRANSB) {
                int r = i / (BN / 4), c = (i % (BN / 4)) * 4;
                *(float4*)&Bs[b][r][c] = rB[l];
            } else {
                int n = i / (BK / 4), c = (i % (BK / 4)) * 4;
                Bs[b][c + 0][n] = rB[l].x; Bs[b][c + 1][n] = rB[l].y;
                Bs[b][c + 2][n] = rB[l].z; Bs[b][c + 3][n] = rB[l].w;
            }
        }
    };

    const int nIter = K / BK;
    loadA(0); loadB(0);
    storeA(0); storeB(0);
    __syncthreads();

    int buf = 0;
    for (int it = 0; it < nIter; ++it) {
        if (it + 1 < nIter) { loadA((it + 1) * BK); loadB((it + 1) * BK); }
        #pragma unroll
        for (int k = 0; k < BK; k++) {
            float a[TM];
            #pragma unroll
            for (int i = 0; i < TM / 4; i++) {
                float4 t4 = *(const float4*)&As[buf][k][ty * TM + i * 4];
                a[i*4+0] = t4.x; a[i*4+1] = t4.y; a[i*4+2] = t4.z; a[i*4+3] = t4.w;
            }
            unsigned long long bv[TN2];
            #pragma unroll
            for (int j = 0; j < TN / 4; j++) {
                ulonglong2 u = *(const ulonglong2*)&Bs[buf][k][tx * TN + j * 4];
                bv[j*2] = u.x; bv[j*2+1] = u.y;
            }
            #pragma unroll
            for (int i = 0; i < TM; i++) {
                unsigned long long av = pack2(a[i]);
                #pragma unroll
                for (int j = 0; j < TN2; j++) fma2(acc2[i][j], av, bv[j]);
            }
        }
        if (it + 1 < nIter) { storeA(buf ^ 1); storeB(buf ^ 1); }
        __syncthreads();
        buf ^= 1;
    }

    #pragma unroll
    for (int i = 0; i < TM; i++) {
        int row = row0 + ty * TM + i;
        #pragma unroll
        for (int jp = 0; jp < TN2; jp++) {
            float2 f = *reinterpret_cast<float2*>(&acc2[i][jp]);
            int col = col0 + tx * TN + jp * 2;
            if (EPI == EPI_CAUSAL) {
                Cg[(long)row * ldC + col]     = (col     <= row) ? f.x : 0.0f;
                Cg[(long)row * ldC + col + 1] = (col + 1 <= row) ? f.y : 0.0f;
            } else {
                Cg[(long)row * ldC + col]     = f.x;
                Cg[(long)row * ldC + col + 1] = f.y;
            }
        }
    }
}

// ================= rfinal =================
__global__ __launch_bounds__(128)
void rfinal_kernel(const float* __restrict__ CSq, const float* __restrict__ Ac,
                   const float* __restrict__ P, const float* __restrict__ V,
                   float* __restrict__ R)
{
    constexpr int BK = 16;
    __shared__ float As[2][BK][64];
    __shared__ float Bs[2][BK][128];

    const int tid = threadIdx.x;
    const int tx = tid % 16;
    const int ty = tid / 16;
    const int row0 = blockIdx.y * 64;
    const int col0 = blockIdx.x * 128;
    const int c = row0 >> 7;
    const int kstart = ((c & 7) == 0) ? 128 : 0;

    unsigned long long acc2[8][4];
    #pragma unroll
    for (int i = 0; i < 8; i++)
        #pragma unroll
        for (int j = 0; j < 4; j++) acc2[i][j] = 0ull;

    float4 rA[2], rB[4];
    auto loadA = [&](int k0) {
        #pragma unroll
        for (int l = 0; l < 2; l++) {
            int i = tid + l * 128;
            int r = i / 4, cc = (i % 4) * 4;
            const float* src = (k0 < 128)
                ? CSq + (long)(row0 + r) * 128 + k0 + cc
                : Ac + (long)c * 16384 + (long)((row0 & 127) + r) * 128 + (k0 - 128) + cc;
            rA[l] = *(const float4*)src;
        }
    };
    auto storeA = [&](int b) {
        #pragma unroll
        for (int l = 0; l < 2; l++) {
            int i = tid + l * 128;
            int r = i / 4, cc = (i % 4) * 4;
            As[b][cc + 0][r] = rA[l].x; As[b][cc + 1][r] = rA[l].y;
            As[b][cc + 2][r] = rA[l].z; As[b][cc + 3][r] = rA[l].w;
        }
    };
    auto loadB = [&](int k0) {
        #pragma unroll
        for (int l = 0; l < 4; l++) {
            int i = tid + l * 128;
            int r = i / 32, cc = (i % 32) * 4;
            const float* src = (k0 < 128)
                ? P + (long)c * 65536 + (long)(k0 + r) * 512 + col0 + cc
                : V + ((long)c * 128 + (k0 - 128) + r) * 512 + col0 + cc;
            rB[l] = *(const float4*)src;
        }
    };
    auto storeB = [&](int b) {
        #pragma unroll
        for (int l = 0; l < 4; l++) {
            int i = tid + l * 128;
            int r = i / 32, cc = (i % 32) * 4;
            *(float4*)&Bs[b][r][cc] = rB[l];
        }
    };

    const int nIter = (256 - kstart) / BK;
    loadA(kstart); loadB(kstart);
    storeA(0); storeB(0);
    __syncthreads();

    int buf = 0;
    for (int it = 0; it < nIter; ++it) {
        if (it + 1 < nIter) { loadA(kstart + (it + 1) * BK); loadB(kstart + (it + 1) * BK); }
        #pragma unroll
        for (int k = 0; k < BK; k++) {
            float a[8];
            #pragma unroll
            for (int i = 0; i < 2; i++) {
                float4 t4 = *(const float4*)&As[buf][k][ty * 8 + i * 4];
                a[i*4+0] = t4.x; a[i*4+1] = t4.y; a[i*4+2] = t4.z; a[i*4+3] = t4.w;
            }
            unsigned long long bv[4];
            #pragma unroll
            for (int j = 0; j < 2; j++) {
                ulonglong2 u = *(const ulonglong2*)&Bs[buf][k][tx * 8 + j * 4];
                bv[j*2] = u.x; bv[j*2+1] = u.y;
            }
            #pragma unroll
            for (int i = 0; i < 8; i++) {
                unsigned long long av = pack2(a[i]);
                #pragma unroll
                for (int j = 0; j < 4; j++) fma2(acc2[i][j], av, bv[j]);
            }
        }
        if (it + 1 < nIter) { storeA(buf ^ 1); storeB(buf ^ 1); }
        __syncthreads();
        buf ^= 1;
    }

    #pragma unroll
    for (int i = 0; i < 8; i++) {
        int row = row0 + ty * 8 + i;
        float scale = rsqrtf((float)((row & 1023) + 1) * 64.0f);
        #pragma unroll
        for (int jp = 0; jp < 4; jp++) {
            float2 f = *reinterpret_cast<float2*>(&acc2[i][jp]);
            int col = col0 + tx * 8 + jp * 2;
            R[(long)row * 512 + col]     = f.x * scale;
            R[(long)row * 512 + col + 1] = f.y * scale;
        }
    }
}

// ================= phase kernel =================
__global__ __launch_bounds__(256)
void phase_kernel(const float* __restrict__ Hk, const float* __restrict__ Hq,
                  const float* __restrict__ Wk2, const float* __restrict__ Wq2,
                  const float* __restrict__ bk2, const float* __restrict__ bq2,
                  float* __restrict__ CSk, float* __restrict__ CSq)
{
    const int z = blockIdx.z;
    const float* H  = z ? Hq  : Hk;
    const float* W  = z ? Wq2 : Wk2;
    const float* bb = z ? bq2 : bk2;
    float* CS = z ? CSq : CSk;

    const int row0 = blockIdx.x * 32;
    __shared__ float As[32][33];
    __shared__ float Bs[32][64];

    const int tid = threadIdx.x;
    const int tx = tid % 16;
    const int ty = tid / 16;
    float acc[2][4] = {{0,0,0,0},{0,0,0,0}};

    for (int k0 = 0; k0 < 512; k0 += 32) {
        {
            int r = tid / 8, c = (tid % 8) * 4;
            float4 v = *(const float4*)(H + (long)(row0 + r) * 512 + k0 + c);
            As[c + 0][r] = v.x; As[c + 1][r] = v.y;
            As[c + 2][r] = v.z; As[c + 3][r] = v.w;
        }
        #pragma unroll
        for (int l = 0; l < 2; l++) {
            int i = tid + l * 256;
            int r = i / 16, c = (i % 16) * 4;
            *(float4*)&Bs[r][c] = *(const float4*)(W + (long)(k0 + r) * 64 + c);
        }
        __syncthreads();
        #pragma unroll
        for (int k = 0; k < 32; k++) {
            float a0 = As[k][ty * 2], a1 = As[k][ty * 2 + 1];
            float4 b = *(const float4*)&Bs[k][tx * 4];
            acc[0][0] = fmaf(a0, b.x, acc[0][0]); acc[0][1] = fmaf(a0, b.y, acc[0][1]);
            acc[0][2] = fmaf(a0, b.z, acc[0][2]); acc[0][3] = fmaf(a0, b.w, acc[0][3]);
            acc[1][0] = fmaf(a1, b.x, acc[1][0]); acc[1][1] = fmaf(a1, b.y, acc[1][1]);
            acc[1][2] = fmaf(a1, b.z, acc[1][2]); acc[1][3] = fmaf(a1, b.w, acc[1][3]);
        }
        __syncthreads();
    }

    #pragma unroll
    for (int i = 0; i < 2; i++) {
        int row = row0 + ty * 2 + i;
        #pragma unroll
        for (int j = 0; j < 4; j++) {
            int col = tx * 4 + j;
            float p = tanhf(acc[i][j] + bb[col]) * PI_F;
            float s, c;
            sincosf(p, &s, &c);
            CS[(long)row * 128 + col]      = c;
            CS[(long)row * 128 + 64 + col] = s;
        }
    }
}

// ================= prefix =================
__global__ __launch_bounds__(256)
void prefix_kernel(const float4* __restrict__ S, float4* __restrict__ P)
{
    int g = blockIdx.x * 256 + threadIdx.x;
    int b = g >> 14;
    int i = g & 16383;
    long base = (long)b * 8 * 16384 + i;
    float4 run = make_float4(0.f, 0.f, 0.f, 0.f);
    #pragma unroll
    for (int c = 0; c < 8; c++) {
        long idx = base + (long)c * 16384;
        P[idx] = run;
        float4 s = S[idx];
        run.x += s.x; run.y += s.y; run.z += s.z; run.w += s.w;
    }
}

// ================= LayerNorm (emits split bf16) =================
__global__ __launch_bounds__(128)
void ln_kernel(const float* __restrict__ X, const float* __restrict__ g,
               const float* __restrict__ b, __nv_bfloat16* __restrict__ oh,
               __nv_bfloat16* __restrict__ ol)
{
    const int D = 512;
    int row = blockIdx.x;
    int t = threadIdx.x;
    float4 v = ((const float4*)(X + (long)row * D))[t];
    float s  = v.x + v.y + v.z + v.w;
    float sq = v.x * v.x + v.y * v.y + v.z * v.z + v.w * v.w;
    #pragma unroll
    for (int o = 16; o; o >>= 1) {
        s  += __shfl_xor_sync(0xFFFFFFFFu, s, o);
        sq += __shfl_xor_sync(0xFFFFFFFFu, sq, o);
    }
    __shared__ float ss[4], ssq[4];
    int w = t >> 5, l = t & 31;
    if (l == 0) { ss[w] = s; ssq[w] = sq; }
    __syncthreads();
    s  = ss[0] + ss[1] + ss[2] + ss[3];
    sq = ssq[0] + ssq[1] + ssq[2] + ssq[3];
    float mean = s * (1.0f / 512.0f);
    float var  = sq * (1.0f / 512.0f) - mean * mean;
    float rs   = rsqrtf(var + 1e-5f);
    float4 gv = ((const float4*)g)[t];
    float4 bv = ((const float4*)b)[t];
    float o[4];
    o[0] = (v.x - mean) * rs * gv.x + bv.x;
    o[1] = (v.y - mean) * rs * gv.y + bv.y;
    o[2] = (v.z - mean) * rs * gv.z + bv.z;
    o[3] = (v.w - mean) * rs * gv.w + bv.w;
    #pragma unroll
    for (int j = 0; j < 4; j++) {
        __nv_bfloat16 h = __float2bfloat16(o[j]);
        oh[(long)row * D + t * 4 + j] = h;
        ol[(long)row * D + t * 4 + j] = __float2bfloat16(o[j] - __bfloat162float(h));
    }
}

// ================= launch =================
extern "C" void kernel_launch(void* const* d_in, const int* in_sizes, int n_in,
                              void* d_out, int out_size)
{
    const float* x    = (const float*)d_in[0];
    const float* Wk1  = (const float*)d_in[1];
    const float* bk1  = (const float*)d_in[2];
    const float* Wk2  = (const float*)d_in[3];
    const float* bk2  = (const float*)d_in[4];
    const float* Wq1  = (const float*)d_in[5];
    const float* bq1  = (const float*)d_in[6];
    const float* Wq2  = (const float*)d_in[7];
    const float* bq2  = (const float*)d_in[8];
    const float* Wv   = (const float*)d_in[9];
    const float* bv   = (const float*)d_in[10];
    const float* ln_g = (const float*)d_in[11];
    const float* ln_b = (const float*)d_in[12];
    const float* Wo   = (const float*)d_in[13];
    const float* bo   = (const float*)d_in[14];
    float* out = (float*)d_out;

    void* p;
    cudaGetSymbolAddress(&p, g_Hk);  float* Hk  = (float*)p;
    cudaGetSymbolAddress(&p, g_Hq);  float* Hq  = (float*)p;
    cudaGetSymbolAddress(&p, g_CSk); float* CSk = (float*)p;
    cudaGetSymbolAddress(&p, g_CSq); float* CSq = (float*)p;
    cudaGetSymbolAddress(&p, g_V);   float* V   = (float*)p;
    cudaGetSymbolAddress(&p, g_S);   float* S   = (float*)p;
    cudaGetSymbolAddress(&p, g_P);   float* P   = (float*)p;
    cudaGetSymbolAddress(&p, g_Ac);  float* Ac  = (float*)p;
    cudaGetSymbolAddress(&p, g_R);   float* R   = (float*)p;
    cudaGetSymbolAddress(&p, g_xh);  __nv_bfloat16* xh  = (__nv_bfloat16*)p;
    cudaGetSymbolAddress(&p, g_xl);  __nv_bfloat16* xl  = (__nv_bfloat16*)p;
    cudaGetSymbolAddress(&p, g_LNh); __nv_bfloat16* LNh = (__nv_bfloat16*)p;
    cudaGetSymbolAddress(&p, g_LNl); __nv_bfloat16* LNl = (__nv_bfloat16*)p;
    cudaGetSymbolAddress(&p, g_Wth); __nv_bfloat16* Wth = (__nv_bfloat16*)p;
    cudaGetSymbolAddress(&p, g_Wtl); __nv_bfloat16* Wtl = (__nv_bfloat16*)p;

    static int smem_set = 0;
    if (!smem_set) {
        cudaFuncSetAttribute(mma_gemm<true>,  cudaFuncAttributeMaxDynamicSharedMemorySize, MM_SMEM);
        cudaFuncSetAttribute(mma_gemm<false>, cudaFuncAttributeMaxDynamicSharedMemorySize, MM_SMEM);
        smem_set = 1;
    }

    // 0) conversions
    xsplit_kernel<<<1024, 256>>>((const float4*)x, xh, xl);
    wsplit_kernel<<<dim3(16,16,4), 1024>>>(Wk1, Wq1, Wv, Wo, Wth, Wtl);

    // 1) XW on tensor cores (mma.sync): Hk=gelu, Hq=gelu, V=bias. grid (4,16,3).
    mma_gemm<true><<<dim3(4,16,3), 256, MM_SMEM>>>(
        xh, xl, Wth, Wtl, bk1, bq1, bv, nullptr, Hk, Hq, V);

    // 2) Phases
    phase_kernel<<<dim3(64,1,2), 256>>>(Hk, Hq, Wk2, Wq2, bk2, bq2, CSk, CSq);

    // 3) Ac[c] = tril(CSq_c @ CSk_c^T)
    gemm_f32x2<128,128,8,8,256,false,true,EPI_CAUSAL><<<dim3(1,1,16), 256>>>(
        CSq, CSk, Ac, 128, 128, 128, 128, 128, 128, 16384, 16384, 16384);

    // 4) S[c] = CSk_c^T @ V_c
    gemm_f32x2<128,128,8,8,256,true,false,EPI_NONE><<<dim3(4,1,16), 256>>>(
        CSk, V, S, 128, 512, 128, 128, 512, 512, 16384, 65536, 65536);

    // 5) exclusive prefix
    prefix_kernel<<<128, 256>>>((const float4*)S, (float4*)P);

    // 6) R
    rfinal_kernel<<<dim3(4,32), 128>>>(CSq, Ac, P, V, R);

    // 7) LN -> split bf16
    ln_kernel<<<2048, 128>>>(R, ln_g, ln_b, LNh, LNl);

    // 8) out = x + LN @ Wo + bo on tensor cores. grid (4,16).
    mma_gemm<false><<<dim3(4,16,1), 256, MM_SMEM>>>(
        LNh, LNl, Wth + 3L*262144, Wtl + 3L*262144, bo, nullptr, nullptr, x, out, nullptr, nullptr);
}

// round 6
// speedup vs baseline: 3.4884x; 1.3189x over previous
#include <cuda_runtime.h>
#include <cuda_bf16.h>
#include <math.h>
#include <stdint.h>

#define PI_F 3.14159265358979323846f
typedef __nv_bfloat16 bf16;

// ---------------- scratch (allocation-free: __device__ globals) ----------------
__device__ bf16 g_xh  [2048 * 512];
__device__ bf16 g_xl  [2048 * 512];
__device__ bf16 g_Wth [4 * 512 * 512];   // transposed weights hi: Wk1,Wq1,Wv,Wo
__device__ bf16 g_Wtl [4 * 512 * 512];
__device__ bf16 g_Wph [128 * 512];       // phase weights [n][k]: rows 0-63 Wk2^T, 64-127 Wq2^T
__device__ bf16 g_Wpl [128 * 512];
__device__ bf16 g_Hkh [2048 * 512];
__device__ bf16 g_Hkl [2048 * 512];
__device__ bf16 g_Hqh [2048 * 512];
__device__ bf16 g_Hql [2048 * 512];
__device__ bf16 g_Vh  [2048 * 512];
__device__ bf16 g_Vl  [2048 * 512];
__device__ bf16 g_CSkh[2048 * 128];
__device__ bf16 g_CSkl[2048 * 128];
__device__ bf16 g_CSqh[2048 * 128];
__device__ bf16 g_CSql[2048 * 128];
__device__ bf16 g_CSkTh[16 * 128 * 128]; // [chunk][phase][seq]
__device__ bf16 g_CSkTl[16 * 128 * 128];
__device__ bf16 g_Ach [16 * 128 * 128];
__device__ bf16 g_Acl [16 * 128 * 128];
__device__ float g_S  [16 * 128 * 512];
__device__ bf16 g_Ph  [16 * 128 * 512];
__device__ bf16 g_Pl  [16 * 128 * 512];
__device__ float g_R  [2048 * 512];
__device__ bf16 g_LNh [2048 * 512];
__device__ bf16 g_LNl [2048 * 512];

// ================= PTX helpers =================
__device__ __forceinline__ uint32_t smem_u32(const void* p) {
    uint32_t a;
    asm("{ .reg .u64 t; cvta.to.shared.u64 t, %1; cvt.u32.u64 %0, t; }" : "=r"(a) : "l"(p));
    return a;
}
__device__ __forceinline__ void cp16(uint32_t dst, const void* src) {
    asm volatile("cp.async.cg.shared.global [%0], [%1], 16;" :: "r"(dst), "l"(src));
}
__device__ __forceinline__ void ldx4(uint32_t* r, uint32_t addr) {
    asm volatile("ldmatrix.sync.aligned.m8n8.x4.shared.b16 {%0,%1,%2,%3}, [%4];"
        : "=r"(r[0]), "=r"(r[1]), "=r"(r[2]), "=r"(r[3]) : "r"(addr));
}
__device__ __forceinline__ void ldx4t(uint32_t* r, uint32_t addr) {
    asm volatile("ldmatrix.sync.aligned.m8n8.x4.trans.shared.b16 {%0,%1,%2,%3}, [%4];"
        : "=r"(r[0]), "=r"(r[1]), "=r"(r[2]), "=r"(r[3]) : "r"(addr));
}
__device__ __forceinline__ void mma16816(float* c, const uint32_t* a,
                                         uint32_t b0, uint32_t b1) {
    asm volatile("mma.sync.aligned.m16n8k16.row.col.f32.bf16.bf16.f32 "
        "{%0,%1,%2,%3}, {%4,%5,%6,%7}, {%8,%9}, {%0,%1,%2,%3};"
        : "+f"(c[0]), "+f"(c[1]), "+f"(c[2]), "+f"(c[3])
        : "r"(a[0]), "r"(a[1]), "r"(a[2]), "r"(a[3]), "r"(b0), "r"(b1));
}
__device__ __forceinline__ void bsplit2(float v0, float v1, bf16* hd, bf16* ld) {
    __nv_bfloat162 h, l;
    h.x = __float2bfloat16(v0); h.y = __float2bfloat16(v1);
    l.x = __float2bfloat16(v0 - __bfloat162float(h.x));
    l.y = __float2bfloat16(v1 - __bfloat162float(h.y));
    *(__nv_bfloat162*)hd = h; *(__nv_bfloat162*)ld = l;
}

// ================= XW / OUT GEMM: 128x128x(K=512), 256 thr, 8 warps 4x2 ====
// MODE 0: XW — out split bf16, gelu for z<2, bias.  MODE 1: OUT — fp32 + resid + bias.
static constexpr int MM_PITCH = 80;
static constexpr int MM_ARR   = 128 * MM_PITCH;
static constexpr int MM_BUF   = 4 * MM_ARR;
static constexpr int MM_SMEM  = 2 * MM_BUF;   // 81920

template<int MODE>
__global__ __launch_bounds__(256)
void mma_gemm(const bf16* __restrict__ Ah, const bf16* __restrict__ Al,
              const bf16* __restrict__ Wth, const bf16* __restrict__ Wtl,
              const float* __restrict__ b0, const float* __restrict__ b1,
              const float* __restrict__ b2, const float* __restrict__ resid,
              bf16* __restrict__ O0h, bf16* __restrict__ O0l,
              bf16* __restrict__ O1h, bf16* __restrict__ O1l,
              bf16* __restrict__ O2h, bf16* __restrict__ O2l,
              float* __restrict__ Cout)
{
    extern __shared__ __align__(128) char smem[];
    const uint32_t sb = smem_u32(smem);
    const int tid = threadIdx.x, wid = tid >> 5, lane = tid & 31;
    const int row0 = blockIdx.y * 128, col0 = blockIdx.x * 128;
    const int z = (MODE == 0) ? blockIdx.z : 0;
    const bf16* Bh = Wth + (long)z * 262144;
    const bf16* Bl = Wtl + (long)z * 262144;
    const float* bias = (z == 0) ? b0 : (z == 1 ? b1 : b2);
    const bool gelu = (MODE == 0) && (z < 2);
    bf16* Oh = (z == 0) ? O0h : (z == 1 ? O1h : O2h);
    bf16* Ol = (z == 0) ? O0l : (z == 1 ? O1l : O2l);

    const int wm = (wid & 3) * 32, wn = (wid >> 2) * 64;
    float acc[2][8][4];
    #pragma unroll
    for (int i = 0; i < 2; i++)
        #pragma unroll
        for (int j = 0; j < 8; j++)
            #pragma unroll
            for (int e = 0; e < 4; e++) acc[i][j][e] = 0.0f;

    const int g = lane >> 3, wr = lane & 7;
    const int fRow = wr + (g & 1) * 8, fK = (g >> 1) * 8;

    auto load_chunk = [&](int ch, int b) {
        const int k0 = ch * 32;
        const uint32_t base = sb + b * MM_BUF;
        #pragma unroll
        for (int l = 0; l < 8; l++) {
            const int arr = l >> 1;
            const int idx = tid + (l & 1) * 256;
            const int r = idx >> 2, s = idx & 3;
            const uint32_t dst = base + arr * MM_ARR + r * MM_PITCH + s * 16;
            const bf16* src;
            if (arr == 0)      src = Ah + (long)(row0 + r) * 512 + k0 + s * 8;
            else if (arr == 1) src = Al + (long)(row0 + r) * 512 + k0 + s * 8;
            else if (arr == 2) src = Bh + (long)(col0 + r) * 512 + k0 + s * 8;
            else               src = Bl + (long)(col0 + r) * 512 + k0 + s * 8;
            cp16(dst, src);
        }
        asm volatile("cp.async.commit_group;" ::: "memory");
    };

    load_chunk(0, 0);
    for (int ch = 0; ch < 16; ch++) {
        const int b = ch & 1;
        if (ch < 15) {
            load_chunk(ch + 1, b ^ 1);
            asm volatile("cp.async.wait_group 1;" ::: "memory");
        } else {
            asm volatile("cp.async.wait_group 0;" ::: "memory");
        }
        __syncthreads();
        const uint32_t base = sb + b * MM_BUF;
        #pragma unroll
        for (int ks = 0; ks < 2; ks++) {
            uint32_t ahf[2][4], alf[2][4], bb[4][4];
            #pragma unroll
            for (int mt = 0; mt < 2; mt++) {
                const uint32_t ra = base + (wm + mt * 16 + fRow) * MM_PITCH + (ks * 16 + fK) * 2;
                ldx4(ahf[mt], ra);
                ldx4(alf[mt], ra + MM_ARR);
            }
            #pragma unroll
            for (int nt = 0; nt < 4; nt++) {
                const uint32_t rb = base + 2 * MM_ARR + (wn + nt * 16 + fRow) * MM_PITCH + (ks * 16 + fK) * 2;
                ldx4(bb[nt], rb);
            }
            #pragma unroll
            for (int mt = 0; mt < 2; mt++)
                #pragma unroll
                for (int nt = 0; nt < 4; nt++) {
                    mma16816(acc[mt][nt*2],   ahf[mt], bb[nt][0], bb[nt][2]);
                    mma16816(acc[mt][nt*2+1], ahf[mt], bb[nt][1], bb[nt][3]);
                    mma16816(acc[mt][nt*2],   alf[mt], bb[nt][0], bb[nt][2]);
                    mma16816(acc[mt][nt*2+1], alf[mt], bb[nt][1], bb[nt][3]);
                }
            #pragma unroll
            for (int nt = 0; nt < 4; nt++) {
                const uint32_t rb = base + 3 * MM_ARR + (wn + nt * 16 + fRow) * MM_PITCH + (ks * 16 + fK) * 2;
                ldx4(bb[nt], rb);
            }
            #pragma unroll
            for (int mt = 0; mt < 2; mt++)
                #pragma unroll
                for (int nt = 0; nt < 4; nt++) {
                    mma16816(acc[mt][nt*2],   ahf[mt], bb[nt][0], bb[nt][2]);
                    mma16816(acc[mt][nt*2+1], ahf[mt], bb[nt][1], bb[nt][3]);
                }
        }
        __syncthreads();
    }

    const int rbase = row0 + wm + (lane >> 2);
    const int cbase = col0 + wn + (lane & 3) * 2;
    #pragma unroll
    for (int mt = 0; mt < 2; mt++)
        #pragma unroll
        for (int h = 0; h < 2; h++) {
            const int row = rbase + mt * 16 + h * 8;
            #pragma unroll
            for (int n8 = 0; n8 < 8; n8++) {
                const int col = cbase + n8 * 8;
                float v0 = acc[mt][n8][h * 2 + 0];
                float v1 = acc[mt][n8][h * 2 + 1];
                const float2 bq = *(const float2*)&bias[col];
                v0 += bq.x; v1 += bq.y;
                if (MODE == 0) {
                    if (gelu) {
                        v0 = 0.5f * v0 * (1.0f + erff(v0 * 0.70710678118654752f));
                        v1 = 0.5f * v1 * (1.0f + erff(v1 * 0.70710678118654752f));
                    }
                    bsplit2(v0, v1, Oh + (long)row * 512 + col, Ol + (long)row * 512 + col);
                } else {
                    const float2 r2 = *(const float2*)&resid[(long)row * 512 + col];
                    float2 o; o.x = v0 + r2.x; o.y = v1 + r2.y;
                    *(float2*)&Cout[(long)row * 512 + col] = o;
                }
            }
        }
}

// ================= phase GEMM: 64x64x(K=512), 128 thr, 4 warps 2x2 =========
static constexpr int PH_PITCH = 80;
static constexpr int PH_ARR   = 64 * PH_PITCH;   // 5120
static constexpr int PH_BUF   = 4 * PH_ARR;      // 20480
static constexpr int PH_SMEM  = 2 * PH_BUF;      // 40960

__global__ __launch_bounds__(128)
void phase_mma(const bf16* __restrict__ Hkh, const bf16* __restrict__ Hkl,
               const bf16* __restrict__ Hqh, const bf16* __restrict__ Hql,
               const bf16* __restrict__ Wph, const bf16* __restrict__ Wpl,
               const float* __restrict__ bk2, const float* __restrict__ bq2,
               bf16* __restrict__ CSkh, bf16* __restrict__ CSkl,
               bf16* __restrict__ CSqh, bf16* __restrict__ CSql,
               bf16* __restrict__ CSkTh, bf16* __restrict__ CSkTl)
{
    extern __shared__ __align__(128) char smem[];
    const uint32_t sb = smem_u32(smem);
    const int tid = threadIdx.x, wid = tid >> 5, lane = tid & 31;
    const int z = blockIdx.z, row0 = blockIdx.y * 64;
    const bf16* Ah = z ? Hqh : Hkh;
    const bf16* Al = z ? Hql : Hkl;
    const bf16* Bh = Wph + (long)z * 64 * 512;
    const bf16* Bl = Wpl + (long)z * 64 * 512;
    const float* bias = z ? bq2 : bk2;

    const int wm = (wid & 1) * 32, wn = (wid >> 1) * 32;
    float acc[2][4][4];
    #pragma unroll
    for (int i = 0; i < 2; i++)
        #pragma unroll
        for (int j = 0; j < 4; j++)
            #pragma unroll
            for (int e = 0; e < 4; e++) acc[i][j][e] = 0.0f;

    const int g = lane >> 3, wr = lane & 7;
    const int fRow = wr + (g & 1) * 8, fK = (g >> 1) * 8;

    auto load_chunk = [&](int ch, int b) {
        const int k0 = ch * 32;
        const uint32_t base = sb + b * PH_BUF;
        #pragma unroll
        for (int l = 0; l < 8; l++) {
            const int arr = l >> 1;
            const int idx = tid + (l & 1) * 128;
            const int r = idx >> 2, s = idx & 3;
            const uint32_t dst = base + arr * PH_ARR + r * PH_PITCH + s * 16;
            const bf16* src;
            if (arr == 0)      src = Ah + (long)(row0 + r) * 512 + k0 + s * 8;
            else if (arr == 1) src = Al + (long)(row0 + r) * 512 + k0 + s * 8;
            else if (arr == 2) src = Bh + (long)r * 512 + k0 + s * 8;
            else               src = Bl + (long)r * 512 + k0 + s * 8;
            cp16(dst, src);
        }
        asm volatile("cp.async.commit_group;" ::: "memory");
    };

    load_chunk(0, 0);
    for (int ch = 0; ch < 16; ch++) {
        const int b = ch & 1;
        if (ch < 15) {
            load_chunk(ch + 1, b ^ 1);
            asm volatile("cp.async.wait_group 1;" ::: "memory");
        } else {
            asm volatile("cp.async.wait_group 0;" ::: "memory");
        }
        __syncthreads();
        const uint32_t base = sb + b * PH_BUF;
        #pragma unroll
        for (int ks = 0; ks < 2; ks++) {
            uint32_t ahf[2][4], alf[2][4], bb[2][4];
            #pragma unroll
            for (int mt = 0; mt < 2; mt++) {
                const uint32_t ra = base + (wm + mt * 16 + fRow) * PH_PITCH + (ks * 16 + fK) * 2;
                ldx4(ahf[mt], ra);
                ldx4(alf[mt], ra + PH_ARR);
            }
            #pragma unroll
            for (int nt = 0; nt < 2; nt++) {
                const uint32_t rb = base + 2 * PH_ARR + (wn + nt * 16 + fRow) * PH_PITCH + (ks * 16 + fK) * 2;
                ldx4(bb[nt], rb);
            }
            #pragma unroll
            for (int mt = 0; mt < 2; mt++)
                #pragma unroll
                for (int nt = 0; nt < 2; nt++) {
                    mma16816(acc[mt][nt*2],   ahf[mt], bb[nt][0], bb[nt][2]);
                    mma16816(acc[mt][nt*2+1], ahf[mt], bb[nt][1], bb[nt][3]);
                    mma16816(acc[mt][nt*2],   alf[mt], bb[nt][0], bb[nt][2]);
                    mma16816(acc[mt][nt*2+1], alf[mt], bb[nt][1], bb[nt][3]);
                }
            #pragma unroll
            for (int nt = 0; nt < 2; nt++) {
                const uint32_t rb = base + 3 * PH_ARR + (wn + nt * 16 + fRow) * PH_PITCH + (ks * 16 + fK) * 2;
                ldx4(bb[nt], rb);
            }
            #pragma unroll
            for (int mt = 0; mt < 2; mt++)
                #pragma unroll
                for (int nt = 0; nt < 2; nt++) {
                    mma16816(acc[mt][nt*2],   ahf[mt], bb[nt][0], bb[nt][2]);
                    mma16816(acc[mt][nt*2+1], ahf[mt], bb[nt][1], bb[nt][3]);
                }
        }
        __syncthreads();
    }

    // epilogue: p = tanh(acc + bias)*pi; write cos|sin
    #pragma unroll
    for (int mt = 0; mt < 2; mt++)
        #pragma unroll
        for (int h = 0; h < 2; h++) {
            const int row = row0 + wm + mt * 16 + h * 8 + (lane >> 2);
            #pragma unroll
            for (int j = 0; j < 4; j++) {
                const int n = wn + (j >> 1) * 16 + (j & 1) * 8 + (lane & 3) * 2;
                float v0 = acc[mt][j][h * 2 + 0] + bias[n];
                float v1 = acc[mt][j][h * 2 + 1] + bias[n + 1];
                float p0 = tanhf(v0) * PI_F, p1 = tanhf(v1) * PI_F;
                float c0, s0, c1, s1;
                sincosf(p0, &s0, &c0);
                sincosf(p1, &s1, &c1);
                bf16* Rh = z ? CSqh : CSkh;
                bf16* Rl = z ? CSql : CSkl;
                const long rb_ = (long)row * 128;
                bsplit2(c0, c1, Rh + rb_ + n,      Rl + rb_ + n);
                bsplit2(s0, s1, Rh + rb_ + n + 64, Rl + rb_ + n + 64);
                if (!z) {  // transposed CSk^T[chunk][phase][seq]
                    const int c = row >> 7, ro = row & 127;
                    const long t0 = (long)c * 16384 + (long)n * 128 + ro;
                    bf16 h0 = __float2bfloat16(c0);
                    bf16 h1 = __float2bfloat16(c1);
                    bf16 h2 = __float2bfloat16(s0);
                    bf16 h3 = __float2bfloat16(s1);
                    CSkTh[t0]               = h0;
                    CSkTh[t0 + 128]         = h1;
                    CSkTh[t0 + 64*128]      = h2;
                    CSkTh[t0 + 65*128]      = h3;
                    CSkTl[t0]               = __float2bfloat16(c0 - __bfloat162float(h0));
                    CSkTl[t0 + 128]         = __float2bfloat16(c1 - __bfloat162float(h1));
                    CSkTl[t0 + 64*128]      = __float2bfloat16(s0 - __bfloat162float(h2));
                    CSkTl[t0 + 65*128]      = __float2bfloat16(s1 - __bfloat162float(h3));
                }
            }
        }
}

// ================= Ac GEMM: per chunk, 128x128x128, masked, split out ======
__global__ __launch_bounds__(256)
void ac_mma(const bf16* __restrict__ CSqh, const bf16* __restrict__ CSql,
            const bf16* __restrict__ CSkh, const bf16* __restrict__ CSkl,
            bf16* __restrict__ Ach, bf16* __restrict__ Acl)
{
    extern __shared__ __align__(128) char smem[];
    const uint32_t sb = smem_u32(smem);
    const int tid = threadIdx.x, wid = tid >> 5, lane = tid & 31;
    const int z = blockIdx.z;
    const bf16* Ah = CSqh + (long)z * 16384;
    const bf16* Al = CSql + (long)z * 16384;
    const bf16* Bh = CSkh + (long)z * 16384;
    const bf16* Bl = CSkl + (long)z * 16384;

    const int wm = (wid & 3) * 32, wn = (wid >> 2) * 64;
    float acc[2][8][4];
    #pragma unroll
    for (int i = 0; i < 2; i++)
        #pragma unroll
        for (int j = 0; j < 8; j++)
            #pragma unroll
            for (int e = 0; e < 4; e++) acc[i][j][e] = 0.0f;

    const int g = lane >> 3, wr = lane & 7;
    const int fRow = wr + (g & 1) * 8, fK = (g >> 1) * 8;

    auto load_chunk = [&](int ch, int b) {
        const int k0 = ch * 32;
        const uint32_t base = sb + b * MM_BUF;
        #pragma unroll
        for (int l = 0; l < 8; l++) {
            const int arr = l >> 1;
            const int idx = tid + (l & 1) * 256;
            const int r = idx >> 2, s = idx & 3;
            const uint32_t dst = base + arr * MM_ARR + r * MM_PITCH + s * 16;
            const bf16* src;
            if (arr == 0)      src = Ah + (long)r * 128 + k0 + s * 8;
            else if (arr == 1) src = Al + (long)r * 128 + k0 + s * 8;
            else if (arr == 2) src = Bh + (long)r * 128 + k0 + s * 8;
            else               src = Bl + (long)r * 128 + k0 + s * 8;
            cp16(dst, src);
        }
        asm volatile("cp.async.commit_group;" ::: "memory");
    };

    load_chunk(0, 0);
    for (int ch = 0; ch < 4; ch++) {
        const int b = ch & 1;
        if (ch < 3) {
            load_chunk(ch + 1, b ^ 1);
            asm volatile("cp.async.wait_group 1;" ::: "memory");
        } else {
            asm volatile("cp.async.wait_group 0;" ::: "memory");
        }
        __syncthreads();
        const uint32_t base = sb + b * MM_BUF;
        #pragma unroll
        for (int ks = 0; ks < 2; ks++) {
            uint32_t ahf[2][4], alf[2][4], bb[4][4];
            #pragma unroll
            for (int mt = 0; mt < 2; mt++) {
                const uint32_t ra = base + (wm + mt * 16 + fRow) * MM_PITCH + (ks * 16 + fK) * 2;
                ldx4(ahf[mt], ra);
                ldx4(alf[mt], ra + MM_ARR);
            }
            #pragma unroll
            for (int nt = 0; nt < 4; nt++) {
                const uint32_t rb = base + 2 * MM_ARR + (wn + nt * 16 + fRow) * MM_PITCH + (ks * 16 + fK) * 2;
                ldx4(bb[nt], rb);
            }
            #pragma unroll
            for (int mt = 0; mt < 2; mt++)
                #pragma unroll
                for (int nt = 0; nt < 4; nt++) {
                    mma16816(acc[mt][nt*2],   ahf[mt], bb[nt][0], bb[nt][2]);
                    mma16816(acc[mt][nt*2+1], ahf[mt], bb[nt][1], bb[nt][3]);
                    mma16816(acc[mt][nt*2],   alf[mt], bb[nt][0], bb[nt][2]);
                    mma16816(acc[mt][nt*2+1], alf[mt], bb[nt][1], bb[nt][3]);
                }
            #pragma unroll
            for (int nt = 0; nt < 4; nt++) {
                const uint32_t rb = base + 3 * MM_ARR + (wn + nt * 16 + fRow) * MM_PITCH + (ks * 16 + fK) * 2;
                ldx4(bb[nt], rb);
            }
            #pragma unroll
            for (int mt = 0; mt < 2; mt++)
                #pragma unroll
                for (int nt = 0; nt < 4; nt++) {
                    mma16816(acc[mt][nt*2],   ahf[mt], bb[nt][0], bb[nt][2]);
                    mma16816(acc[mt][nt*2+1], ahf[mt], bb[nt][1], bb[nt][3]);
                }
        }
        __syncthreads();
    }

    #pragma unroll
    for (int mt = 0; mt < 2; mt++)
        #pragma unroll
        for (int h = 0; h < 2; h++) {
            const int row = wm + mt * 16 + h * 8 + (lane >> 2);
            #pragma unroll
            for (int n8 = 0; n8 < 8; n8++) {
                const int col = wn + n8 * 8 + (lane & 3) * 2;
                float v0 = (col     <= row) ? acc[mt][n8][h*2+0] : 0.0f;
                float v1 = (col + 1 <= row) ? acc[mt][n8][h*2+1] : 0.0f;
                const long o = (long)z * 16384 + (long)row * 128 + col;
                bsplit2(v0, v1, Ach + o, Acl + o);
            }
        }
}

// ================= S / rfinal GEMM: 128x128 tiles, B k-major via ldmatrix.trans
static constexpr int KB_PITCH = 272;                // 128 bf16 + 8 pad
static constexpr int KB_ARR   = 32 * KB_PITCH;      // 8704
static constexpr int SR_ABUF  = 2 * MM_ARR;         // 20480 (Ah, Al)
static constexpr int SR_BUF   = SR_ABUF + 2 * KB_ARR; // 37888
static constexpr int SR_SMEM  = 2 * SR_BUF;         // 75776

// MODE 0: S = CSkT @ V  (K=128, out fp32)
// MODE 1: R = [CSq | Ac] @ [P ; V] (K=256, out fp32 scaled)
template<int MODE>
__global__ __launch_bounds__(256)
void sr_mma(const bf16* __restrict__ A0h, const bf16* __restrict__ A0l,
            const bf16* __restrict__ A1h, const bf16* __restrict__ A1l,
            const bf16* __restrict__ B0h, const bf16* __restrict__ B0l,
            const bf16* __restrict__ B1h, const bf16* __restrict__ B1l,
            float* __restrict__ Out)
{
    extern __shared__ __align__(128) char smem[];
    const uint32_t sb = smem_u32(smem);
    const int tid = threadIdx.x, wid = tid >> 5, lane = tid & 31;
    const int z = blockIdx.z, col0 = blockIdx.x * 128;

    const int wm = (wid & 3) * 32, wn = (wid >> 2) * 64;
    float acc[2][8][4];
    #pragma unroll
    for (int i = 0; i < 2; i++)
        #pragma unroll
        for (int j = 0; j < 8; j++)
            #pragma unroll
            for (int e = 0; e < 4; e++) acc[i][j][e] = 0.0f;

    const int g = lane >> 3, wr = lane & 7;
    const int fRow = wr + (g & 1) * 8, fK = (g >> 1) * 8;
    const int tK = wr + (g & 1) * 8, tN = (g >> 1) * 8;

    const int NCH = (MODE == 0) ? 4 : 8;

    auto load_chunk = [&](int ch, int b) {
        const uint32_t base = sb + b * SR_BUF;
        // A: row-major ld=128
        const bf16* aH; const bf16* aL; int k0a;
        if (MODE == 0 || ch < 4) {
            aH = A0h + (long)z * 16384; aL = A0l + (long)z * 16384; k0a = ch * 32;
        } else {
            aH = A1h + (long)z * 16384; aL = A1l + (long)z * 16384; k0a = (ch - 4) * 32;
        }
        #pragma unroll
        for (int l = 0; l < 4; l++) {
            const int arr = l >> 1;
            const int idx = tid + (l & 1) * 256;
            const int r = idx >> 2, s = idx & 3;
            const uint32_t dst = base + arr * MM_ARR + r * MM_PITCH + s * 16;
            const bf16* src = (arr ? aL : aH) + (long)r * 128 + k0a + s * 8;
            cp16(dst, src);
        }
        // B: k-major rows, ld=512
        const bf16* bH; const bf16* bL; long rowB;
        if (MODE == 0) {
            bH = B0h; bL = B0l; rowB = (long)z * 128 + ch * 32;
        } else if (ch < 4) {
            bH = B0h + (long)z * 65536; bL = B0l + (long)z * 65536; rowB = ch * 32;
        } else {
            bH = B1h; bL = B1l; rowB = (long)z * 128 + (ch - 4) * 32;
        }
        #pragma unroll
        for (int l = 0; l < 4; l++) {
            const int arr = l >> 1;
            const int idx = tid + (l & 1) * 256;
            const int r = idx >> 4, s = idx & 15;
            const uint32_t dst = base + SR_ABUF + arr * KB_ARR + r * KB_PITCH + s * 16;
            const bf16* src = (arr ? bL : bH) + (rowB + r) * 512 + col0 + s * 8;
            cp16(dst, src);
        }
        asm volatile("cp.async.commit_group;" ::: "memory");
    };

    load_chunk(0, 0);
    for (int ch = 0; ch < NCH; ch++) {
        const int b = ch & 1;
        if (ch < NCH - 1) {
            load_chunk(ch + 1, b ^ 1);
            asm volatile("cp.async.wait_group 1;" ::: "memory");
        } else {
            asm volatile("cp.async.wait_group 0;" ::: "memory");
        }
        __syncthreads();
        const uint32_t base = sb + b * SR_BUF;
        #pragma unroll
        for (int ks = 0; ks < 2; ks++) {
            uint32_t ahf[2][4], alf[2][4], bb[4][4];
            #pragma unroll
            for (int mt = 0; mt < 2; mt++) {
                const uint32_t ra = base + (wm + mt * 16 + fRow) * MM_PITCH + (ks * 16 + fK) * 2;
                ldx4(ahf[mt], ra);
                ldx4(alf[mt], ra + MM_ARR);
            }
            #pragma unroll
            for (int nt = 0; nt < 4; nt++) {
                const uint32_t rb = base + SR_ABUF + (ks * 16 + tK) * KB_PITCH + (wn + nt * 16 + tN) * 2;
                ldx4t(bb[nt], rb);
            }
            #pragma unroll
            for (int mt = 0; mt < 2; mt++)
                #pragma unroll
                for (int nt = 0; nt < 4; nt++) {
                    mma16816(acc[mt][nt*2],   ahf[mt], bb[nt][0], bb[nt][1]);
                    mma16816(acc[mt][nt*2+1], ahf[mt], bb[nt][2], bb[nt][3]);
                    mma16816(acc[mt][nt*2],   alf[mt], bb[nt][0], bb[nt][1]);
                    mma16816(acc[mt][nt*2+1], alf[mt], bb[nt][2], bb[nt][3]);
                }
            #pragma unroll
            for (int nt = 0; nt < 4; nt++) {
                const uint32_t rb = base + SR_ABUF + KB_ARR + (ks * 16 + tK) * KB_PITCH + (wn + nt * 16 + tN) * 2;
                ldx4t(bb[nt], rb);
            }
            #pragma unroll
            for (int mt = 0; mt < 2; mt++)
                #pragma unroll
                for (int nt = 0; nt < 4; nt++) {
                    mma16816(acc[mt][nt*2],   ahf[mt], bb[nt][0], bb[nt][1]);
                    mma16816(acc[mt][nt*2+1], ahf[mt], bb[nt][2], bb[nt][3]);
                }
        }
        __syncthreads();
    }

    #pragma unroll
    for (int mt = 0; mt < 2; mt++)
        #pragma unroll
        for (int h = 0; h < 2; h++) {
            const int m = wm + mt * 16 + h * 8 + (lane >> 2);
            float scale = 1.0f;
            long orow;
            if (MODE == 0) {
                orow = (long)z * 65536 + (long)m * 512;
            } else {
                const int pos = (z & 7) * 128 + m;
                scale = rsqrtf((float)(pos + 1) * 64.0f);
                orow = ((long)z * 128 + m) * 512;
            }
            #pragma unroll
            for (int n8 = 0; n8 < 8; n8++) {
                const int col = col0 + wn + n8 * 8 + (lane & 3) * 2;
                float2 o;
                o.x = acc[mt][n8][h*2+0] * scale;
                o.y = acc[mt][n8][h*2+1] * scale;
                *(float2*)&Out[orow + col] = o;
            }
        }
}

// ================= conversion / pointwise kernels =================
__global__ __launch_bounds__(256)
void xsplit_kernel(const float4* __restrict__ src, bf16* __restrict__ hi,
                   bf16* __restrict__ lo)
{
    int i = blockIdx.x * 256 + threadIdx.x;
    float4 v = src[i];
    bsplit2(v.x, v.y, hi + i * 4,     lo + i * 4);
    bsplit2(v.z, v.w, hi + i * 4 + 2, lo + i * 4 + 2);
}

__global__ __launch_bounds__(1024)
void wsplit_kernel(const float* __restrict__ W0, const float* __restrict__ W1,
                   const float* __restrict__ W2, const float* __restrict__ W3,
                   bf16* __restrict__ hi, bf16* __restrict__ lo)
{
    const int z = blockIdx.z;
    const float* W = z == 0 ? W0 : z == 1 ? W1 : z == 2 ? W2 : W3;
    __shared__ float t[32][33];
    int tx = threadIdx.x & 31, ty = threadIdx.x >> 5;
    int k0 = blockIdx.y * 32, n0 = blockIdx.x * 32;
    t[ty][tx] = W[(long)(k0 + ty) * 512 + n0 + tx];
    __syncthreads();
    float v = t[tx][ty];
    long o = (long)z * 262144 + (long)(n0 + ty) * 512 + k0 + tx;
    bf16 h = __float2bfloat16(v);
    hi[o] = h;
    lo[o] = __float2bfloat16(v - __bfloat162float(h));
}

__global__ __launch_bounds__(1024)
void wp_split(const float* __restrict__ Wk2, const float* __restrict__ Wq2,
              bf16* __restrict__ Wph, bf16* __restrict__ Wpl)
{
    const int z = blockIdx.z;
    const float* W = z ? Wq2 : Wk2;
    __shared__ float t[32][33];
    int tx = threadIdx.x & 31, ty = threadIdx.x >> 5;
    int k0 = blockIdx.y * 32, n0 = blockIdx.x * 32;
    t[ty][tx] = W[(long)(k0 + ty) * 64 + n0 + tx];
    __syncthreads();
    float v = t[tx][ty];   // = W[(k0+tx)*64 + n0+ty]
    long o = (long)(z * 64 + n0 + ty) * 512 + k0 + tx;
    bf16 h = __float2bfloat16(v);
    Wph[o] = h;
    Wpl[o] = __float2bfloat16(v - __bfloat162float(h));
}

__global__ __launch_bounds__(256)
void prefix_kernel(const float4* __restrict__ S, bf16* __restrict__ Ph,
                   bf16* __restrict__ Pl)
{
    int gidx = blockIdx.x * 256 + threadIdx.x;
    int b = gidx >> 14;
    int i = gidx & 16383;
    long base = (long)b * 8 * 16384 + i;
    float4 run = make_float4(0.f, 0.f, 0.f, 0.f);
    #pragma unroll
    for (int c = 0; c < 8; c++) {
        long idx = base + (long)c * 16384;
        long e = idx * 4;
        bsplit2(run.x, run.y, Ph + e,     Pl + e);
        bsplit2(run.z, run.w, Ph + e + 2, Pl + e + 2);
        float4 s = S[idx];
        run.x += s.x; run.y += s.y; run.z += s.z; run.w += s.w;
    }
}

__global__ __launch_bounds__(128)
void ln_kernel(const float* __restrict__ X, const float* __restrict__ gg,
               const float* __restrict__ bb, bf16* __restrict__ oh,
               bf16* __restrict__ ol)
{
    const int D = 512;
    int row = blockIdx.x;
    int t = threadIdx.x;
    float4 v = ((const float4*)(X + (long)row * D))[t];
    float s  = v.x + v.y + v.z + v.w;
    float sq = v.x * v.x + v.y * v.y + v.z * v.z + v.w * v.w;
    #pragma unroll
    for (int o = 16; o; o >>= 1) {
        s  += __shfl_xor_sync(0xFFFFFFFFu, s, o);
        sq += __shfl_xor_sync(0xFFFFFFFFu, sq, o);
    }
    __shared__ float ss[4], ssq[4];
    int w = t >> 5, l = t & 31;
    if (l == 0) { ss[w] = s; ssq[w] = sq; }
    __syncthreads();
    s  = ss[0] + ss[1] + ss[2] + ss[3];
    sq = ssq[0] + ssq[1] + ssq[2] + ssq[3];
    float mean = s * (1.0f / 512.0f);
    float var  = sq * (1.0f / 512.0f) - mean * mean;
    float rs   = rsqrtf(var + 1e-5f);
    float4 gv = ((const float4*)gg)[t];
    float4 bv = ((const float4*)bb)[t];
    float o0 = (v.x - mean) * rs * gv.x + bv.x;
    float o1 = (v.y - mean) * rs * gv.y + bv.y;
    float o2 = (v.z - mean) * rs * gv.z + bv.z;
    float o3 = (v.w - mean) * rs * gv.w + bv.w;
    long e = (long)row * D + t * 4;
    bsplit2(o0, o1, oh + e,     ol + e);
    bsplit2(o2, o3, oh + e + 2, ol + e + 2);
}

// ================= launch =================
extern "C" void kernel_launch(void* const* d_in, const int* in_sizes, int n_in,
                              void* d_out, int out_size)
{
    const float* x    = (const float*)d_in[0];
    const float* Wk1  = (const float*)d_in[1];
    const float* bk1  = (const float*)d_in[2];
    const float* Wk2  = (const float*)d_in[3];
    const float* bk2  = (const float*)d_in[4];
    const float* Wq1  = (const float*)d_in[5];
    const float* bq1  = (const float*)d_in[6];
    const float* Wq2  = (const float*)d_in[7];
    const float* bq2  = (const float*)d_in[8];
    const float* Wv   = (const float*)d_in[9];
    const float* bv   = (const float*)d_in[10];
    const float* ln_g = (const float*)d_in[11];
    const float* ln_b = (const float*)d_in[12];
    const float* Wo   = (const float*)d_in[13];
    const float* bo   = (const float*)d_in[14];
    float* out = (float*)d_out;

    void* p;
    cudaGetSymbolAddress(&p, g_xh);   bf16* xh   = (bf16*)p;
    cudaGetSymbolAddress(&p, g_xl);   bf16* xl   = (bf16*)p;
    cudaGetSymbolAddress(&p, g_Wth);  bf16* Wth  = (bf16*)p;
    cudaGetSymbolAddress(&p, g_Wtl);  bf16* Wtl  = (bf16*)p;
    cudaGetSymbolAddress(&p, g_Wph);  bf16* Wph  = (bf16*)p;
    cudaGetSymbolAddress(&p, g_Wpl);  bf16* Wpl  = (bf16*)p;
    cudaGetSymbolAddress(&p, g_Hkh);  bf16* Hkh  = (bf16*)p;
    cudaGetSymbolAddress(&p, g_Hkl);  bf16* Hkl  = (bf16*)p;
    cudaGetSymbolAddress(&p, g_Hqh);  bf16* Hqh  = (bf16*)p;
    cudaGetSymbolAddress(&p, g_Hql);  bf16* Hql  = (bf16*)p;
    cudaGetSymbolAddress(&p, g_Vh);   bf16* Vh   = (bf16*)p;
    cudaGetSymbolAddress(&p, g_Vl);   bf16* Vl   = (bf16*)p;
    cudaGetSymbolAddress(&p, g_CSkh); bf16* CSkh = (bf16*)p;
    cudaGetSymbolAddress(&p, g_CSkl); bf16* CSkl = (bf16*)p;
    cudaGetSymbolAddress(&p, g_CSqh); bf16* CSqh = (bf16*)p;
    cudaGetSymbolAddress(&p, g_CSql); bf16* CSql = (bf16*)p;
    cudaGetSymbolAddress(&p, g_CSkTh); bf16* CSkTh = (bf16*)p;
    cudaGetSymbolAddress(&p, g_CSkTl); bf16* CSkTl = (bf16*)p;
    cudaGetSymbolAddress(&p, g_Ach);  bf16* Ach  = (bf16*)p;
    cudaGetSymbolAddress(&p, g_Acl);  bf16* Acl  = (bf16*)p;
    cudaGetSymbolAddress(&p, g_S);    float* S   = (float*)p;
    cudaGetSymbolAddress(&p, g_Ph);   bf16* Ph   = (bf16*)p;
    cudaGetSymbolAddress(&p, g_Pl);   bf16* Pl   = (bf16*)p;
    cudaGetSymbolAddress(&p, g_R);    float* R   = (float*)p;
    cudaGetSymbolAddress(&p, g_LNh);  bf16* LNh  = (bf16*)p;
    cudaGetSymbolAddress(&p, g_LNl);  bf16* LNl  = (bf16*)p;

    static int attr_set = 0;
    if (!attr_set) {
        cudaFuncSetAttribute(mma_gemm<0>, cudaFuncAttributeMaxDynamicSharedMemorySize, MM_SMEM);
        cudaFuncSetAttribute(mma_gemm<1>, cudaFuncAttributeMaxDynamicSharedMemorySize, MM_SMEM);
        cudaFuncSetAttribute(ac_mma,      cudaFuncAttributeMaxDynamicSharedMemorySize, MM_SMEM);
        cudaFuncSetAttribute(sr_mma<0>,   cudaFuncAttributeMaxDynamicSharedMemorySize, SR_SMEM);
        cudaFuncSetAttribute(sr_mma<1>,   cudaFuncAttributeMaxDynamicSharedMemorySize, SR_SMEM);
        attr_set = 1;
    }

    // 0) conversions
    xsplit_kernel<<<1024, 256>>>((const float4*)x, xh, xl);
    wsplit_kernel<<<dim3(16,16,4), 1024>>>(Wk1, Wq1, Wv, Wo, Wth, Wtl);
    wp_split<<<dim3(2,16,2), 1024>>>(Wk2, Wq2, Wph, Wpl);

    // 1) XW: Hk(gelu), Hq(gelu), V(bias) -> split bf16. grid (4,16,3).
    mma_gemm<0><<<dim3(4,16,3), 256, MM_SMEM>>>(
        xh, xl, Wth, Wtl, bk1, bq1, bv, nullptr,
        Hkh, Hkl, Hqh, Hql, Vh, Vl, nullptr);

    // 2) Phases: CSk/CSq + CSk^T. grid (1,32,2).
    phase_mma<<<dim3(1,32,2), 128, PH_SMEM>>>(
        Hkh, Hkl, Hqh, Hql, Wph, Wpl, bk2, bq2,
        CSkh, CSkl, CSqh, CSql, CSkTh, CSkTl);

    // 3) Ac[c] = tril(CSq_c @ CSk_c^T). grid 16.
    ac_mma<<<dim3(1,1,16), 256, MM_SMEM>>>(CSqh, CSql, CSkh, CSkl, Ach, Acl);

    // 4) S[c] = CSk_c^T @ V_c. grid (4,1,16).
    sr_mma<0><<<dim3(4,1,16), 256, SR_SMEM>>>(
        CSkTh, CSkTl, nullptr, nullptr, Vh, Vl, nullptr, nullptr, S);

    // 5) exclusive prefix -> split bf16 P
    prefix_kernel<<<128, 256>>>((const float4*)S, Ph, Pl);

    // 6) R = (CSq@P + Ac@V) * rsqrt((t+1)*64). grid (4,1,16).
    sr_mma<1><<<dim3(4,1,16), 256, SR_SMEM>>>(
        CSqh, CSql, Ach, Acl, Ph, Pl, Vh, Vl, R);

    // 7) LN -> split bf16
    ln_kernel<<<2048, 128>>>(R, ln_g, ln_b, LNh, LNl);

    // 8) out = x + LN @ Wo + bo. grid (4,16).
    mma_gemm<1><<<dim3(4,16,1), 256, MM_SMEM>>>(
        LNh, LNl, Wth + 3L*262144, Wtl + 3L*262144, bo, nullptr, nullptr, x,
        nullptr, nullptr, nullptr, nullptr, nullptr, nullptr, out);
}

// round 7
// speedup vs baseline: 4.8817x; 1.3994x over previous
#include <cuda_runtime.h>
#include <cuda_bf16.h>
#include <math.h>
#include <stdint.h>

#define PI_F 3.14159265358979323846f
typedef __nv_bfloat16 bf16;

// ---------------- scratch (allocation-free: __device__ globals) ----------------
__device__ bf16 g_xh  [2048 * 512];
__device__ bf16 g_xl  [2048 * 512];
__device__ bf16 g_Wth [4 * 512 * 512];   // transposed weights hi: Wk1,Wq1,Wv,Wo
__device__ bf16 g_Wtl [4 * 512 * 512];
__device__ bf16 g_Wph [128 * 512];       // phase weights [n][k]
__device__ bf16 g_Wpl [128 * 512];
__device__ bf16 g_Hkh [2048 * 512];
__device__ bf16 g_Hkl [2048 * 512];
__device__ bf16 g_Hqh [2048 * 512];
__device__ bf16 g_Hql [2048 * 512];
__device__ bf16 g_Vh  [2048 * 512];
__device__ bf16 g_Vl  [2048 * 512];
__device__ bf16 g_CSkh[2048 * 128];
__device__ bf16 g_CSkl[2048 * 128];
__device__ bf16 g_CSqh[2048 * 128];
__device__ bf16 g_CSql[2048 * 128];
__device__ bf16 g_CSkTh[32 * 128 * 64];  // [chunk][phase][seq64]
__device__ bf16 g_CSkTl[32 * 128 * 64];
__device__ bf16 g_Ach [32 * 64 * 64];
__device__ bf16 g_Acl [32 * 64 * 64];
__device__ float g_S  [32 * 128 * 512];
__device__ bf16 g_Ph  [32 * 128 * 512];
__device__ bf16 g_Pl  [32 * 128 * 512];
__device__ float g_R  [2048 * 512];
__device__ bf16 g_LNh [2048 * 512];
__device__ bf16 g_LNl [2048 * 512];

// ================= PTX helpers =================
__device__ __forceinline__ uint32_t smem_u32(const void* p) {
    uint32_t a;
    asm("{ .reg .u64 t; cvta.to.shared.u64 t, %1; cvt.u32.u64 %0, t; }" : "=r"(a) : "l"(p));
    return a;
}
__device__ __forceinline__ void cp16(uint32_t dst, const void* src) {
    asm volatile("cp.async.cg.shared.global [%0], [%1], 16;" :: "r"(dst), "l"(src));
}
__device__ __forceinline__ void ldx4(uint32_t* r, uint32_t addr) {
    asm volatile("ldmatrix.sync.aligned.m8n8.x4.shared.b16 {%0,%1,%2,%3}, [%4];"
        : "=r"(r[0]), "=r"(r[1]), "=r"(r[2]), "=r"(r[3]) : "r"(addr));
}
__device__ __forceinline__ void ldx4t(uint32_t* r, uint32_t addr) {
    asm volatile("ldmatrix.sync.aligned.m8n8.x4.trans.shared.b16 {%0,%1,%2,%3}, [%4];"
        : "=r"(r[0]), "=r"(r[1]), "=r"(r[2]), "=r"(r[3]) : "r"(addr));
}
__device__ __forceinline__ void mma16816(float* c, const uint32_t* a,
                                         uint32_t b0, uint32_t b1) {
    asm volatile("mma.sync.aligned.m16n8k16.row.col.f32.bf16.bf16.f32 "
        "{%0,%1,%2,%3}, {%4,%5,%6,%7}, {%8,%9}, {%0,%1,%2,%3};"
        : "+f"(c[0]), "+f"(c[1]), "+f"(c[2]), "+f"(c[3])
        : "r"(a[0]), "r"(a[1]), "r"(a[2]), "r"(a[3]), "r"(b0), "r"(b1));
}
__device__ __forceinline__ void bsplit2(float v0, float v1, bf16* hd, bf16* ld) {
    __nv_bfloat162 h, l;
    h.x = __float2bfloat16(v0); h.y = __float2bfloat16(v1);
    l.x = __float2bfloat16(v0 - __bfloat162float(h.x));
    l.y = __float2bfloat16(v1 - __bfloat162float(h.y));
    *(__nv_bfloat162*)hd = h; *(__nv_bfloat162*)ld = l;
}
#define CPA_COMMIT() asm volatile("cp.async.commit_group;" ::: "memory")
#define CPA_WAIT1()  asm volatile("cp.async.wait_group 1;" ::: "memory")
#define CPA_WAIT0()  asm volatile("cp.async.wait_group 0;" ::: "memory")

// ================= XW / OUT GEMM: 64x128 tiles, 8 warps (2x4), 3 CTAs/SM ====
static constexpr int XA_ARR = 64 * 80;          // 5120
static constexpr int XB_OFF = 2 * XA_ARR;       // 10240
static constexpr int XB_ARR = 128 * 80;         // 10240
static constexpr int X_BUF  = XB_OFF + 2 * XB_ARR;  // 30720
static constexpr int X_SMEM = 2 * X_BUF;        // 61440

template<int MODE>   // 0: XW (split bf16 out, gelu z<2), 1: OUT (fp32 + resid)
__global__ __launch_bounds__(256, 3)
void mma_gemm(const bf16* __restrict__ Ah, const bf16* __restrict__ Al,
              const bf16* __restrict__ Wth, const bf16* __restrict__ Wtl,
              const float* __restrict__ b0, const float* __restrict__ b1,
              const float* __restrict__ b2, const float* __restrict__ resid,
              bf16* __restrict__ O0h, bf16* __restrict__ O0l,
              bf16* __restrict__ O1h, bf16* __restrict__ O1l,
              bf16* __restrict__ O2h, bf16* __restrict__ O2l,
              float* __restrict__ Cout)
{
    extern __shared__ __align__(128) char smem[];
    const uint32_t sb = smem_u32(smem);
    const int tid = threadIdx.x, wid = tid >> 5, lane = tid & 31;
    const int row0 = blockIdx.y * 64, col0 = blockIdx.x * 128;
    const int z = (MODE == 0) ? blockIdx.z : 0;
    const bf16* Bh = Wth + (long)z * 262144;
    const bf16* Bl = Wtl + (long)z * 262144;
    const float* bias = (z == 0) ? b0 : (z == 1 ? b1 : b2);
    const bool gelu = (MODE == 0) && (z < 2);
    bf16* Oh = (z == 0) ? O0h : (z == 1 ? O1h : O2h);
    bf16* Ol = (z == 0) ? O0l : (z == 1 ? O1l : O2l);

    const int wm = (wid & 1) * 32, wn = (wid >> 1) * 32;
    float acc[2][4][4];
    #pragma unroll
    for (int i = 0; i < 2; i++)
        #pragma unroll
        for (int j = 0; j < 4; j++)
            #pragma unroll
            for (int e = 0; e < 4; e++) acc[i][j][e] = 0.0f;

    const int g = lane >> 3, wr = lane & 7;
    const int fRow = wr + (g & 1) * 8, fK = (g >> 1) * 8;

    auto load_chunk = [&](int ch, int b) {
        const int k0 = ch * 32;
        const uint32_t base = sb + b * X_BUF;
        #pragma unroll
        for (int l = 0; l < 2; l++) {
            const int idx = tid + l * 256;
            const int arr = idx >> 8, rr = (idx >> 2) & 63, s = idx & 3;
            cp16(base + arr * XA_ARR + rr * 80 + s * 16,
                 (arr ? Al : Ah) + (long)(row0 + rr) * 512 + k0 + s * 8);
        }
        #pragma unroll
        for (int l = 0; l < 4; l++) {
            const int idx = tid + l * 256;
            const int arr = idx >> 9, rr = (idx >> 2) & 127, s = idx & 3;
            cp16(base + XB_OFF + arr * XB_ARR + rr * 80 + s * 16,
                 (arr ? Bl : Bh) + (long)(col0 + rr) * 512 + k0 + s * 8);
        }
        CPA_COMMIT();
    };

    load_chunk(0, 0);
    for (int ch = 0; ch < 16; ch++) {
        const int b = ch & 1;
        if (ch < 15) { load_chunk(ch + 1, b ^ 1); CPA_WAIT1(); }
        else CPA_WAIT0();
        __syncthreads();
        const uint32_t base = sb + b * X_BUF;
        #pragma unroll
        for (int ks = 0; ks < 2; ks++) {
            uint32_t ahf[2][4], alf[2][4], bb[2][4];
            #pragma unroll
            for (int mt = 0; mt < 2; mt++) {
                const uint32_t ra = base + (wm + mt * 16 + fRow) * 80 + (ks * 16 + fK) * 2;
                ldx4(ahf[mt], ra);
                ldx4(alf[mt], ra + XA_ARR);
            }
            #pragma unroll
            for (int nt = 0; nt < 2; nt++) {
                const uint32_t rb = base + XB_OFF + (wn + nt * 16 + fRow) * 80 + (ks * 16 + fK) * 2;
                ldx4(bb[nt], rb);
            }
            #pragma unroll
            for (int mt = 0; mt < 2; mt++)
                #pragma unroll
                for (int nt = 0; nt < 2; nt++) {
                    mma16816(acc[mt][nt*2],   ahf[mt], bb[nt][0], bb[nt][2]);
                    mma16816(acc[mt][nt*2+1], ahf[mt], bb[nt][1], bb[nt][3]);
                    mma16816(acc[mt][nt*2],   alf[mt], bb[nt][0], bb[nt][2]);
                    mma16816(acc[mt][nt*2+1], alf[mt], bb[nt][1], bb[nt][3]);
                }
            #pragma unroll
            for (int nt = 0; nt < 2; nt++) {
                const uint32_t rb = base + XB_OFF + XB_ARR + (wn + nt * 16 + fRow) * 80 + (ks * 16 + fK) * 2;
                ldx4(bb[nt], rb);
            }
            #pragma unroll
            for (int mt = 0; mt < 2; mt++)
                #pragma unroll
                for (int nt = 0; nt < 2; nt++) {
                    mma16816(acc[mt][nt*2],   ahf[mt], bb[nt][0], bb[nt][2]);
                    mma16816(acc[mt][nt*2+1], ahf[mt], bb[nt][1], bb[nt][3]);
                }
        }
        __syncthreads();
    }

    #pragma unroll
    for (int mt = 0; mt < 2; mt++)
        #pragma unroll
        for (int h = 0; h < 2; h++) {
            const int row = row0 + wm + mt * 16 + h * 8 + (lane >> 2);
            #pragma unroll
            for (int n8 = 0; n8 < 4; n8++) {
                const int col = col0 + wn + n8 * 8 + (lane & 3) * 2;
                float v0 = acc[mt][n8][h * 2 + 0];
                float v1 = acc[mt][n8][h * 2 + 1];
                const float2 bq = *(const float2*)&bias[col];
                v0 += bq.x; v1 += bq.y;
                if (MODE == 0) {
                    if (gelu) {
                        v0 = 0.5f * v0 * (1.0f + erff(v0 * 0.70710678118654752f));
                        v1 = 0.5f * v1 * (1.0f + erff(v1 * 0.70710678118654752f));
                    }
                    bsplit2(v0, v1, Oh + (long)row * 512 + col, Ol + (long)row * 512 + col);
                } else {
                    const float2 r2 = *(const float2*)&resid[(long)row * 512 + col];
                    float2 o; o.x = v0 + r2.x; o.y = v1 + r2.y;
                    *(float2*)&Cout[(long)row * 512 + col] = o;
                }
            }
        }
}

// ================= phase GEMM: 64x64xK512, 128 thr, 4 warps 2x2 =========
static constexpr int PH_ARR  = 64 * 80;      // 5120
static constexpr int PH_BUF  = 4 * PH_ARR;   // 20480
static constexpr int PH_SMEM = 2 * PH_BUF;   // 40960

__global__ __launch_bounds__(128)
void phase_mma(const bf16* __restrict__ Hkh, const bf16* __restrict__ Hkl,
               const bf16* __restrict__ Hqh, const bf16* __restrict__ Hql,
               const bf16* __restrict__ Wph, const bf16* __restrict__ Wpl,
               const float* __restrict__ bk2, const float* __restrict__ bq2,
               bf16* __restrict__ CSkh, bf16* __restrict__ CSkl,
               bf16* __restrict__ CSqh, bf16* __restrict__ CSql,
               bf16* __restrict__ CSkTh, bf16* __restrict__ CSkTl)
{
    extern __shared__ __align__(128) char smem[];
    const uint32_t sb = smem_u32(smem);
    const int tid = threadIdx.x, wid = tid >> 5, lane = tid & 31;
    const int z = blockIdx.z, row0 = blockIdx.y * 64;
    const bf16* Ah = z ? Hqh : Hkh;
    const bf16* Al = z ? Hql : Hkl;
    const bf16* Bh = Wph + (long)z * 64 * 512;
    const bf16* Bl = Wpl + (long)z * 64 * 512;
    const float* bias = z ? bq2 : bk2;

    const int wm = (wid & 1) * 32, wn = (wid >> 1) * 32;
    float acc[2][4][4];
    #pragma unroll
    for (int i = 0; i < 2; i++)
        #pragma unroll
        for (int j = 0; j < 4; j++)
            #pragma unroll
            for (int e = 0; e < 4; e++) acc[i][j][e] = 0.0f;

    const int g = lane >> 3, wr = lane & 7;
    const int fRow = wr + (g & 1) * 8, fK = (g >> 1) * 8;

    auto load_chunk = [&](int ch, int b) {
        const int k0 = ch * 32;
        const uint32_t base = sb + b * PH_BUF;
        #pragma unroll
        for (int l = 0; l < 8; l++) {
            const int arr = l >> 1;
            const int idx = tid + (l & 1) * 128;
            const int r = idx >> 2, s = idx & 3;
            const uint32_t dst = base + arr * PH_ARR + r * 80 + s * 16;
            const bf16* src;
            if (arr == 0)      src = Ah + (long)(row0 + r) * 512 + k0 + s * 8;
            else if (arr == 1) src = Al + (long)(row0 + r) * 512 + k0 + s * 8;
            else if (arr == 2) src = Bh + (long)r * 512 + k0 + s * 8;
            else               src = Bl + (long)r * 512 + k0 + s * 8;
            cp16(dst, src);
        }
        CPA_COMMIT();
    };

    load_chunk(0, 0);
    for (int ch = 0; ch < 16; ch++) {
        const int b = ch & 1;
        if (ch < 15) { load_chunk(ch + 1, b ^ 1); CPA_WAIT1(); }
        else CPA_WAIT0();
        __syncthreads();
        const uint32_t base = sb + b * PH_BUF;
        #pragma unroll
        for (int ks = 0; ks < 2; ks++) {
            uint32_t ahf[2][4], alf[2][4], bb[2][4];
            #pragma unroll
            for (int mt = 0; mt < 2; mt++) {
                const uint32_t ra = base + (wm + mt * 16 + fRow) * 80 + (ks * 16 + fK) * 2;
                ldx4(ahf[mt], ra);
                ldx4(alf[mt], ra + PH_ARR);
            }
            #pragma unroll
            for (int nt = 0; nt < 2; nt++) {
                const uint32_t rb = base + 2 * PH_ARR + (wn + nt * 16 + fRow) * 80 + (ks * 16 + fK) * 2;
                ldx4(bb[nt], rb);
            }
            #pragma unroll
            for (int mt = 0; mt < 2; mt++)
                #pragma unroll
                for (int nt = 0; nt < 2; nt++) {
                    mma16816(acc[mt][nt*2],   ahf[mt], bb[nt][0], bb[nt][2]);
                    mma16816(acc[mt][nt*2+1], ahf[mt], bb[nt][1], bb[nt][3]);
                    mma16816(acc[mt][nt*2],   alf[mt], bb[nt][0], bb[nt][2]);
                    mma16816(acc[mt][nt*2+1], alf[mt], bb[nt][1], bb[nt][3]);
                }
            #pragma unroll
            for (int nt = 0; nt < 2; nt++) {
                const uint32_t rb = base + 3 * PH_ARR + (wn + nt * 16 + fRow) * 80 + (ks * 16 + fK) * 2;
                ldx4(bb[nt], rb);
            }
            #pragma unroll
            for (int mt = 0; mt < 2; mt++)
                #pragma unroll
                for (int nt = 0; nt < 2; nt++) {
                    mma16816(acc[mt][nt*2],   ahf[mt], bb[nt][0], bb[nt][2]);
                    mma16816(acc[mt][nt*2+1], ahf[mt], bb[nt][1], bb[nt][3]);
                }
        }
        __syncthreads();
    }

    #pragma unroll
    for (int mt = 0; mt < 2; mt++)
        #pragma unroll
        for (int h = 0; h < 2; h++) {
            const int row = row0 + wm + mt * 16 + h * 8 + (lane >> 2);
            #pragma unroll
            for (int j = 0; j < 4; j++) {
                const int n = wn + (j >> 1) * 16 + (j & 1) * 8 + (lane & 3) * 2;
                float v0 = acc[mt][j][h * 2 + 0] + bias[n];
                float v1 = acc[mt][j][h * 2 + 1] + bias[n + 1];
                float p0 = tanhf(v0) * PI_F, p1 = tanhf(v1) * PI_F;
                float c0, s0, c1, s1;
                sincosf(p0, &s0, &c0);
                sincosf(p1, &s1, &c1);
                bf16* Rh = z ? CSqh : CSkh;
                bf16* Rl = z ? CSql : CSkl;
                const long rb_ = (long)row * 128;
                bsplit2(c0, c1, Rh + rb_ + n,      Rl + rb_ + n);
                bsplit2(s0, s1, Rh + rb_ + n + 64, Rl + rb_ + n + 64);
                if (!z) {  // CSk^T[chunk][phase128][seq64]
                    const int c = row >> 6, ro = row & 63;
                    const long t0 = (long)c * 8192 + (long)n * 64 + ro;
                    bf16 h0 = __float2bfloat16(c0);
                    bf16 h1 = __float2bfloat16(c1);
                    bf16 h2 = __float2bfloat16(s0);
                    bf16 h3 = __float2bfloat16(s1);
                    CSkTh[t0]          = h0;
                    CSkTh[t0 + 64]     = h1;
                    CSkTh[t0 + 4096]   = h2;
                    CSkTh[t0 + 4160]   = h3;
                    CSkTl[t0]          = __float2bfloat16(c0 - __bfloat162float(h0));
                    CSkTl[t0 + 64]     = __float2bfloat16(c1 - __bfloat162float(h1));
                    CSkTl[t0 + 4096]   = __float2bfloat16(s0 - __bfloat162float(h2));
                    CSkTl[t0 + 4160]   = __float2bfloat16(s1 - __bfloat162float(h3));
                }
            }
        }
}

// ================= S + Ac combined launch ==================================
// blockIdx.x<4: S_c = CSkT_c(128x64) @ V_c(64x512) col tile  (M128,N128,K64)
// blockIdx.x==4: Ac_c = tril(CSq_c(64x128) @ CSk_c^T)        (M64,N64,K128)
static constexpr int S_AARR = 128 * 80;          // 10240
static constexpr int S_BOFF = 2 * S_AARR;        // 20480
static constexpr int S_BARR = 32 * 272;          // 8704
static constexpr int S_BUF  = S_BOFF + 2 * S_BARR;  // 37888
static constexpr int SAC_SMEM = 2 * S_BUF;       // 75776
static constexpr int AC_AARR = 64 * 80;          // 5120
static constexpr int AC_BOFF = 2 * AC_AARR;      // 10240
static constexpr int AC_BUF  = 2 * AC_BOFF;      // 20480

__global__ __launch_bounds__(256)
void sac_mma(const bf16* __restrict__ CSkTh, const bf16* __restrict__ CSkTl,
             const bf16* __restrict__ Vh, const bf16* __restrict__ Vl,
             const bf16* __restrict__ CSqh, const bf16* __restrict__ CSql,
             const bf16* __restrict__ CSkh, const bf16* __restrict__ CSkl,
             float* __restrict__ S, bf16* __restrict__ Ach, bf16* __restrict__ Acl)
{
    extern __shared__ __align__(128) char smem[];
    const uint32_t sb = smem_u32(smem);
    const int tid = threadIdx.x, wid = tid >> 5, lane = tid & 31;
    const int c = blockIdx.z;
    const int g = lane >> 3, wr = lane & 7;
    const int fRow = wr + (g & 1) * 8, fK = (g >> 1) * 8;
    const int tK = fRow, tN = (g >> 1) * 8;

    if (blockIdx.x < 4) {
        // ---------- S path ----------
        const int col0 = blockIdx.x * 128;
        const int wm = (wid & 3) * 32, wn = (wid >> 2) * 64;
        float acc[2][8][4];
        #pragma unroll
        for (int i = 0; i < 2; i++)
            #pragma unroll
            for (int j = 0; j < 8; j++)
                #pragma unroll
                for (int e = 0; e < 4; e++) acc[i][j][e] = 0.0f;

        auto load_chunk = [&](int ch, int b) {
            const int k0 = ch * 32;
            const uint32_t base = sb + b * S_BUF;
            #pragma unroll
            for (int l = 0; l < 4; l++) {   // A: CSkT rows 128, ld 64
                const int idx = tid + l * 256;
                const int arr = idx >> 9, rr = (idx >> 2) & 127, s = idx & 3;
                cp16(base + arr * S_AARR + rr * 80 + s * 16,
                     (arr ? CSkTl : CSkTh) + (long)c * 8192 + (long)rr * 64 + k0 + s * 8);
            }
            #pragma unroll
            for (int l = 0; l < 4; l++) {   // B: V rows k-major, ld 512
                const int idx = tid + l * 256;
                const int arr = idx >> 9, rr = (idx >> 4) & 31, s = idx & 15;
                cp16(base + S_BOFF + arr * S_BARR + rr * 272 + s * 16,
                     (arr ? Vl : Vh) + ((long)c * 64 + k0 + rr) * 512 + col0 + s * 8);
            }
            CPA_COMMIT();
        };

        load_chunk(0, 0);
        for (int ch = 0; ch < 2; ch++) {
            const int b = ch & 1;
            if (ch < 1) { load_chunk(1, 1); CPA_WAIT1(); }
            else CPA_WAIT0();
            __syncthreads();
            const uint32_t base = sb + b * S_BUF;
            #pragma unroll
            for (int ks = 0; ks < 2; ks++) {
                uint32_t ahf[2][4], alf[2][4], bb[4][4];
                #pragma unroll
                for (int mt = 0; mt < 2; mt++) {
                    const uint32_t ra = base + (wm + mt * 16 + fRow) * 80 + (ks * 16 + fK) * 2;
                    ldx4(ahf[mt], ra);
                    ldx4(alf[mt], ra + S_AARR);
                }
                #pragma unroll
                for (int nt = 0; nt < 4; nt++) {
                    const uint32_t rb = base + S_BOFF + (ks * 16 + tK) * 272 + (wn + nt * 16 + tN) * 2;
                    ldx4t(bb[nt], rb);
                }
                #pragma unroll
                for (int mt = 0; mt < 2; mt++)
                    #pragma unroll
                    for (int nt = 0; nt < 4; nt++) {
                        mma16816(acc[mt][nt*2],   ahf[mt], bb[nt][0], bb[nt][1]);
                        mma16816(acc[mt][nt*2+1], ahf[mt], bb[nt][2], bb[nt][3]);
                        mma16816(acc[mt][nt*2],   alf[mt], bb[nt][0], bb[nt][1]);
                        mma16816(acc[mt][nt*2+1], alf[mt], bb[nt][2], bb[nt][3]);
                    }
                #pragma unroll
                for (int nt = 0; nt < 4; nt++) {
                    const uint32_t rb = base + S_BOFF + S_BARR + (ks * 16 + tK) * 272 + (wn + nt * 16 + tN) * 2;
                    ldx4t(bb[nt], rb);
                }
                #pragma unroll
                for (int mt = 0; mt < 2; mt++)
                    #pragma unroll
                    for (int nt = 0; nt < 4; nt++) {
                        mma16816(acc[mt][nt*2],   ahf[mt], bb[nt][0], bb[nt][1]);
                        mma16816(acc[mt][nt*2+1], ahf[mt], bb[nt][2], bb[nt][3]);
                    }
            }
            __syncthreads();
        }

        #pragma unroll
        for (int mt = 0; mt < 2; mt++)
            #pragma unroll
            for (int h = 0; h < 2; h++) {
                const int m = wm + mt * 16 + h * 8 + (lane >> 2);
                const long orow = (long)c * 65536 + (long)m * 512;
                #pragma unroll
                for (int n8 = 0; n8 < 8; n8++) {
                    const int col = col0 + wn + n8 * 8 + (lane & 3) * 2;
                    float2 o; o.x = acc[mt][n8][h*2+0]; o.y = acc[mt][n8][h*2+1];
                    *(float2*)&S[orow + col] = o;
                }
            }
    } else {
        // ---------- Ac path: M64,N64,K128 ----------
        const int wm = (wid & 1) * 32, wn = (wid >> 1) * 16;
        float acc[2][2][4];
        #pragma unroll
        for (int i = 0; i < 2; i++)
            #pragma unroll
            for (int j = 0; j < 2; j++)
                #pragma unroll
                for (int e = 0; e < 4; e++) acc[i][j][e] = 0.0f;

        auto load_chunk = [&](int ch, int b) {
            const int k0 = ch * 32;
            const uint32_t base = sb + b * AC_BUF;
            #pragma unroll
            for (int l = 0; l < 2; l++) {   // A: CSq rows c*64.., ld 128
                const int idx = tid + l * 256;
                const int arr = idx >> 8, rr = (idx >> 2) & 63, s = idx & 3;
                cp16(base + arr * AC_AARR + rr * 80 + s * 16,
                     (arr ? CSql : CSqh) + ((long)c * 64 + rr) * 128 + k0 + s * 8);
            }
            #pragma unroll
            for (int l = 0; l < 2; l++) {   // B: CSk rows (n-major), ld 128
                const int idx = tid + l * 256;
                const int arr = idx >> 8, rr = (idx >> 2) & 63, s = idx & 3;
                cp16(base + AC_BOFF + arr * AC_AARR + rr * 80 + s * 16,
                     (arr ? CSkl : CSkh) + ((long)c * 64 + rr) * 128 + k0 + s * 8);
            }
            CPA_COMMIT();
        };

        load_chunk(0, 0);
        for (int ch = 0; ch < 4; ch++) {
            const int b = ch & 1;
            if (ch < 3) { load_chunk(ch + 1, b ^ 1); CPA_WAIT1(); }
            else CPA_WAIT0();
            __syncthreads();
            const uint32_t base = sb + b * AC_BUF;
            #pragma unroll
            for (int ks = 0; ks < 2; ks++) {
                uint32_t ahf[2][4], alf[2][4], bb[4];
                #pragma unroll
                for (int mt = 0; mt < 2; mt++) {
                    const uint32_t ra = base + (wm + mt * 16 + fRow) * 80 + (ks * 16 + fK) * 2;
                    ldx4(ahf[mt], ra);
                    ldx4(alf[mt], ra + AC_AARR);
                }
                {
                    const uint32_t rb = base + AC_BOFF + (wn + fRow) * 80 + (ks * 16 + fK) * 2;
                    ldx4(bb, rb);
                }
                #pragma unroll
                for (int mt = 0; mt < 2; mt++) {
                    mma16816(acc[mt][0], ahf[mt], bb[0], bb[2]);
                    mma16816(acc[mt][1], ahf[mt], bb[1], bb[3]);
                    mma16816(acc[mt][0], alf[mt], bb[0], bb[2]);
                    mma16816(acc[mt][1], alf[mt], bb[1], bb[3]);
                }
                {
                    const uint32_t rb = base + AC_BOFF + AC_AARR + (wn + fRow) * 80 + (ks * 16 + fK) * 2;
                    ldx4(bb, rb);
                }
                #pragma unroll
                for (int mt = 0; mt < 2; mt++) {
                    mma16816(acc[mt][0], ahf[mt], bb[0], bb[2]);
                    mma16816(acc[mt][1], ahf[mt], bb[1], bb[3]);
                }
            }
            __syncthreads();
        }

        #pragma unroll
        for (int mt = 0; mt < 2; mt++)
            #pragma unroll
            for (int h = 0; h < 2; h++) {
                const int row = wm + mt * 16 + h * 8 + (lane >> 2);
                #pragma unroll
                for (int n8 = 0; n8 < 2; n8++) {
                    const int col = wn + n8 * 8 + (lane & 3) * 2;
                    float v0 = (col     <= row) ? acc[mt][n8][h*2+0] : 0.0f;
                    float v1 = (col + 1 <= row) ? acc[mt][n8][h*2+1] : 0.0f;
                    const long o = (long)c * 4096 + (long)row * 64 + col;
                    bsplit2(v0, v1, Ach + o, Acl + o);
                }
            }
    }
}

// ================= R GEMM: M64,N128,K192 ([CSq|Ac] @ [P;V]) ================
static constexpr int R_AARR = 64 * 80;          // 5120
static constexpr int R_BOFF = 2 * R_AARR;       // 10240
static constexpr int R_BARR = 32 * 272;         // 8704
static constexpr int R_BUF  = R_BOFF + 2 * R_BARR;  // 27648
static constexpr int R_SMEM = 2 * R_BUF;        // 55296

__global__ __launch_bounds__(256)
void r_mma(const bf16* __restrict__ CSqh, const bf16* __restrict__ CSql,
           const bf16* __restrict__ Ach, const bf16* __restrict__ Acl,
           const bf16* __restrict__ Ph, const bf16* __restrict__ Pl,
           const bf16* __restrict__ Vh, const bf16* __restrict__ Vl,
           float* __restrict__ Out)
{
    extern __shared__ __align__(128) char smem[];
    const uint32_t sb = smem_u32(smem);
    const int tid = threadIdx.x, wid = tid >> 5, lane = tid & 31;
    const int c = blockIdx.z, col0 = blockIdx.x * 128;
    const int wm = (wid & 1) * 32, wn = (wid >> 1) * 32;
    const int g = lane >> 3, wr = lane & 7;
    const int fRow = wr + (g & 1) * 8, fK = (g >> 1) * 8;
    const int tK = fRow, tN = (g >> 1) * 8;

    float acc[2][4][4];
    #pragma unroll
    for (int i = 0; i < 2; i++)
        #pragma unroll
        for (int j = 0; j < 4; j++)
            #pragma unroll
            for (int e = 0; e < 4; e++) acc[i][j][e] = 0.0f;

    auto load_chunk = [&](int ch, int b) {
        const uint32_t base = sb + b * R_BUF;
        const bf16 *aH, *aL, *bH, *bL;
        int ldA, k0;
        long rowB;
        if (ch < 4) {
            aH = CSqh + (long)c * 8192; aL = CSql + (long)c * 8192;
            ldA = 128; k0 = ch * 32;
            bH = Ph; bL = Pl; rowB = (long)c * 128 + ch * 32;
        } else {
            aH = Ach + (long)c * 4096; aL = Acl + (long)c * 4096;
            ldA = 64; k0 = (ch - 4) * 32;
            bH = Vh; bL = Vl; rowB = (long)c * 64 + (ch - 4) * 32;
        }
        #pragma unroll
        for (int l = 0; l < 2; l++) {
            const int idx = tid + l * 256;
            const int arr = idx >> 8, rr = (idx >> 2) & 63, s = idx & 3;
            cp16(base + arr * R_AARR + rr * 80 + s * 16,
                 (arr ? aL : aH) + (long)rr * ldA + k0 + s * 8);
        }
        #pragma unroll
        for (int l = 0; l < 4; l++) {
            const int idx = tid + l * 256;
            const int arr = idx >> 9, rr = (idx >> 4) & 31, s = idx & 15;
            cp16(base + R_BOFF + arr * R_BARR + rr * 272 + s * 16,
                 (arr ? bL : bH) + (rowB + rr) * 512 + col0 + s * 8);
        }
        CPA_COMMIT();
    };

    load_chunk(0, 0);
    for (int ch = 0; ch < 6; ch++) {
        const int b = ch & 1;
        if (ch < 5) { load_chunk(ch + 1, b ^ 1); CPA_WAIT1(); }
        else CPA_WAIT0();
        __syncthreads();
        const uint32_t base = sb + b * R_BUF;
        #pragma unroll
        for (int ks = 0; ks < 2; ks++) {
            uint32_t ahf[2][4], alf[2][4], bb[2][4];
            #pragma unroll
            for (int mt = 0; mt < 2; mt++) {
                const uint32_t ra = base + (wm + mt * 16 + fRow) * 80 + (ks * 16 + fK) * 2;
                ldx4(ahf[mt], ra);
                ldx4(alf[mt], ra + R_AARR);
            }
            #pragma unroll
            for (int nt = 0; nt < 2; nt++) {
                const uint32_t rb = base + R_BOFF + (ks * 16 + tK) * 272 + (wn + nt * 16 + tN) * 2;
                ldx4t(bb[nt], rb);
            }
            #pragma unroll
            for (int mt = 0; mt < 2; mt++)
                #pragma unroll
                for (int nt = 0; nt < 2; nt++) {
                    mma16816(acc[mt][nt*2],   ahf[mt], bb[nt][0], bb[nt][1]);
                    mma16816(acc[mt][nt*2+1], ahf[mt], bb[nt][2], bb[nt][3]);
                    mma16816(acc[mt][nt*2],   alf[mt], bb[nt][0], bb[nt][1]);
                    mma16816(acc[mt][nt*2+1], alf[mt], bb[nt][2], bb[nt][3]);
                }
            #pragma unroll
            for (int nt = 0; nt < 2; nt++) {
                const uint32_t rb = base + R_BOFF + R_BARR + (ks * 16 + tK) * 272 + (wn + nt * 16 + tN) * 2;
                ldx4t(bb[nt], rb);
            }
            #pragma unroll
            for (int mt = 0; mt < 2; mt++)
                #pragma unroll
                for (int nt = 0; nt < 2; nt++) {
                    mma16816(acc[mt][nt*2],   ahf[mt], bb[nt][0], bb[nt][1]);
                    mma16816(acc[mt][nt*2+1], ahf[mt], bb[nt][2], bb[nt][3]);
                }
        }
        __syncthreads();
    }

    #pragma unroll
    for (int mt = 0; mt < 2; mt++)
        #pragma unroll
        for (int h = 0; h < 2; h++) {
            const int m = wm + mt * 16 + h * 8 + (lane >> 2);
            const int pos = (c & 15) * 64 + m;
            const float scale = rsqrtf((float)(pos + 1) * 64.0f);
            const long orow = ((long)c * 64 + m) * 512;
            #pragma unroll
            for (int n8 = 0; n8 < 4; n8++) {
                const int col = col0 + wn + n8 * 8 + (lane & 3) * 2;
                float2 o;
                o.x = acc[mt][n8][h*2+0] * scale;
                o.y = acc[mt][n8][h*2+1] * scale;
                *(float2*)&Out[orow + col] = o;
            }
        }
}

// ================= prep: xsplit + wsplit + wp_split in one launch ==========
__global__ __launch_bounds__(256)
void prep_kernel(const float* __restrict__ x,
                 const float* __restrict__ W0, const float* __restrict__ W1,
                 const float* __restrict__ W2, const float* __restrict__ W3,
                 const float* __restrict__ Wk2, const float* __restrict__ Wq2,
                 bf16* __restrict__ xh, bf16* __restrict__ xl,
                 bf16* __restrict__ Wth, bf16* __restrict__ Wtl,
                 bf16* __restrict__ Wph, bf16* __restrict__ Wpl)
{
    const int bid = blockIdx.x, tid = threadIdx.x;
    if (bid < 1024) {
        const int i = bid * 256 + tid;
        float4 v = ((const float4*)x)[i];
        bsplit2(v.x, v.y, xh + i * 4,     xl + i * 4);
        bsplit2(v.z, v.w, xh + i * 4 + 2, xl + i * 4 + 2);
    } else if (bid < 2048) {
        const int widx = bid - 1024;
        const int z = widx >> 8, tile = widx & 255;
        const int k0 = (tile >> 4) * 32, n0 = (tile & 15) * 32;
        const float* W = z == 0 ? W0 : z == 1 ? W1 : z == 2 ? W2 : W3;
        __shared__ float t[32][33];
        #pragma unroll
        for (int j = 0; j < 4; j++) {
            const int r = (tid >> 5) + j * 8;
            t[r][tid & 31] = W[(long)(k0 + r) * 512 + n0 + (tid & 31)];
        }
        __syncthreads();
        #pragma unroll
        for (int j = 0; j < 4; j++) {
            const int nr = (tid >> 5) + j * 8, kc = tid & 31;
            const float v = t[kc][nr];
            const long o = (long)z * 262144 + (long)(n0 + nr) * 512 + k0 + kc;
            bf16 h = __float2bfloat16(v);
            Wth[o] = h;
            Wtl[o] = __float2bfloat16(v - __bfloat162float(h));
        }
    } else {
        const int widx = bid - 2048;
        const int z = widx >> 5, tile = widx & 31;
        const int k0 = (tile >> 1) * 32, n0 = (tile & 1) * 32;
        const float* W = z ? Wq2 : Wk2;
        __shared__ float t[32][33];
        #pragma unroll
        for (int j = 0; j < 4; j++) {
            const int r = (tid >> 5) + j * 8;
            t[r][tid & 31] = W[(long)(k0 + r) * 64 + n0 + (tid & 31)];
        }
        __syncthreads();
        #pragma unroll
        for (int j = 0; j < 4; j++) {
            const int nr = (tid >> 5) + j * 8, kc = tid & 31;
            const float v = t[kc][nr];
            const long o = (long)(z * 64 + n0 + nr) * 512 + k0 + kc;
            bf16 h = __float2bfloat16(v);
            Wph[o] = h;
            Wpl[o] = __float2bfloat16(v - __bfloat162float(h));
        }
    }
}

// ================= prefix over 16 chunks per batch =========================
__global__ __launch_bounds__(256)
void prefix_kernel(const float4* __restrict__ S, bf16* __restrict__ Ph,
                   bf16* __restrict__ Pl)
{
    int gidx = blockIdx.x * 256 + threadIdx.x;   // [0, 32768)
    int b = gidx >> 14;
    int i = gidx & 16383;
    long base = (long)b * 16 * 16384 + i;
    float4 run = make_float4(0.f, 0.f, 0.f, 0.f);
    #pragma unroll
    for (int c = 0; c < 16; c++) {
        long idx = base + (long)c * 16384;
        long e = idx * 4;
        bsplit2(run.x, run.y, Ph + e,     Pl + e);
        bsplit2(run.z, run.w, Ph + e + 2, Pl + e + 2);
        float4 s = S[idx];
        run.x += s.x; run.y += s.y; run.z += s.z; run.w += s.w;
    }
}

// ================= LayerNorm (emits split bf16) =================
__global__ __launch_bounds__(128)
void ln_kernel(const float* __restrict__ X, const float* __restrict__ gg,
               const float* __restrict__ bb, bf16* __restrict__ oh,
               bf16* __restrict__ ol)
{
    const int D = 512;
    int row = blockIdx.x;
    int t = threadIdx.x;
    float4 v = ((const float4*)(X + (long)row * D))[t];
    float s  = v.x + v.y + v.z + v.w;
    float sq = v.x * v.x + v.y * v.y + v.z * v.z + v.w * v.w;
    #pragma unroll
    for (int o = 16; o; o >>= 1) {
        s  += __shfl_xor_sync(0xFFFFFFFFu, s, o);
        sq += __shfl_xor_sync(0xFFFFFFFFu, sq, o);
    }
    __shared__ float ss[4], ssq[4];
    int w = t >> 5, l = t & 31;
    if (l == 0) { ss[w] = s; ssq[w] = sq; }
    __syncthreads();
    s  = ss[0] + ss[1] + ss[2] + ss[3];
    sq = ssq[0] + ssq[1] + ssq[2] + ssq[3];
    float mean = s * (1.0f / 512.0f);
    float var  = sq * (1.0f / 512.0f) - mean * mean;
    float rs   = rsqrtf(var + 1e-5f);
    float4 gv = ((const float4*)gg)[t];
    float4 bv = ((const float4*)bb)[t];
    float o0 = (v.x - mean) * rs * gv.x + bv.x;
    float o1 = (v.y - mean) * rs * gv.y + bv.y;
    float o2 = (v.z - mean) * rs * gv.z + bv.z;
    float o3 = (v.w - mean) * rs * gv.w + bv.w;
    long e = (long)row * D + t * 4;
    bsplit2(o0, o1, oh + e,     ol + e);
    bsplit2(o2, o3, oh + e + 2, ol + e + 2);
}

// ================= launch =================
extern "C" void kernel_launch(void* const* d_in, const int* in_sizes, int n_in,
                              void* d_out, int out_size)
{
    const float* x    = (const float*)d_in[0];
    const float* Wk1  = (const float*)d_in[1];
    const float* bk1  = (const float*)d_in[2];
    const float* Wk2  = (const float*)d_in[3];
    const float* bk2  = (const float*)d_in[4];
    const float* Wq1  = (const float*)d_in[5];
    const float* bq1  = (const float*)d_in[6];
    const float* Wq2  = (const float*)d_in[7];
    const float* bq2  = (const float*)d_in[8];
    const float* Wv   = (const float*)d_in[9];
    const float* bv   = (const float*)d_in[10];
    const float* ln_g = (const float*)d_in[11];
    const float* ln_b = (const float*)d_in[12];
    const float* Wo   = (const float*)d_in[13];
    const float* bo   = (const float*)d_in[14];
    float* out = (float*)d_out;

    void* p;
    cudaGetSymbolAddress(&p, g_xh);    bf16* xh    = (bf16*)p;
    cudaGetSymbolAddress(&p, g_xl);    bf16* xl    = (bf16*)p;
    cudaGetSymbolAddress(&p, g_Wth);   bf16* Wth   = (bf16*)p;
    cudaGetSymbolAddress(&p, g_Wtl);   bf16* Wtl   = (bf16*)p;
    cudaGetSymbolAddress(&p, g_Wph);   bf16* Wph   = (bf16*)p;
    cudaGetSymbolAddress(&p, g_Wpl);   bf16* Wpl   = (bf16*)p;
    cudaGetSymbolAddress(&p, g_Hkh);   bf16* Hkh   = (bf16*)p;
    cudaGetSymbolAddress(&p, g_Hkl);   bf16* Hkl   = (bf16*)p;
    cudaGetSymbolAddress(&p, g_Hqh);   bf16* Hqh   = (bf16*)p;
    cudaGetSymbolAddress(&p, g_Hql);   bf16* Hql   = (bf16*)p;
    cudaGetSymbolAddress(&p, g_Vh);    bf16* Vh    = (bf16*)p;
    cudaGetSymbolAddress(&p, g_Vl);    bf16* Vl    = (bf16*)p;
    cudaGetSymbolAddress(&p, g_CSkh);  bf16* CSkh  = (bf16*)p;
    cudaGetSymbolAddress(&p, g_CSkl);  bf16* CSkl  = (bf16*)p;
    cudaGetSymbolAddress(&p, g_CSqh);  bf16* CSqh  = (bf16*)p;
    cudaGetSymbolAddress(&p, g_CSql);  bf16* CSql  = (bf16*)p;
    cudaGetSymbolAddress(&p, g_CSkTh); bf16* CSkTh = (bf16*)p;
    cudaGetSymbolAddress(&p, g_CSkTl); bf16* CSkTl = (bf16*)p;
    cudaGetSymbolAddress(&p, g_Ach);   bf16* Ach   = (bf16*)p;
    cudaGetSymbolAddress(&p, g_Acl);   bf16* Acl   = (bf16*)p;
    cudaGetSymbolAddress(&p, g_S);     float* S    = (float*)p;
    cudaGetSymbolAddress(&p, g_Ph);    bf16* Ph    = (bf16*)p;
    cudaGetSymbolAddress(&p, g_Pl);    bf16* Pl    = (bf16*)p;
    cudaGetSymbolAddress(&p, g_R);     float* R    = (float*)p;
    cudaGetSymbolAddress(&p, g_LNh);   bf16* LNh   = (bf16*)p;
    cudaGetSymbolAddress(&p, g_LNl);   bf16* LNl   = (bf16*)p;

    static int attr_set = 0;
    if (!attr_set) {
        cudaFuncSetAttribute(mma_gemm<0>, cudaFuncAttributeMaxDynamicSharedMemorySize, X_SMEM);
        cudaFuncSetAttribute(mma_gemm<1>, cudaFuncAttributeMaxDynamicSharedMemorySize, X_SMEM);
        cudaFuncSetAttribute(sac_mma,     cudaFuncAttributeMaxDynamicSharedMemorySize, SAC_SMEM);
        cudaFuncSetAttribute(r_mma,       cudaFuncAttributeMaxDynamicSharedMemorySize, R_SMEM);
        attr_set = 1;
    }

    // 0) conversions (one launch)
    prep_kernel<<<2112, 256>>>(x, Wk1, Wq1, Wv, Wo, Wk2, Wq2,
                               xh, xl, Wth, Wtl, Wph, Wpl);

    // 1) XW: Hk(gelu), Hq(gelu), V(bias) -> split bf16. grid (4,32,3)=384.
    mma_gemm<0><<<dim3(4,32,3), 256, X_SMEM>>>(
        xh, xl, Wth, Wtl, bk1, bq1, bv, nullptr,
        Hkh, Hkl, Hqh, Hql, Vh, Vl, nullptr);

    // 2) Phases: CSk/CSq + CSk^T. grid (1,32,2)=64.
    phase_mma<<<dim3(1,32,2), 128, PH_SMEM>>>(
        Hkh, Hkl, Hqh, Hql, Wph, Wpl, bk2, bq2,
        CSkh, CSkl, CSqh, CSql, CSkTh, CSkTl);

    // 3) S + Ac combined. grid (5,1,32)=160.
    sac_mma<<<dim3(5,1,32), 256, SAC_SMEM>>>(
        CSkTh, CSkTl, Vh, Vl, CSqh, CSql, CSkh, CSkl, S, Ach, Acl);

    // 4) exclusive prefix -> split bf16 P
    prefix_kernel<<<128, 256>>>((const float4*)S, Ph, Pl);

    // 5) R = (CSq@P + Ac@V) * scale. grid (4,1,32)=128.
    r_mma<<<dim3(4,1,32), 256, R_SMEM>>>(
        CSqh, CSql, Ach, Acl, Ph, Pl, Vh, Vl, R);

    // 6) LN -> split bf16
    ln_kernel<<<2048, 128>>>(R, ln_g, ln_b, LNh, LNl);

    // 7) out = x + LN @ Wo + bo. grid (4,32)=128.
    mma_gemm<1><<<dim3(4,32,1), 256, X_SMEM>>>(
        LNh, LNl, Wth + 3L*262144, Wtl + 3L*262144, bo, nullptr, nullptr, x,
        nullptr, nullptr, nullptr, nullptr, nullptr, nullptr, out);
}

// round 8
// speedup vs baseline: 5.2660x; 1.0787x over previous
#include <cuda_runtime.h>
#include <cuda_bf16.h>
#include <math.h>
#include <stdint.h>

#define PI_F 3.14159265358979323846f
typedef __nv_bfloat16 bf16;

// ---------------- scratch (allocation-free: __device__ globals) ----------------
__device__ bf16 g_xh  [2048 * 512];
__device__ bf16 g_xl  [2048 * 512];
__device__ bf16 g_Wth [4 * 512 * 512];
__device__ bf16 g_Wtl [4 * 512 * 512];
__device__ bf16 g_Wph [128 * 512];
__device__ bf16 g_Wpl [128 * 512];
__device__ bf16 g_Hkh [2048 * 512];
__device__ bf16 g_Hkl [2048 * 512];
__device__ bf16 g_Hqh [2048 * 512];
__device__ bf16 g_Hql [2048 * 512];
__device__ bf16 g_Vh  [2048 * 512];
__device__ bf16 g_Vl  [2048 * 512];
__device__ bf16 g_CSkh[2048 * 128];
__device__ bf16 g_CSkl[2048 * 128];
__device__ bf16 g_CSqh[2048 * 128];
__device__ bf16 g_CSql[2048 * 128];
__device__ bf16 g_CSkTh[32 * 128 * 64];
__device__ bf16 g_CSkTl[32 * 128 * 64];
__device__ bf16 g_Ach [32 * 64 * 64];
__device__ bf16 g_Acl [32 * 64 * 64];
__device__ float g_S  [32 * 128 * 512];
__device__ bf16 g_Ph  [32 * 128 * 512];
__device__ bf16 g_Pl  [32 * 128 * 512];
__device__ float g_R  [2048 * 512];
__device__ bf16 g_LNh [2048 * 512];
__device__ bf16 g_LNl [2048 * 512];

// ================= PTX helpers =================
__device__ __forceinline__ uint32_t smem_u32(const void* p) {
    uint32_t a;
    asm("{ .reg .u64 t; cvta.to.shared.u64 t, %1; cvt.u32.u64 %0, t; }" : "=r"(a) : "l"(p));
    return a;
}
__device__ __forceinline__ void cp16(uint32_t dst, const void* src) {
    asm volatile("cp.async.cg.shared.global [%0], [%1], 16;" :: "r"(dst), "l"(src));
}
__device__ __forceinline__ void ldx4(uint32_t* r, uint32_t addr) {
    asm volatile("ldmatrix.sync.aligned.m8n8.x4.shared.b16 {%0,%1,%2,%3}, [%4];"
        : "=r"(r[0]), "=r"(r[1]), "=r"(r[2]), "=r"(r[3]) : "r"(addr));
}
__device__ __forceinline__ void ldx4t(uint32_t* r, uint32_t addr) {
    asm volatile("ldmatrix.sync.aligned.m8n8.x4.trans.shared.b16 {%0,%1,%2,%3}, [%4];"
        : "=r"(r[0]), "=r"(r[1]), "=r"(r[2]), "=r"(r[3]) : "r"(addr));
}
__device__ __forceinline__ void mma16816(float* c, const uint32_t* a,
                                         uint32_t b0, uint32_t b1) {
    asm volatile("mma.sync.aligned.m16n8k16.row.col.f32.bf16.bf16.f32 "
        "{%0,%1,%2,%3}, {%4,%5,%6,%7}, {%8,%9}, {%0,%1,%2,%3};"
        : "+f"(c[0]), "+f"(c[1]), "+f"(c[2]), "+f"(c[3])
        : "r"(a[0]), "r"(a[1]), "r"(a[2]), "r"(a[3]), "r"(b0), "r"(b1));
}
__device__ __forceinline__ void bsplit2(float v0, float v1, bf16* hd, bf16* ld) {
    __nv_bfloat162 h, l;
    h.x = __float2bfloat16(v0); h.y = __float2bfloat16(v1);
    l.x = __float2bfloat16(v0 - __bfloat162float(h.x));
    l.y = __float2bfloat16(v1 - __bfloat162float(h.y));
    *(__nv_bfloat162*)hd = h; *(__nv_bfloat162*)ld = l;
}
#define CPA_COMMIT() asm volatile("cp.async.commit_group;" ::: "memory")
#define CPA_WAIT2()  asm volatile("cp.async.wait_group 2;" ::: "memory")
#define CPA_WAIT1()  asm volatile("cp.async.wait_group 1;" ::: "memory")
#define CPA_WAIT0()  asm volatile("cp.async.wait_group 0;" ::: "memory")

// ================= XW / OUT GEMM: 64x128 tile, 128 thr, 4 warps (2m x 2n),
// warp tile 32x64, 3 CTAs/SM ====
static constexpr int XA_ARR = 64 * 80;          // 5120
static constexpr int XB_OFF = 2 * XA_ARR;       // 10240
static constexpr int XB_ARR = 128 * 80;         // 10240
static constexpr int X_BUF  = XB_OFF + 2 * XB_ARR;  // 30720
static constexpr int X_SMEM = 2 * X_BUF;        // 61440

template<int MODE>   // 0: XW (split bf16 out, gelu z<2), 1: OUT (fp32 + resid)
__global__ __launch_bounds__(128, 3)
void mma_gemm(const bf16* __restrict__ Ah, const bf16* __restrict__ Al,
              const bf16* __restrict__ Wth, const bf16* __restrict__ Wtl,
              const float* __restrict__ b0, const float* __restrict__ b1,
              const float* __restrict__ b2, const float* __restrict__ resid,
              bf16* __restrict__ O0h, bf16* __restrict__ O0l,
              bf16* __restrict__ O1h, bf16* __restrict__ O1l,
              bf16* __restrict__ O2h, bf16* __restrict__ O2l,
              float* __restrict__ Cout)
{
    extern __shared__ __align__(128) char smem[];
    const uint32_t sb = smem_u32(smem);
    const int tid = threadIdx.x, wid = tid >> 5, lane = tid & 31;
    const int row0 = blockIdx.y * 64, col0 = blockIdx.x * 128;
    const int z = (MODE == 0) ? blockIdx.z : 0;
    const bf16* Bh = Wth + (long)z * 262144;
    const bf16* Bl = Wtl + (long)z * 262144;
    const float* bias = (z == 0) ? b0 : (z == 1 ? b1 : b2);
    const bool gelu = (MODE == 0) && (z < 2);
    bf16* Oh = (z == 0) ? O0h : (z == 1 ? O1h : O2h);
    bf16* Ol = (z == 0) ? O0l : (z == 1 ? O1l : O2l);

    const int wm = (wid & 1) * 32, wn = (wid >> 1) * 64;
    float acc[2][8][4];
    #pragma unroll
    for (int i = 0; i < 2; i++)
        #pragma unroll
        for (int j = 0; j < 8; j++)
            #pragma unroll
            for (int e = 0; e < 4; e++) acc[i][j][e] = 0.0f;

    const int g = lane >> 3, wr = lane & 7;
    const int fRow = wr + (g & 1) * 8, fK = (g >> 1) * 8;

    auto load_chunk = [&](int ch, int b) {
        const int k0 = ch * 32;
        const uint32_t base = sb + b * X_BUF;
        #pragma unroll
        for (int l = 0; l < 4; l++) {
            const int idx = tid + l * 128;
            const int arr = idx >> 8, rr = (idx >> 2) & 63, s = idx & 3;
            cp16(base + arr * XA_ARR + rr * 80 + s * 16,
                 (arr ? Al : Ah) + (long)(row0 + rr) * 512 + k0 + s * 8);
        }
        #pragma unroll
        for (int l = 0; l < 8; l++) {
            const int idx = tid + l * 128;
            const int arr = idx >> 9, rr = (idx >> 2) & 127, s = idx & 3;
            cp16(base + XB_OFF + arr * XB_ARR + rr * 80 + s * 16,
                 (arr ? Bl : Bh) + (long)(col0 + rr) * 512 + k0 + s * 8);
        }
        CPA_COMMIT();
    };

    load_chunk(0, 0);
    for (int ch = 0; ch < 16; ch++) {
        const int b = ch & 1;
        if (ch < 15) { load_chunk(ch + 1, b ^ 1); CPA_WAIT1(); }
        else CPA_WAIT0();
        __syncthreads();
        const uint32_t base = sb + b * X_BUF;
        #pragma unroll
        for (int ks = 0; ks < 2; ks++) {
            uint32_t ahf[2][4], alf[2][4], bb[4][4];
            #pragma unroll
            for (int mt = 0; mt < 2; mt++) {
                const uint32_t ra = base + (wm + mt * 16 + fRow) * 80 + (ks * 16 + fK) * 2;
                ldx4(ahf[mt], ra);
                ldx4(alf[mt], ra + XA_ARR);
            }
            #pragma unroll
            for (int nt = 0; nt < 4; nt++) {
                const uint32_t rb = base + XB_OFF + (wn + nt * 16 + fRow) * 80 + (ks * 16 + fK) * 2;
                ldx4(bb[nt], rb);
            }
            #pragma unroll
            for (int mt = 0; mt < 2; mt++)
                #pragma unroll
                for (int nt = 0; nt < 4; nt++) {
                    mma16816(acc[mt][nt*2],   ahf[mt], bb[nt][0], bb[nt][2]);
                    mma16816(acc[mt][nt*2+1], ahf[mt], bb[nt][1], bb[nt][3]);
                    mma16816(acc[mt][nt*2],   alf[mt], bb[nt][0], bb[nt][2]);
                    mma16816(acc[mt][nt*2+1], alf[mt], bb[nt][1], bb[nt][3]);
                }
            #pragma unroll
            for (int nt = 0; nt < 4; nt++) {
                const uint32_t rb = base + XB_OFF + XB_ARR + (wn + nt * 16 + fRow) * 80 + (ks * 16 + fK) * 2;
                ldx4(bb[nt], rb);
            }
            #pragma unroll
            for (int mt = 0; mt < 2; mt++)
                #pragma unroll
                for (int nt = 0; nt < 4; nt++) {
                    mma16816(acc[mt][nt*2],   ahf[mt], bb[nt][0], bb[nt][2]);
                    mma16816(acc[mt][nt*2+1], ahf[mt], bb[nt][1], bb[nt][3]);
                }
        }
        __syncthreads();
    }

    #pragma unroll
    for (int mt = 0; mt < 2; mt++)
        #pragma unroll
        for (int h = 0; h < 2; h++) {
            const int row = row0 + wm + mt * 16 + h * 8 + (lane >> 2);
            #pragma unroll
            for (int n8 = 0; n8 < 8; n8++) {
                const int col = col0 + wn + n8 * 8 + (lane & 3) * 2;
                float v0 = acc[mt][n8][h * 2 + 0];
                float v1 = acc[mt][n8][h * 2 + 1];
                const float2 bq = *(const float2*)&bias[col];
                v0 += bq.x; v1 += bq.y;
                if (MODE == 0) {
                    if (gelu) {
                        v0 = 0.5f * v0 * (1.0f + erff(v0 * 0.70710678118654752f));
                        v1 = 0.5f * v1 * (1.0f + erff(v1 * 0.70710678118654752f));
                    }
                    bsplit2(v0, v1, Oh + (long)row * 512 + col, Ol + (long)row * 512 + col);
                } else {
                    const float2 r2 = *(const float2*)&resid[(long)row * 512 + col];
                    float2 o; o.x = v0 + r2.x; o.y = v1 + r2.y;
                    *(float2*)&Cout[(long)row * 512 + col] = o;
                }
            }
        }
}

// ================= phase GEMM: 32x64 tile, 128 thr, 4 warps (2m x 2n),
// warp tile 16x32, 3-stage pipeline =========
static constexpr int PA_ARR = 32 * 80;      // 2560
static constexpr int PB_OFF = 2 * PA_ARR;   // 5120
static constexpr int PB_ARR = 64 * 80;      // 5120
static constexpr int P_BUF  = PB_OFF + 2 * PB_ARR;  // 15360
static constexpr int P_SMEM = 3 * P_BUF;    // 46080

__global__ __launch_bounds__(128)
void phase_mma(const bf16* __restrict__ Hkh, const bf16* __restrict__ Hkl,
               const bf16* __restrict__ Hqh, const bf16* __restrict__ Hql,
               const bf16* __restrict__ Wph, const bf16* __restrict__ Wpl,
               const float* __restrict__ bk2, const float* __restrict__ bq2,
               bf16* __restrict__ CSkh, bf16* __restrict__ CSkl,
               bf16* __restrict__ CSqh, bf16* __restrict__ CSql,
               bf16* __restrict__ CSkTh, bf16* __restrict__ CSkTl)
{
    extern __shared__ __align__(128) char smem[];
    const uint32_t sb = smem_u32(smem);
    const int tid = threadIdx.x, wid = tid >> 5, lane = tid & 31;
    const int z = blockIdx.z, row0 = blockIdx.y * 32;
    const bf16* Ah = z ? Hqh : Hkh;
    const bf16* Al = z ? Hql : Hkl;
    const bf16* Bh = Wph + (long)z * 64 * 512;
    const bf16* Bl = Wpl + (long)z * 64 * 512;
    const float* bias = z ? bq2 : bk2;

    const int wm = (wid & 1) * 16, wn = (wid >> 1) * 32;
    float acc[4][4];
    #pragma unroll
    for (int j = 0; j < 4; j++)
        #pragma unroll
        for (int e = 0; e < 4; e++) acc[j][e] = 0.0f;

    const int g = lane >> 3, wr = lane & 7;
    const int fRow = wr + (g & 1) * 8, fK = (g >> 1) * 8;

    auto load_chunk = [&](int ch) {
        const int k0 = ch * 32;
        const uint32_t base = sb + (ch % 3) * P_BUF;
        #pragma unroll
        for (int l = 0; l < 2; l++) {
            const int idx = tid + l * 128;
            const int arr = idx >> 7, rr = (idx >> 2) & 31, s = idx & 3;
            cp16(base + arr * PA_ARR + rr * 80 + s * 16,
                 (arr ? Al : Ah) + (long)(row0 + rr) * 512 + k0 + s * 8);
        }
        #pragma unroll
        for (int l = 0; l < 4; l++) {
            const int idx = tid + l * 128;
            const int arr = idx >> 8, rr = (idx >> 2) & 63, s = idx & 3;
            cp16(base + PB_OFF + arr * PB_ARR + rr * 80 + s * 16,
                 (arr ? Bl : Bh) + (long)rr * 512 + k0 + s * 8);
        }
        CPA_COMMIT();
    };

    load_chunk(0); load_chunk(1);
    for (int ch = 0; ch < 16; ch++) {
        if (ch + 2 < 16) load_chunk(ch + 2);
        if (ch < 14) CPA_WAIT2();
        else if (ch == 14) CPA_WAIT1();
        else CPA_WAIT0();
        __syncthreads();
        const uint32_t base = sb + (ch % 3) * P_BUF;
        #pragma unroll
        for (int ks = 0; ks < 2; ks++) {
            uint32_t ahf[4], alf[4], bb[2][4];
            {
                const uint32_t ra = base + (wm + fRow) * 80 + (ks * 16 + fK) * 2;
                ldx4(ahf, ra);
                ldx4(alf, ra + PA_ARR);
            }
            #pragma unroll
            for (int nt = 0; nt < 2; nt++) {
                const uint32_t rb = base + PB_OFF + (wn + nt * 16 + fRow) * 80 + (ks * 16 + fK) * 2;
                ldx4(bb[nt], rb);
            }
            #pragma unroll
            for (int nt = 0; nt < 2; nt++) {
                mma16816(acc[nt*2],   ahf, bb[nt][0], bb[nt][2]);
                mma16816(acc[nt*2+1], ahf, bb[nt][1], bb[nt][3]);
                mma16816(acc[nt*2],   alf, bb[nt][0], bb[nt][2]);
                mma16816(acc[nt*2+1], alf, bb[nt][1], bb[nt][3]);
            }
            #pragma unroll
            for (int nt = 0; nt < 2; nt++) {
                const uint32_t rb = base + PB_OFF + PB_ARR + (wn + nt * 16 + fRow) * 80 + (ks * 16 + fK) * 2;
                ldx4(bb[nt], rb);
            }
            #pragma unroll
            for (int nt = 0; nt < 2; nt++) {
                mma16816(acc[nt*2],   ahf, bb[nt][0], bb[nt][2]);
                mma16816(acc[nt*2+1], ahf, bb[nt][1], bb[nt][3]);
            }
        }
        __syncthreads();
    }

    #pragma unroll
    for (int h = 0; h < 2; h++) {
        const int row = row0 + wm + h * 8 + (lane >> 2);
        #pragma unroll
        for (int j = 0; j < 4; j++) {
            const int n = wn + (j >> 1) * 16 + (j & 1) * 8 + (lane & 3) * 2;
            float v0 = acc[j][h * 2 + 0] + bias[n];
            float v1 = acc[j][h * 2 + 1] + bias[n + 1];
            float p0 = tanhf(v0) * PI_F, p1 = tanhf(v1) * PI_F;
            float c0, s0, c1, s1;
            sincosf(p0, &s0, &c0);
            sincosf(p1, &s1, &c1);
            bf16* Rh = z ? CSqh : CSkh;
            bf16* Rl = z ? CSql : CSkl;
            const long rb_ = (long)row * 128;
            bsplit2(c0, c1, Rh + rb_ + n,      Rl + rb_ + n);
            bsplit2(s0, s1, Rh + rb_ + n + 64, Rl + rb_ + n + 64);
            if (!z) {
                const int c = row >> 6, ro = row & 63;
                const long t0 = (long)c * 8192 + (long)n * 64 + ro;
                bf16 h0 = __float2bfloat16(c0);
                bf16 h1 = __float2bfloat16(c1);
                bf16 h2 = __float2bfloat16(s0);
                bf16 h3 = __float2bfloat16(s1);
                CSkTh[t0]        = h0;
                CSkTh[t0 + 64]   = h1;
                CSkTh[t0 + 4096] = h2;
                CSkTh[t0 + 4160] = h3;
                CSkTl[t0]        = __float2bfloat16(c0 - __bfloat162float(h0));
                CSkTl[t0 + 64]   = __float2bfloat16(c1 - __bfloat162float(h1));
                CSkTl[t0 + 4096] = __float2bfloat16(s0 - __bfloat162float(h2));
                CSkTl[t0 + 4160] = __float2bfloat16(s1 - __bfloat162float(h3));
            }
        }
    }
}

// ================= S + Ac combined launch ==================================
// blockIdx.x<8: S col tile 64 wide (M128,N64,K64). blockIdx.x==8: Ac (M64,N64,K128).
static constexpr int S_AARR = 128 * 80;          // 10240
static constexpr int S_BOFF = 2 * S_AARR;        // 20480
static constexpr int S_BARR = 32 * 144;          // 4608
static constexpr int S_BUF  = S_BOFF + 2 * S_BARR;  // 29696
static constexpr int SAC_SMEM = 2 * S_BUF;       // 59392
static constexpr int AC_AARR = 64 * 80;          // 5120
static constexpr int AC_BOFF = 2 * AC_AARR;      // 10240
static constexpr int AC_BUF  = 2 * AC_BOFF;      // 20480

__global__ __launch_bounds__(256)
void sac_mma(const bf16* __restrict__ CSkTh, const bf16* __restrict__ CSkTl,
             const bf16* __restrict__ Vh, const bf16* __restrict__ Vl,
             const bf16* __restrict__ CSqh, const bf16* __restrict__ CSql,
             const bf16* __restrict__ CSkh, const bf16* __restrict__ CSkl,
             float* __restrict__ S, bf16* __restrict__ Ach, bf16* __restrict__ Acl)
{
    extern __shared__ __align__(128) char smem[];
    const uint32_t sb = smem_u32(smem);
    const int tid = threadIdx.x, wid = tid >> 5, lane = tid & 31;
    const int c = blockIdx.z;
    const int g = lane >> 3, wr = lane & 7;
    const int fRow = wr + (g & 1) * 8, fK = (g >> 1) * 8;
    const int tK = fRow, tN = (g >> 1) * 8;

    if (blockIdx.x < 8) {
        // ---------- S path: M128 x N64, K=64 ----------
        const int col0 = blockIdx.x * 64;
        const int wm = (wid & 3) * 32, wn = (wid >> 2) * 32;
        float acc[2][4][4];
        #pragma unroll
        for (int i = 0; i < 2; i++)
            #pragma unroll
            for (int j = 0; j < 4; j++)
                #pragma unroll
                for (int e = 0; e < 4; e++) acc[i][j][e] = 0.0f;

        auto load_chunk = [&](int ch, int b) {
            const int k0 = ch * 32;
            const uint32_t base = sb + b * S_BUF;
            #pragma unroll
            for (int l = 0; l < 4; l++) {   // A: CSkT 128 rows, ld 64
                const int idx = tid + l * 256;
                const int arr = idx >> 9, rr = (idx >> 2) & 127, s = idx & 3;
                cp16(base + arr * S_AARR + rr * 80 + s * 16,
                     (arr ? CSkTl : CSkTh) + (long)c * 8192 + (long)rr * 64 + k0 + s * 8);
            }
            #pragma unroll
            for (int l = 0; l < 2; l++) {   // B: V 32 k-rows x 64 cols, ld 512
                const int idx = tid + l * 256;
                const int arr = idx >> 8, rr = (idx >> 3) & 31, s = idx & 7;
                cp16(base + S_BOFF + arr * S_BARR + rr * 144 + s * 16,
                     (arr ? Vl : Vh) + ((long)c * 64 + k0 + rr) * 512 + col0 + s * 8);
            }
            CPA_COMMIT();
        };

        load_chunk(0, 0);
        load_chunk(1, 1);
        for (int ch = 0; ch < 2; ch++) {
            if (ch == 0) CPA_WAIT1(); else CPA_WAIT0();
            __syncthreads();
            const uint32_t base = sb + ch * S_BUF;
            #pragma unroll
            for (int ks = 0; ks < 2; ks++) {
                uint32_t ahf[2][4], alf[2][4], bb[2][4];
                #pragma unroll
                for (int mt = 0; mt < 2; mt++) {
                    const uint32_t ra = base + (wm + mt * 16 + fRow) * 80 + (ks * 16 + fK) * 2;
                    ldx4(ahf[mt], ra);
                    ldx4(alf[mt], ra + S_AARR);
                }
                #pragma unroll
                for (int nt = 0; nt < 2; nt++) {
                    const uint32_t rb = base + S_BOFF + (ks * 16 + tK) * 144 + (wn + nt * 16 + tN) * 2;
                    ldx4t(bb[nt], rb);
                }
                #pragma unroll
                for (int mt = 0; mt < 2; mt++)
                    #pragma unroll
                    for (int nt = 0; nt < 2; nt++) {
                        mma16816(acc[mt][nt*2],   ahf[mt], bb[nt][0], bb[nt][1]);
                        mma16816(acc[mt][nt*2+1], ahf[mt], bb[nt][2], bb[nt][3]);
                        mma16816(acc[mt][nt*2],   alf[mt], bb[nt][0], bb[nt][1]);
                        mma16816(acc[mt][nt*2+1], alf[mt], bb[nt][2], bb[nt][3]);
                    }
                #pragma unroll
                for (int nt = 0; nt < 2; nt++) {
                    const uint32_t rb = base + S_BOFF + S_BARR + (ks * 16 + tK) * 144 + (wn + nt * 16 + tN) * 2;
                    ldx4t(bb[nt], rb);
                }
                #pragma unroll
                for (int mt = 0; mt < 2; mt++)
                    #pragma unroll
                    for (int nt = 0; nt < 2; nt++) {
                        mma16816(acc[mt][nt*2],   ahf[mt], bb[nt][0], bb[nt][1]);
                        mma16816(acc[mt][nt*2+1], ahf[mt], bb[nt][2], bb[nt][3]);
                    }
            }
            __syncthreads();
        }

        #pragma unroll
        for (int mt = 0; mt < 2; mt++)
            #pragma unroll
            for (int h = 0; h < 2; h++) {
                const int m = wm + mt * 16 + h * 8 + (lane >> 2);
                const long orow = (long)c * 65536 + (long)m * 512;
                #pragma unroll
                for (int n8 = 0; n8 < 4; n8++) {
                    const int col = col0 + wn + n8 * 8 + (lane & 3) * 2;
                    float2 o; o.x = acc[mt][n8][h*2+0]; o.y = acc[mt][n8][h*2+1];
                    *(float2*)&S[orow + col] = o;
                }
            }
    } else {
        // ---------- Ac path: M64,N64,K128 ----------
        const int wm = (wid & 1) * 32, wn = (wid >> 1) * 16;
        float acc[2][2][4];
        #pragma unroll
        for (int i = 0; i < 2; i++)
            #pragma unroll
            for (int j = 0; j < 2; j++)
                #pragma unroll
                for (int e = 0; e < 4; e++) acc[i][j][e] = 0.0f;

        auto load_chunk = [&](int ch, int b) {
            const int k0 = ch * 32;
            const uint32_t base = sb + b * AC_BUF;
            #pragma unroll
            for (int l = 0; l < 2; l++) {
                const int idx = tid + l * 256;
                const int arr = idx >> 8, rr = (idx >> 2) & 63, s = idx & 3;
                cp16(base + arr * AC_AARR + rr * 80 + s * 16,
                     (arr ? CSql : CSqh) + ((long)c * 64 + rr) * 128 + k0 + s * 8);
            }
            #pragma unroll
            for (int l = 0; l < 2; l++) {
                const int idx = tid + l * 256;
                const int arr = idx >> 8, rr = (idx >> 2) & 63, s = idx & 3;
                cp16(base + AC_BOFF + arr * AC_AARR + rr * 80 + s * 16,
                     (arr ? CSkl : CSkh) + ((long)c * 64 + rr) * 128 + k0 + s * 8);
            }
            CPA_COMMIT();
        };

        load_chunk(0, 0);
        for (int ch = 0; ch < 4; ch++) {
            const int b = ch & 1;
            if (ch < 3) { load_chunk(ch + 1, b ^ 1); CPA_WAIT1(); }
            else CPA_WAIT0();
            __syncthreads();
            const uint32_t base = sb + b * AC_BUF;
            #pragma unroll
            for (int ks = 0; ks < 2; ks++) {
                uint32_t ahf[2][4], alf[2][4], bb[4];
                #pragma unroll
                for (int mt = 0; mt < 2; mt++) {
                    const uint32_t ra = base + (wm + mt * 16 + fRow) * 80 + (ks * 16 + fK) * 2;
                    ldx4(ahf[mt], ra);
                    ldx4(alf[mt], ra + AC_AARR);
                }
                {
                    const uint32_t rb = base + AC_BOFF + (wn + fRow) * 80 + (ks * 16 + fK) * 2;
                    ldx4(bb, rb);
                }
                #pragma unroll
                for (int mt = 0; mt < 2; mt++) {
                    mma16816(acc[mt][0], ahf[mt], bb[0], bb[2]);
                    mma16816(acc[mt][1], ahf[mt], bb[1], bb[3]);
                    mma16816(acc[mt][0], alf[mt], bb[0], bb[2]);
                    mma16816(acc[mt][1], alf[mt], bb[1], bb[3]);
                }
                {
                    const uint32_t rb = base + AC_BOFF + AC_AARR + (wn + fRow) * 80 + (ks * 16 + fK) * 2;
                    ldx4(bb, rb);
                }
                #pragma unroll
                for (int mt = 0; mt < 2; mt++) {
                    mma16816(acc[mt][0], ahf[mt], bb[0], bb[2]);
                    mma16816(acc[mt][1], ahf[mt], bb[1], bb[3]);
                }
            }
            __syncthreads();
        }

        #pragma unroll
        for (int mt = 0; mt < 2; mt++)
            #pragma unroll
            for (int h = 0; h < 2; h++) {
                const int row = wm + mt * 16 + h * 8 + (lane >> 2);
                #pragma unroll
                for (int n8 = 0; n8 < 2; n8++) {
                    const int col = wn + n8 * 8 + (lane & 3) * 2;
                    float v0 = (col     <= row) ? acc[mt][n8][h*2+0] : 0.0f;
                    float v1 = (col + 1 <= row) ? acc[mt][n8][h*2+1] : 0.0f;
                    const long o = (long)c * 4096 + (long)row * 64 + col;
                    bsplit2(v0, v1, Ach + o, Acl + o);
                }
            }
    }
}

// ================= R GEMM: M64,N64,K192, 128 thr, 4 warps (2m x 2n),
// warp 32x32, 3-stage pipeline ================
static constexpr int R_AARR = 64 * 80;          // 5120
static constexpr int R_BOFF = 2 * R_AARR;       // 10240
static constexpr int R_BARR = 32 * 144;         // 4608
static constexpr int R_BUF  = R_BOFF + 2 * R_BARR;  // 19456
static constexpr int R_SMEM = 3 * R_BUF;        // 58368

__global__ __launch_bounds__(128)
void r_mma(const bf16* __restrict__ CSqh, const bf16* __restrict__ CSql,
           const bf16* __restrict__ Ach, const bf16* __restrict__ Acl,
           const bf16* __restrict__ Ph, const bf16* __restrict__ Pl,
           const bf16* __restrict__ Vh, const bf16* __restrict__ Vl,
           float* __restrict__ Out)
{
    extern __shared__ __align__(128) char smem[];
    const uint32_t sb = smem_u32(smem);
    const int tid = threadIdx.x, wid = tid >> 5, lane = tid & 31;
    const int c = blockIdx.z, col0 = blockIdx.x * 64;
    const int wm = (wid & 1) * 32, wn = (wid >> 1) * 32;
    const int g = lane >> 3, wr = lane & 7;
    const int fRow = wr + (g & 1) * 8, fK = (g >> 1) * 8;
    const int tK = fRow, tN = (g >> 1) * 8;

    float acc[2][4][4];
    #pragma unroll
    for (int i = 0; i < 2; i++)
        #pragma unroll
        for (int j = 0; j < 4; j++)
            #pragma unroll
            for (int e = 0; e < 4; e++) acc[i][j][e] = 0.0f;

    auto load_chunk = [&](int ch) {
        const uint32_t base = sb + (ch % 3) * R_BUF;
        const bf16 *aH, *aL, *bH, *bL;
        int ldA, k0;
        long rowB;
        if (ch < 4) {
            aH = CSqh + (long)c * 8192; aL = CSql + (long)c * 8192;
            ldA = 128; k0 = ch * 32;
            bH = Ph; bL = Pl; rowB = (long)c * 128 + ch * 32;
        } else {
            aH = Ach + (long)c * 4096; aL = Acl + (long)c * 4096;
            ldA = 64; k0 = (ch - 4) * 32;
            bH = Vh; bL = Vl; rowB = (long)c * 64 + (ch - 4) * 32;
        }
        #pragma unroll
        for (int l = 0; l < 4; l++) {
            const int idx = tid + l * 128;
            const int arr = idx >> 8, rr = (idx >> 2) & 63, s = idx & 3;
            cp16(base + arr * R_AARR + rr * 80 + s * 16,
                 (arr ? aL : aH) + (long)rr * ldA + k0 + s * 8);
        }
        #pragma unroll
        for (int l = 0; l < 4; l++) {
            const int idx = tid + l * 128;
            const int arr = idx >> 8, rr = (idx >> 3) & 31, s = idx & 7;
            cp16(base + R_BOFF + arr * R_BARR + rr * 144 + s * 16,
                 (arr ? bL : bH) + (rowB + rr) * 512 + col0 + s * 8);
        }
        CPA_COMMIT();
    };

    load_chunk(0); load_chunk(1);
    for (int ch = 0; ch < 6; ch++) {
        if (ch + 2 < 6) load_chunk(ch + 2);
        if (ch < 4) CPA_WAIT2();
        else if (ch == 4) CPA_WAIT1();
        else CPA_WAIT0();
        __syncthreads();
        const uint32_t base = sb + (ch % 3) * R_BUF;
        #pragma unroll
        for (int ks = 0; ks < 2; ks++) {
            uint32_t ahf[2][4], alf[2][4], bb[2][4];
            #pragma unroll
            for (int mt = 0; mt < 2; mt++) {
                const uint32_t ra = base + (wm + mt * 16 + fRow) * 80 + (ks * 16 + fK) * 2;
                ldx4(ahf[mt], ra);
                ldx4(alf[mt], ra + R_AARR);
            }
            #pragma unroll
            for (int nt = 0; nt < 2; nt++) {
                const uint32_t rb = base + R_BOFF + (ks * 16 + tK) * 144 + (wn + nt * 16 + tN) * 2;
                ldx4t(bb[nt], rb);
            }
            #pragma unroll
            for (int mt = 0; mt < 2; mt++)
                #pragma unroll
                for (int nt = 0; nt < 2; nt++) {
                    mma16816(acc[mt][nt*2],   ahf[mt], bb[nt][0], bb[nt][1]);
                    mma16816(acc[mt][nt*2+1], ahf[mt], bb[nt][2], bb[nt][3]);
                    mma16816(acc[mt][nt*2],   alf[mt], bb[nt][0], bb[nt][1]);
                    mma16816(acc[mt][nt*2+1], alf[mt], bb[nt][2], bb[nt][3]);
                }
            #pragma unroll
            for (int nt = 0; nt < 2; nt++) {
                const uint32_t rb = base + R_BOFF + R_BARR + (ks * 16 + tK) * 144 + (wn + nt * 16 + tN) * 2;
                ldx4t(bb[nt], rb);
            }
            #pragma unroll
            for (int mt = 0; mt < 2; mt++)
                #pragma unroll
                for (int nt = 0; nt < 2; nt++) {
                    mma16816(acc[mt][nt*2],   ahf[mt], bb[nt][0], bb[nt][1]);
                    mma16816(acc[mt][nt*2+1], ahf[mt], bb[nt][2], bb[nt][3]);
                }
        }
        __syncthreads();
    }

    #pragma unroll
    for (int mt = 0; mt < 2; mt++)
        #pragma unroll
        for (int h = 0; h < 2; h++) {
            const int m = wm + mt * 16 + h * 8 + (lane >> 2);
            const int pos = (c & 15) * 64 + m;
            const float scale = rsqrtf((float)(pos + 1) * 64.0f);
            const long orow = ((long)c * 64 + m) * 512;
            #pragma unroll
            for (int n8 = 0; n8 < 4; n8++) {
                const int col = col0 + wn + n8 * 8 + (lane & 3) * 2;
                float2 o;
                o.x = acc[mt][n8][h*2+0] * scale;
                o.y = acc[mt][n8][h*2+1] * scale;
                *(float2*)&Out[orow + col] = o;
            }
        }
}

// ================= prep: xsplit + wsplit + wp_split in one launch ==========
__global__ __launch_bounds__(256)
void prep_kernel(const float* __restrict__ x,
                 const float* __restrict__ W0, const float* __restrict__ W1,
                 const float* __restrict__ W2, const float* __restrict__ W3,
                 const float* __restrict__ Wk2, const float* __restrict__ Wq2,
                 bf16* __restrict__ xh, bf16* __restrict__ xl,
                 bf16* __restrict__ Wth, bf16* __restrict__ Wtl,
                 bf16* __restrict__ Wph, bf16* __restrict__ Wpl)
{
    const int bid = blockIdx.x, tid = threadIdx.x;
    if (bid < 1024) {
        const int i = bid * 256 + tid;
        float4 v = ((const float4*)x)[i];
        bsplit2(v.x, v.y, xh + i * 4,     xl + i * 4);
        bsplit2(v.z, v.w, xh + i * 4 + 2, xl + i * 4 + 2);
    } else if (bid < 2048) {
        const int widx = bid - 1024;
        const int z = widx >> 8, tile = widx & 255;
        const int k0 = (tile >> 4) * 32, n0 = (tile & 15) * 32;
        const float* W = z == 0 ? W0 : z == 1 ? W1 : z == 2 ? W2 : W3;
        __shared__ float t[32][33];
        #pragma unroll
        for (int j = 0; j < 4; j++) {
            const int r = (tid >> 5) + j * 8;
            t[r][tid & 31] = W[(long)(k0 + r) * 512 + n0 + (tid & 31)];
        }
        __syncthreads();
        #pragma unroll
        for (int j = 0; j < 4; j++) {
            const int nr = (tid >> 5) + j * 8, kc = tid & 31;
            const float v = t[kc][nr];
            const long o = (long)z * 262144 + (long)(n0 + nr) * 512 + k0 + kc;
            bf16 h = __float2bfloat16(v);
            Wth[o] = h;
            Wtl[o] = __float2bfloat16(v - __bfloat162float(h));
        }
    } else {
        const int widx = bid - 2048;
        const int z = widx >> 5, tile = widx & 31;
        const int k0 = (tile >> 1) * 32, n0 = (tile & 1) * 32;
        const float* W = z ? Wq2 : Wk2;
        __shared__ float t[32][33];
        #pragma unroll
        for (int j = 0; j < 4; j++) {
            const int r = (tid >> 5) + j * 8;
            t[r][tid & 31] = W[(long)(k0 + r) * 64 + n0 + (tid & 31)];
        }
        __syncthreads();
        #pragma unroll
        for (int j = 0; j < 4; j++) {
            const int nr = (tid >> 5) + j * 8, kc = tid & 31;
            const float v = t[kc][nr];
            const long o = (long)(z * 64 + n0 + nr) * 512 + k0 + kc;
            bf16 h = __float2bfloat16(v);
            Wph[o] = h;
            Wpl[o] = __float2bfloat16(v - __bfloat162float(h));
        }
    }
}

// ================= prefix over 16 chunks per batch =========================
__global__ __launch_bounds__(256)
void prefix_kernel(const float4* __restrict__ S, bf16* __restrict__ Ph,
                   bf16* __restrict__ Pl)
{
    int gidx = blockIdx.x * 256 + threadIdx.x;
    int b = gidx >> 14;
    int i = gidx & 16383;
    long base = (long)b * 16 * 16384 + i;
    float4 run = make_float4(0.f, 0.f, 0.f, 0.f);
    #pragma unroll
    for (int c = 0; c < 16; c++) {
        long idx = base + (long)c * 16384;
        long e = idx * 4;
        bsplit2(run.x, run.y, Ph + e,     Pl + e);
        bsplit2(run.z, run.w, Ph + e + 2, Pl + e + 2);
        float4 s = S[idx];
        run.x += s.x; run.y += s.y; run.z += s.z; run.w += s.w;
    }
}

// ================= LayerNorm (emits split bf16) =================
__global__ __launch_bounds__(128)
void ln_kernel(const float* __restrict__ X, const float* __restrict__ gg,
               const float* __restrict__ bb, bf16* __restrict__ oh,
               bf16* __restrict__ ol)
{
    const int D = 512;
    int row = blockIdx.x;
    int t = threadIdx.x;
    float4 v = ((const float4*)(X + (long)row * D))[t];
    float s  = v.x + v.y + v.z + v.w;
    float sq = v.x * v.x + v.y * v.y + v.z * v.z + v.w * v.w;
    #pragma unroll
    for (int o = 16; o; o >>= 1) {
        s  += __shfl_xor_sync(0xFFFFFFFFu, s, o);
        sq += __shfl_xor_sync(0xFFFFFFFFu, sq, o);
    }
    __shared__ float ss[4], ssq[4];
    int w = t >> 5, l = t & 31;
    if (l == 0) { ss[w] = s; ssq[w] = sq; }
    __syncthreads();
    s  = ss[0] + ss[1] + ss[2] + ss[3];
    sq = ssq[0] + ssq[1] + ssq[2] + ssq[3];
    float mean = s * (1.0f / 512.0f);
    float var  = sq * (1.0f / 512.0f) - mean * mean;
    float rs   = rsqrtf(var + 1e-5f);
    float4 gv = ((const float4*)gg)[t];
    float4 bv = ((const float4*)bb)[t];
    float o0 = (v.x - mean) * rs * gv.x + bv.x;
    float o1 = (v.y - mean) * rs * gv.y + bv.y;
    float o2 = (v.z - mean) * rs * gv.z + bv.z;
    float o3 = (v.w - mean) * rs * gv.w + bv.w;
    long e = (long)row * D + t * 4;
    bsplit2(o0, o1, oh + e,     ol + e);
    bsplit2(o2, o3, oh + e + 2, ol + e + 2);
}

// ================= launch =================
extern "C" void kernel_launch(void* const* d_in, const int* in_sizes, int n_in,
                              void* d_out, int out_size)
{
    const float* x    = (const float*)d_in[0];
    const float* Wk1  = (const float*)d_in[1];
    const float* bk1  = (const float*)d_in[2];
    const float* Wk2  = (const float*)d_in[3];
    const float* bk2  = (const float*)d_in[4];
    const float* Wq1  = (const float*)d_in[5];
    const float* bq1  = (const float*)d_in[6];
    const float* Wq2  = (const float*)d_in[7];
    const float* bq2  = (const float*)d_in[8];
    const float* Wv   = (const float*)d_in[9];
    const float* bv   = (const float*)d_in[10];
    const float* ln_g = (const float*)d_in[11];
    const float* ln_b = (const float*)d_in[12];
    const float* Wo   = (const float*)d_in[13];
    const float* bo   = (const float*)d_in[14];
    float* out = (float*)d_out;

    void* p;
    cudaGetSymbolAddress(&p, g_xh);    bf16* xh    = (bf16*)p;
    cudaGetSymbolAddress(&p, g_xl);    bf16* xl    = (bf16*)p;
    cudaGetSymbolAddress(&p, g_Wth);   bf16* Wth   = (bf16*)p;
    cudaGetSymbolAddress(&p, g_Wtl);   bf16* Wtl   = (bf16*)p;
    cudaGetSymbolAddress(&p, g_Wph);   bf16* Wph   = (bf16*)p;
    cudaGetSymbolAddress(&p, g_Wpl);   bf16* Wpl   = (bf16*)p;
    cudaGetSymbolAddress(&p, g_Hkh);   bf16* Hkh   = (bf16*)p;
    cudaGetSymbolAddress(&p, g_Hkl);   bf16* Hkl   = (bf16*)p;
    cudaGetSymbolAddress(&p, g_Hqh);   bf16* Hqh   = (bf16*)p;
    cudaGetSymbolAddress(&p, g_Hql);   bf16* Hql   = (bf16*)p;
    cudaGetSymbolAddress(&p, g_Vh);    bf16* Vh    = (bf16*)p;
    cudaGetSymbolAddress(&p, g_Vl);    bf16* Vl    = (bf16*)p;
    cudaGetSymbolAddress(&p, g_CSkh);  bf16* CSkh  = (bf16*)p;
    cudaGetSymbolAddress(&p, g_CSkl);  bf16* CSkl  = (bf16*)p;
    cudaGetSymbolAddress(&p, g_CSqh);  bf16* CSqh  = (bf16*)p;
    cudaGetSymbolAddress(&p, g_CSql);  bf16* CSql  = (bf16*)p;
    cudaGetSymbolAddress(&p, g_CSkTh); bf16* CSkTh = (bf16*)p;
    cudaGetSymbolAddress(&p, g_CSkTl); bf16* CSkTl = (bf16*)p;
    cudaGetSymbolAddress(&p, g_Ach);   bf16* Ach   = (bf16*)p;
    cudaGetSymbolAddress(&p, g_Acl);   bf16* Acl   = (bf16*)p;
    cudaGetSymbolAddress(&p, g_S);     float* S    = (float*)p;
    cudaGetSymbolAddress(&p, g_Ph);    bf16* Ph    = (bf16*)p;
    cudaGetSymbolAddress(&p, g_Pl);    bf16* Pl    = (bf16*)p;
    cudaGetSymbolAddress(&p, g_R);     float* R    = (float*)p;
    cudaGetSymbolAddress(&p, g_LNh);   bf16* LNh   = (bf16*)p;
    cudaGetSymbolAddress(&p, g_LNl);   bf16* LNl   = (bf16*)p;

    static int attr_set = 0;
    if (!attr_set) {
        cudaFuncSetAttribute(mma_gemm<0>, cudaFuncAttributeMaxDynamicSharedMemorySize, X_SMEM);
        cudaFuncSetAttribute(mma_gemm<1>, cudaFuncAttributeMaxDynamicSharedMemorySize, X_SMEM);
        cudaFuncSetAttribute(phase_mma,   cudaFuncAttributeMaxDynamicSharedMemorySize, P_SMEM);
        cudaFuncSetAttribute(sac_mma,     cudaFuncAttributeMaxDynamicSharedMemorySize, SAC_SMEM);
        cudaFuncSetAttribute(r_mma,       cudaFuncAttributeMaxDynamicSharedMemorySize, R_SMEM);
        attr_set = 1;
    }

    // 0) conversions
    prep_kernel<<<2112, 256>>>(x, Wk1, Wq1, Wv, Wo, Wk2, Wq2,
                               xh, xl, Wth, Wtl, Wph, Wpl);

    // 1) XW. grid (4,32,3)=384, 128 thr, 3 CTAs/SM.
    mma_gemm<0><<<dim3(4,32,3), 128, X_SMEM>>>(
        xh, xl, Wth, Wtl, bk1, bq1, bv, nullptr,
        Hkh, Hkl, Hqh, Hql, Vh, Vl, nullptr);

    // 2) Phases. grid (1,64,2)=128, 128 thr.
    phase_mma<<<dim3(1,64,2), 128, P_SMEM>>>(
        Hkh, Hkl, Hqh, Hql, Wph, Wpl, bk2, bq2,
        CSkh, CSkl, CSqh, CSql, CSkTh, CSkTl);

    // 3) S + Ac. grid (9,1,32)=288.
    sac_mma<<<dim3(9,1,32), 256, SAC_SMEM>>>(
        CSkTh, CSkTl, Vh, Vl, CSqh, CSql, CSkh, CSkl, S, Ach, Acl);

    // 4) exclusive prefix -> split bf16 P
    prefix_kernel<<<128, 256>>>((const float4*)S, Ph, Pl);

    // 5) R. grid (8,1,32)=256, 128 thr.
    r_mma<<<dim3(8,1,32), 128, R_SMEM>>>(
        CSqh, CSql, Ach, Acl, Ph, Pl, Vh, Vl, R);

    // 6) LN -> split bf16
    ln_kernel<<<2048, 128>>>(R, ln_g, ln_b, LNh, LNl);

    // 7) out = x + LN @ Wo + bo. grid (4,32)=128, 128 thr.
    mma_gemm<1><<<dim3(4,32,1), 128, X_SMEM>>>(
        LNh, LNl, Wth + 3L*262144, Wtl + 3L*262144, bo, nullptr, nullptr, x,
        nullptr, nullptr, nullptr, nullptr, nullptr, nullptr, out);
}